// round 1
// baseline (speedup 1.0000x reference)
#include <cuda_runtime.h>

// ---------------- problem constants ----------------
#define BB   4
#define IMGD 256
#define HID  64
#define PH   63
#define NPAT 3969   // 63*63
#define PPF  64     // 8*8 patch pixels
#define GHD  128

// ---------------- scratch (device globals; no runtime alloc) ----------------
__device__ float g_h1[(long)BB*HID*IMGD*IMGD];   // conv1 out
__device__ float g_h2[(long)BB*HID*IMGD*IMGD];   // conv2 out
__device__ float g_tmp2[BB*IMGD*IMGD];           // conv3 out
__device__ float g_patch[BB*NPAT*PPF];           // [b][n][64]
__device__ float g_sup[BB*NPAT*GHD];             // patch @ W3
__device__ float g_g[BB*NPAT*GHD];               // relu(adj@sup + b3)
__device__ float g_gsup[BB*NPAT*PPF];            // g @ W4
__device__ float g_g2[BB*NPAT*PPF];              // adj@gsup + b4

// ---------------- conv1: 1 -> 64, 3x3 SAME, relu ----------------
// block 256 = 16x16 pixel tile, loops all 64 oc with input window in regs
__global__ void conv1_kernel(const float* __restrict__ in,
                             const float* __restrict__ w,
                             const float* __restrict__ bias) {
    __shared__ float sIn[18][18];
    __shared__ float sW[64 * 9];
    __shared__ float sB[64];
    int b = blockIdx.z;
    int x0 = blockIdx.x * 16, y0 = blockIdx.y * 16;
    int tid = threadIdx.x;
    for (int i = tid; i < 576; i += 256) sW[i] = w[i];
    if (tid < 64) sB[tid] = bias[tid];
    for (int i = tid; i < 324; i += 256) {
        int yy = i / 18, xx = i % 18;
        int gy = y0 + yy - 1, gx = x0 + xx - 1;
        float v = 0.f;
        if (gy >= 0 && gy < IMGD && gx >= 0 && gx < IMGD)
            v = in[(long)b * IMGD * IMGD + gy * IMGD + gx];
        sIn[yy][xx] = v;
    }
    __syncthreads();
    int tx = tid & 15, ty = tid >> 4;
    float r[9];
#pragma unroll
    for (int dy = 0; dy < 3; dy++)
#pragma unroll
        for (int dx = 0; dx < 3; dx++)
            r[dy * 3 + dx] = sIn[ty + dy][tx + dx];
    int gy = y0 + ty, gx = x0 + tx;
    long obase = ((long)b * HID) * IMGD * IMGD + gy * IMGD + gx;
#pragma unroll 4
    for (int oc = 0; oc < 64; oc++) {
        float acc = sB[oc];
#pragma unroll
        for (int t = 0; t < 9; t++) acc += r[t] * sW[oc * 9 + t];
        g_h1[obase + (long)oc * IMGD * IMGD] = fmaxf(acc, 0.f);
    }
}

// ---------------- conv2: 64 -> 64, 3x3 SAME, relu ----------------
// block 256 = 32x8 pixel tile, 4 oc-chunks x 4 ic-chunks of 16
__global__ void conv2_kernel(const float* __restrict__ w,
                             const float* __restrict__ bias) {
    __shared__ float sIn[16 * 10 * 34];   // [ic16][y 10][x 34]  21.8 KB
    __shared__ float sW[16 * 16 * 9];     // [oc16][ic16][9]     9.2 KB
    int b = blockIdx.z;
    int x0 = blockIdx.x * 32, y0 = blockIdx.y * 8;
    int tid = threadIdx.x;
    int tx = tid & 31, ty = tid >> 5;  // ty 0..7
    int gy = y0 + ty, gx = x0 + tx;

    for (int occ = 0; occ < 4; occ++) {
        float acc[16];
#pragma unroll
        for (int o = 0; o < 16; o++) acc[o] = 0.f;

        for (int icc = 0; icc < 4; icc++) {
            __syncthreads();
            // load 16-channel input tile (rows y0-1..y0+8, cols x0-1..x0+32)
            for (int i = tid; i < 16 * 10 * 34; i += 256) {
                int ic = i / 340;
                int rem = i - ic * 340;
                int yy = rem / 34, xx = rem - yy * 34;
                int iy = y0 + yy - 1, ix = x0 + xx - 1;
                float v = 0.f;
                if (iy >= 0 && iy < IMGD && ix >= 0 && ix < IMGD)
                    v = g_h1[((long)b * HID + icc * 16 + ic) * (IMGD * IMGD) + iy * IMGD + ix];
                sIn[i] = v;
            }
            // load weight chunk
            for (int i = tid; i < 16 * 16 * 9; i += 256) {
                int o = i / 144;
                int rem = i - o * 144;
                int ic = rem / 9, t = rem - ic * 9;
                sW[i] = w[(occ * 16 + o) * 576 + (icc * 16 + ic) * 9 + t];
            }
            __syncthreads();

            for (int ic = 0; ic < 16; ic++) {
                const float* wrow = &sW[ic * 9];
#pragma unroll
                for (int t = 0; t < 9; t++) {
                    int dy = t / 3, dx = t - dy * 3;
                    float iv = sIn[ic * 340 + (ty + dy) * 34 + (tx + dx)];
#pragma unroll
                    for (int o = 0; o < 16; o++)
                        acc[o] += iv * wrow[o * 144 + t];
                }
            }
        }
        long obase = ((long)b * HID + occ * 16) * (IMGD * IMGD) + gy * IMGD + gx;
#pragma unroll
        for (int o = 0; o < 16; o++) {
            float v = acc[o] + bias[occ * 16 + o];
            g_h2[obase + (long)o * IMGD * IMGD] = fmaxf(v, 0.f);
        }
    }
}

// ---------------- conv3: 64 -> 1, 3x3 SAME, no relu ----------------
__global__ void conv3_kernel(const float* __restrict__ w,
                             const float* __restrict__ bias) {
    __shared__ float sIn[8][18][18];
    __shared__ float sW[576];
    int b = blockIdx.z;
    int x0 = blockIdx.x * 16, y0 = blockIdx.y * 16;
    int tid = threadIdx.x;
    for (int i = tid; i < 576; i += 256) sW[i] = w[i];
    int tx = tid & 15, ty = tid >> 4;
    float acc = 0.f;
    for (int cc = 0; cc < 8; cc++) {
        __syncthreads();
        for (int i = tid; i < 8 * 324; i += 256) {
            int ic = i / 324;
            int rem = i - ic * 324;
            int yy = rem / 18, xx = rem - yy * 18;
            int gy = y0 + yy - 1, gx = x0 + xx - 1;
            float v = 0.f;
            if (gy >= 0 && gy < IMGD && gx >= 0 && gx < IMGD)
                v = g_h2[((long)b * HID + cc * 8 + ic) * (IMGD * IMGD) + gy * IMGD + gx];
            sIn[ic][yy][xx] = v;
        }
        __syncthreads();
#pragma unroll
        for (int ic = 0; ic < 8; ic++) {
#pragma unroll
            for (int t = 0; t < 9; t++)
                acc += sIn[ic][ty + t / 3][tx + t % 3] * sW[(cc * 8 + ic) * 9 + t];
        }
    }
    g_tmp2[(long)b * IMGD * IMGD + (y0 + ty) * IMGD + (x0 + tx)] = acc + bias[0];
}

// ---------------- im2patch ----------------
__global__ void patch_kernel(const float* __restrict__ in) {
    long idx = (long)blockIdx.x * 256 + threadIdx.x;
    if (idx >= (long)BB * NPAT * PPF) return;
    int k = idx & 63;
    long t = idx >> 6;
    int n = (int)(t % NPAT);
    int b = (int)(t / NPAT);
    int py = n / PH, px = n - py * PH;
    int i = k >> 3, j = k & 7;
    g_patch[idx] = in[(long)b * IMGD * IMGD + (py * 4 + i) * IMGD + (px * 4 + j)];
}

// ---------------- generic batched SGEMM: C = act(A @ B + bias) ----------------
// BM=64, BN=64, BK=16, 256 threads, 4x4 microtile
__global__ void gemm_kernel(const float* __restrict__ A, long aBatch, int lda,
                            const float* __restrict__ Bm, long bBatch, int ldb,
                            float* __restrict__ C, long cBatch,
                            int M, int K, int Nc,
                            const float* __restrict__ bias, int relu) {
    __shared__ float As[16][65];
    __shared__ float Bs[16][64];
    int b = blockIdx.z;
    const float* Ab = A + (long)b * aBatch;
    const float* Bb = Bm + (long)b * bBatch;
    float* Cb = C + (long)b * cBatch;
    int m0 = blockIdx.x * 64;
    int n0 = blockIdx.y * 64;
    int tid = threadIdx.x;
    int tx = tid & 15, ty = tid >> 4;
    float acc[4][4] = {};
    int nK = (K + 15) >> 4;
    for (int kb = 0; kb < nK; kb++) {
        int k0 = kb * 16;
#pragma unroll
        for (int l = 0; l < 4; l++) {
            int i = tid + l * 256;
            int mm = i >> 4, kk = i & 15;
            int gm = m0 + mm, gk = k0 + kk;
            float v = 0.f;
            if (gm < M && gk < K) v = Ab[(long)gm * lda + gk];
            As[kk][mm] = v;
        }
#pragma unroll
        for (int l = 0; l < 4; l++) {
            int i = tid + l * 256;
            int kk = i >> 6, nn = i & 63;
            int gk = k0 + kk;
            float v = 0.f;
            if (gk < K) v = Bb[(long)gk * ldb + n0 + nn];
            Bs[kk][nn] = v;
        }
        __syncthreads();
#pragma unroll
        for (int kk = 0; kk < 16; kk++) {
            float a[4], bb[4];
#pragma unroll
            for (int r = 0; r < 4; r++) a[r] = As[kk][ty + 16 * r];
#pragma unroll
            for (int c = 0; c < 4; c++) bb[c] = Bs[kk][tx + 16 * c];
#pragma unroll
            for (int r = 0; r < 4; r++)
#pragma unroll
                for (int c = 0; c < 4; c++)
                    acc[r][c] += a[r] * bb[c];
        }
        __syncthreads();
    }
#pragma unroll
    for (int r = 0; r < 4; r++) {
        int gm = m0 + ty + 16 * r;
        if (gm >= M) continue;
#pragma unroll
        for (int c = 0; c < 4; c++) {
            int gn = n0 + tx + 16 * c;
            float v = acc[r][c];
            if (bias) v += bias[gn];
            if (relu) v = fmaxf(v, 0.f);
            Cb[(long)gm * Nc + gn] = v;
        }
    }
}

// ---------------- final: tmp1 + tmp2 + patch2img(g2)/mask, relu ----------------
__global__ void final_kernel(const float* __restrict__ in,
                             const float* __restrict__ proj,
                             const float* __restrict__ lam,
                             float* __restrict__ out) {
    int idx = blockIdx.x * 256 + threadIdx.x;
    if (idx >= BB * IMGD * IMGD) return;
    int x = idx & 255, y = (idx >> 8) & 255, b = idx >> 16;
    float lv = lam[0];
    float iv = in[idx], pv = proj[idx];
    float t1 = iv + lv * (pv - iv);
    float t2 = g_tmp2[idx];
    int tyv = y - 7;
    int py_lo = tyv > 0 ? (tyv + 3) >> 2 : 0;
    int py_hi = min(62, y >> 2);
    int txv = x - 7;
    int px_lo = txv > 0 ? (txv + 3) >> 2 : 0;
    int px_hi = min(62, x >> 2);
    float s = 0.f;
    int cnt = (py_hi - py_lo + 1) * (px_hi - px_lo + 1);
    for (int py = py_lo; py <= py_hi; py++) {
        int i = y - 4 * py;
        for (int px = px_lo; px <= px_hi; px++) {
            int j = x - 4 * px;
            s += g_g2[((long)b * NPAT + (py * PH + px)) * PPF + i * 8 + j];
        }
    }
    float v = t1 + t2 + s / (float)cnt;
    out[idx] = fmaxf(v, 0.f);
}

// ---------------- launch ----------------
extern "C" void kernel_launch(void* const* d_in, const int* in_sizes, int n_in,
                              void* d_out, int out_size) {
    const float* input = (const float*)d_in[0];
    const float* proj  = (const float*)d_in[1];
    const float* adj   = (const float*)d_in[2];
    const float* lam   = (const float*)d_in[3];
    const float* w1 = (const float*)d_in[4];
    const float* b1 = (const float*)d_in[5];
    const float* w2 = (const float*)d_in[6];
    const float* b2 = (const float*)d_in[7];
    const float* w3 = (const float*)d_in[8];
    const float* b3 = (const float*)d_in[9];
    const float* gw3 = (const float*)d_in[10];
    const float* gb3 = (const float*)d_in[11];
    const float* gw4 = (const float*)d_in[12];
    const float* gb4 = (const float*)d_in[13];
    float* out = (float*)d_out;

    float *p_patch, *p_sup, *p_g, *p_gsup, *p_g2;
    cudaGetSymbolAddress((void**)&p_patch, g_patch);
    cudaGetSymbolAddress((void**)&p_sup, g_sup);
    cudaGetSymbolAddress((void**)&p_g, g_g);
    cudaGetSymbolAddress((void**)&p_gsup, g_gsup);
    cudaGetSymbolAddress((void**)&p_g2, g_g2);

    // CNN branch
    conv1_kernel<<<dim3(16, 16, BB), 256>>>(input, w1, b1);
    conv2_kernel<<<dim3(8, 32, BB), 256>>>(w2, b2);
    conv3_kernel<<<dim3(16, 16, BB), 256>>>(w3, b3);

    // GCN branch
    patch_kernel<<<(BB * NPAT * PPF + 255) / 256, 256>>>(input);
    // support = patch @ W3          [3969,64]x[64,128]
    gemm_kernel<<<dim3((NPAT + 63) / 64, GHD / 64, BB), 256>>>(
        p_patch, (long)NPAT * PPF, PPF, gw3, 0, GHD,
        p_sup, (long)NPAT * GHD, NPAT, PPF, GHD, nullptr, 0);
    // g = relu(adj @ support + b3)  [3969,3969]x[3969,128]
    gemm_kernel<<<dim3((NPAT + 63) / 64, GHD / 64, BB), 256>>>(
        adj, (long)NPAT * NPAT, NPAT, p_sup, (long)NPAT * GHD, GHD,
        p_g, (long)NPAT * GHD, NPAT, NPAT, GHD, gb3, 1);
    // gsup = g @ W4                 [3969,128]x[128,64]
    gemm_kernel<<<dim3((NPAT + 63) / 64, PPF / 64, BB), 256>>>(
        p_g, (long)NPAT * GHD, GHD, gw4, 0, PPF,
        p_gsup, (long)NPAT * PPF, NPAT, GHD, PPF, nullptr, 0);
    // g2 = adj @ gsup + b4          [3969,3969]x[3969,64]
    gemm_kernel<<<dim3((NPAT + 63) / 64, PPF / 64, BB), 256>>>(
        adj, (long)NPAT * NPAT, NPAT, p_gsup, (long)NPAT * PPF, PPF,
        p_g2, (long)NPAT * PPF, NPAT, NPAT, PPF, gb4, 0);

    // combine
    final_kernel<<<(BB * IMGD * IMGD + 255) / 256, 256>>>(input, proj, lam, out);
}

// round 2
// speedup vs baseline: 1.4928x; 1.4928x over previous
#include <cuda_runtime.h>

// ---------------- problem constants ----------------
#define BB   4
#define IMGD 256
#define HID  64
#define PH   63
#define NPAT 3969   // 63*63
#define PPF  64     // 8*8 patch pixels
#define GHD  128

// ---------------- scratch (device globals; no runtime alloc) ----------------
__device__ float g_h1[(long)BB*HID*IMGD*IMGD];   // conv1 out
__device__ float g_h2[(long)BB*HID*IMGD*IMGD];   // conv2 out
__device__ float g_tmp2[BB*IMGD*IMGD];           // conv3 out
__device__ float g_patch[BB*NPAT*PPF];           // [b][n][64]
__device__ float g_sup[BB*NPAT*GHD];             // patch @ W3
__device__ float g_g[BB*NPAT*GHD];               // relu(adj@sup + b3)
__device__ float g_gsup[BB*NPAT*PPF];            // g @ W4
__device__ float g_g2[BB*NPAT*PPF];              // adj@gsup + b4

// ---------------- conv1: 1 -> 64, 3x3 SAME, relu ----------------
// tile 64x x 16y, 256 threads, each thread 4 x-consecutive pixels
__global__ void __launch_bounds__(256) conv1_kernel(const float* __restrict__ in,
                             const float* __restrict__ w,
                             const float* __restrict__ bias) {
    __shared__ float sIn[18][66];
    __shared__ float sW[576];
    __shared__ float sB[64];
    int b = blockIdx.z;
    int x0 = blockIdx.x * 64, y0 = blockIdx.y * 16;
    int tid = threadIdx.x;
    for (int i = tid; i < 576; i += 256) sW[i] = w[i];
    if (tid < 64) sB[tid] = bias[tid];
    for (int i = tid; i < 18 * 66; i += 256) {
        int yy = i / 66, xx = i - yy * 66;
        int gy = y0 + yy - 1, gx = x0 + xx - 1;
        float v = 0.f;
        if (gy >= 0 && gy < IMGD && gx >= 0 && gx < IMGD)
            v = in[(long)b * IMGD * IMGD + gy * IMGD + gx];
        sIn[yy][xx] = v;
    }
    __syncthreads();
    int tx = tid & 15, ty = tid >> 4;
    float r[3][6];
#pragma unroll
    for (int dy = 0; dy < 3; dy++)
#pragma unroll
        for (int dx = 0; dx < 6; dx++)
            r[dy][dx] = sIn[ty + dy][tx * 4 + dx];
    int gy = y0 + ty, gx = x0 + tx * 4;
    long obase = (long)b * HID * IMGD * IMGD + gy * IMGD + gx;
#pragma unroll 2
    for (int oc = 0; oc < 64; oc++) {
        float wv[9];
#pragma unroll
        for (int t = 0; t < 9; t++) wv[t] = sW[oc * 9 + t];
        float acc[4];
#pragma unroll
        for (int p = 0; p < 4; p++) acc[p] = sB[oc];
#pragma unroll
        for (int dy = 0; dy < 3; dy++)
#pragma unroll
            for (int dx = 0; dx < 3; dx++)
#pragma unroll
                for (int p = 0; p < 4; p++)
                    acc[p] += r[dy][p + dx] * wv[dy * 3 + dx];
        float4 o;
        o.x = fmaxf(acc[0], 0.f); o.y = fmaxf(acc[1], 0.f);
        o.z = fmaxf(acc[2], 0.f); o.w = fmaxf(acc[3], 0.f);
        *(float4*)&g_h1[obase + (long)oc * IMGD * IMGD] = o;
    }
}

// ---------------- conv2: 64 -> 64, 3x3 SAME, relu ----------------
// tile 32x x 16y; thread = (tx:8, ty:16, to:2); each thread 8 oc x 4 px
__global__ void __launch_bounds__(256) conv2_kernel(const float* __restrict__ w,
                             const float* __restrict__ bias) {
    __shared__ float sIn[8 * 18 * 34];    // [ic8][y18][x34]
    __shared__ float sW[16 * 8 * 9];      // [oc16][ic8][9]
    int b = blockIdx.z;
    int x0 = blockIdx.x * 32, y0 = blockIdx.y * 16;
    int tid = threadIdx.x;
    int tx = tid & 7, ty = (tid >> 3) & 15, to = tid >> 7;
    int gy = y0 + ty, gx = x0 + tx * 4;

    for (int occ = 0; occ < 4; occ++) {
        float acc[8][4];
#pragma unroll
        for (int o = 0; o < 8; o++)
#pragma unroll
            for (int p = 0; p < 4; p++) acc[o][p] = 0.f;

        for (int icc = 0; icc < 8; icc++) {
            __syncthreads();
            // input tile: 8 ic, rows y0-1..y0+16, cols x0-1..x0+32
            for (int i = tid; i < 8 * 18 * 34; i += 256) {
                int ic = i / 612;
                int rem = i - ic * 612;
                int yy = rem / 34, xx = rem - yy * 34;
                int iy = y0 + yy - 1, ix = x0 + xx - 1;
                float v = 0.f;
                if (iy >= 0 && iy < IMGD && ix >= 0 && ix < IMGD)
                    v = g_h1[((long)b * HID + icc * 8 + ic) * (IMGD * IMGD) + iy * IMGD + ix];
                sIn[i] = v;
            }
            for (int i = tid; i < 16 * 8 * 9; i += 256) {
                int o = i / 72;
                int rem = i - o * 72;
                int ic = rem / 9, t = rem - ic * 9;
                sW[i] = w[(occ * 16 + o) * 576 + (icc * 8 + ic) * 9 + t];
            }
            __syncthreads();

#pragma unroll 1
            for (int ic = 0; ic < 8; ic++) {
                float rin[3][6];
#pragma unroll
                for (int dy = 0; dy < 3; dy++)
#pragma unroll
                    for (int dx = 0; dx < 6; dx++)
                        rin[dy][dx] = sIn[ic * 612 + (ty + dy) * 34 + (tx * 4 + dx)];
#pragma unroll
                for (int o = 0; o < 8; o++) {
                    const float* wr = &sW[(to * 8 + o) * 72 + ic * 9];
                    float wv[9];
#pragma unroll
                    for (int t = 0; t < 9; t++) wv[t] = wr[t];
#pragma unroll
                    for (int dy = 0; dy < 3; dy++)
#pragma unroll
                        for (int dx = 0; dx < 3; dx++)
#pragma unroll
                            for (int p = 0; p < 4; p++)
                                acc[o][p] += rin[dy][p + dx] * wv[dy * 3 + dx];
                }
            }
        }
        int ocb = occ * 16 + to * 8;
        long obase = ((long)b * HID + ocb) * (IMGD * IMGD) + gy * IMGD + gx;
#pragma unroll
        for (int o = 0; o < 8; o++) {
            float bv = bias[ocb + o];
            float4 ov;
            ov.x = fmaxf(acc[o][0] + bv, 0.f);
            ov.y = fmaxf(acc[o][1] + bv, 0.f);
            ov.z = fmaxf(acc[o][2] + bv, 0.f);
            ov.w = fmaxf(acc[o][3] + bv, 0.f);
            *(float4*)&g_h2[obase + (long)o * IMGD * IMGD] = ov;
        }
    }
}

// ---------------- conv3: 64 -> 1, 3x3 SAME ----------------
// tile 64x x 16y, each thread 4 px; ic chunks of 4
__global__ void __launch_bounds__(256) conv3_kernel(const float* __restrict__ w,
                             const float* __restrict__ bias) {
    __shared__ float sIn[4 * 18 * 66];
    __shared__ float sW[576];
    int b = blockIdx.z;
    int x0 = blockIdx.x * 64, y0 = blockIdx.y * 16;
    int tid = threadIdx.x;
    for (int i = tid; i < 576; i += 256) sW[i] = w[i];
    int tx = tid & 15, ty = tid >> 4;
    float acc[4] = {0.f, 0.f, 0.f, 0.f};
    for (int cc = 0; cc < 16; cc++) {
        __syncthreads();
        for (int i = tid; i < 4 * 18 * 66; i += 256) {
            int ic = i / 1188;
            int rem = i - ic * 1188;
            int yy = rem / 66, xx = rem - yy * 66;
            int gy = y0 + yy - 1, gx = x0 + xx - 1;
            float v = 0.f;
            if (gy >= 0 && gy < IMGD && gx >= 0 && gx < IMGD)
                v = g_h2[((long)b * HID + cc * 4 + ic) * (IMGD * IMGD) + gy * IMGD + gx];
            sIn[i] = v;
        }
        __syncthreads();
#pragma unroll
        for (int ic = 0; ic < 4; ic++) {
            float rin[3][6];
#pragma unroll
            for (int dy = 0; dy < 3; dy++)
#pragma unroll
                for (int dx = 0; dx < 6; dx++)
                    rin[dy][dx] = sIn[ic * 1188 + (ty + dy) * 66 + (tx * 4 + dx)];
            float wv[9];
#pragma unroll
            for (int t = 0; t < 9; t++) wv[t] = sW[(cc * 4 + ic) * 9 + t];
#pragma unroll
            for (int dy = 0; dy < 3; dy++)
#pragma unroll
                for (int dx = 0; dx < 3; dx++)
#pragma unroll
                    for (int p = 0; p < 4; p++)
                        acc[p] += rin[dy][p + dx] * wv[dy * 3 + dx];
        }
    }
    float bv = bias[0];
    float4 o;
    o.x = acc[0] + bv; o.y = acc[1] + bv; o.z = acc[2] + bv; o.w = acc[3] + bv;
    *(float4*)&g_tmp2[(long)b * IMGD * IMGD + (y0 + ty) * IMGD + x0 + tx * 4] = o;
}

// ---------------- im2patch (vectorized: one 8-pixel patch row per thread) ----
__global__ void patch_kernel(const float* __restrict__ in) {
    int idx = blockIdx.x * 256 + threadIdx.x;
    if (idx >= BB * NPAT * 8) return;
    int i = idx & 7;
    int t = idx >> 3;
    int n = t % NPAT;
    int b = t / NPAT;
    int py = n / PH, px = n - py * PH;
    const float* src = in + (long)b * IMGD * IMGD + (py * 4 + i) * IMGD + px * 4;
    float* dst = g_patch + ((long)b * NPAT + n) * PPF + i * 8;
    *(float4*)dst = *(const float4*)src;
    *(float4*)(dst + 4) = *(const float4*)(src + 4);
}

// ---------------- batched SGEMM: C = act(A @ B + bias) ----------------
// BM=128, BN=16*MN, BK=16, 256 threads, 8xMN microtile, double-buffered
template<int MN>
__global__ void __launch_bounds__(256) gemm_kernel(
        const float* __restrict__ A, long aBatch, int lda,
        const float* __restrict__ Bm, long bBatch, int ldb,
        float* __restrict__ C, long cBatch,
        int M, int K,
        const float* __restrict__ bias, int relu) {
    const int BN = 16 * MN;
    __shared__ float As[2][16][128];
    __shared__ float Bs[2][16][BN];
    int b = blockIdx.z;
    const float* Ab = A + (long)b * aBatch;
    const float* Bb = Bm + (long)b * bBatch;
    float* Cb = C + (long)b * cBatch;
    int m0 = blockIdx.x * 128;
    int n0 = blockIdx.y * BN;
    int tid = threadIdx.x;
    int tx = tid & 15, ty = tid >> 4;
    float acc[8][MN];
#pragma unroll
    for (int r = 0; r < 8; r++)
#pragma unroll
        for (int c = 0; c < MN; c++) acc[r][c] = 0.f;

    const int nK = (K + 15) >> 4;
    // A staging: 8 scalars (lda may be odd -> no float4 on A)
    float rA[8];
    int a_row = tid >> 1;             // 0..127
    int a_kq  = (tid & 1) * 8;        // 0 or 8 (8 consecutive k per thread)
    // B staging: MN/4 float4 per... (BN*16/256 floats = BN/16 = MN floats = MN/4 f4)
    float4 rB[MN / 4];
    int b_kk  = tid / (BN / 4);       // BN=128: tid>>5 ; BN=64: tid>>4
    int b_nn4 = tid % (BN / 4);

    // prologue: tile 0
    {
        int gm = m0 + a_row;
#pragma unroll
        for (int j = 0; j < 8; j++) {
            int gk = a_kq + j;
            rA[j] = (gm < M && gk < K) ? Ab[(long)gm * lda + gk] : 0.f;
        }
#pragma unroll
        for (int l = 0; l < MN / 4; l++) {
            int idx = tid + l * 256;
            int kk = idx / (BN / 4), nn4 = idx % (BN / 4);
            if (kk < K)
                rB[l] = *(const float4*)&Bb[(long)kk * ldb + n0 + nn4 * 4];
            else
                rB[l] = make_float4(0.f, 0.f, 0.f, 0.f);
        }
#pragma unroll
        for (int j = 0; j < 8; j++) As[0][a_kq + j][a_row] = rA[j];
#pragma unroll
        for (int l = 0; l < MN / 4; l++) {
            int idx = tid + l * 256;
            int kk = idx / (BN / 4), nn4 = idx % (BN / 4);
            *(float4*)&Bs[0][kk][nn4 * 4] = rB[l];
        }
    }
    __syncthreads();

    for (int kb = 0; kb < nK; kb++) {
        int cur = kb & 1;
        bool pf = (kb + 1 < nK);
        if (pf) {
            int k0 = (kb + 1) * 16;
            int gm = m0 + a_row;
#pragma unroll
            for (int j = 0; j < 8; j++) {
                int gk = k0 + a_kq + j;
                rA[j] = (gm < M && gk < K) ? Ab[(long)gm * lda + gk] : 0.f;
            }
#pragma unroll
            for (int l = 0; l < MN / 4; l++) {
                int idx = tid + l * 256;
                int kk = idx / (BN / 4), nn4 = idx % (BN / 4);
                int gk = k0 + kk;
                if (gk < K)
                    rB[l] = *(const float4*)&Bb[(long)gk * ldb + n0 + nn4 * 4];
                else
                    rB[l] = make_float4(0.f, 0.f, 0.f, 0.f);
            }
        }
#pragma unroll
        for (int kk = 0; kk < 16; kk++) {
            float4 a0 = *(const float4*)&As[cur][kk][ty * 8];
            float4 a1 = *(const float4*)&As[cur][kk][ty * 8 + 4];
            float av[8] = {a0.x, a0.y, a0.z, a0.w, a1.x, a1.y, a1.z, a1.w};
            float bv[MN];
#pragma unroll
            for (int l = 0; l < MN / 4; l++) {
                float4 bq = *(const float4*)&Bs[cur][kk][tx * MN + l * 4];
                bv[l * 4 + 0] = bq.x; bv[l * 4 + 1] = bq.y;
                bv[l * 4 + 2] = bq.z; bv[l * 4 + 3] = bq.w;
            }
#pragma unroll
            for (int r = 0; r < 8; r++)
#pragma unroll
                for (int c = 0; c < MN; c++)
                    acc[r][c] += av[r] * bv[c];
        }
        if (pf) {
            int nxt = cur ^ 1;
#pragma unroll
            for (int j = 0; j < 8; j++) As[nxt][a_kq + j][a_row] = rA[j];
#pragma unroll
            for (int l = 0; l < MN / 4; l++) {
                int idx = tid + l * 256;
                int kk = idx / (BN / 4), nn4 = idx % (BN / 4);
                *(float4*)&Bs[nxt][kk][nn4 * 4] = rB[l];
            }
        }
        __syncthreads();
    }

    // epilogue
    float bvv[MN];
#pragma unroll
    for (int c = 0; c < MN; c++)
        bvv[c] = bias ? bias[n0 + tx * MN + c] : 0.f;
#pragma unroll
    for (int r = 0; r < 8; r++) {
        int gm = m0 + ty * 8 + r;
        if (gm >= M) continue;
        float* crow = &Cb[(long)gm * BN * gridDim.y + n0 + tx * MN];
#pragma unroll
        for (int l = 0; l < MN / 4; l++) {
            float4 ov;
            float v0 = acc[r][l * 4 + 0] + bvv[l * 4 + 0];
            float v1 = acc[r][l * 4 + 1] + bvv[l * 4 + 1];
            float v2 = acc[r][l * 4 + 2] + bvv[l * 4 + 2];
            float v3 = acc[r][l * 4 + 3] + bvv[l * 4 + 3];
            if (relu) {
                v0 = fmaxf(v0, 0.f); v1 = fmaxf(v1, 0.f);
                v2 = fmaxf(v2, 0.f); v3 = fmaxf(v3, 0.f);
            }
            ov.x = v0; ov.y = v1; ov.z = v2; ov.w = v3;
            *(float4*)&crow[l * 4] = ov;
        }
    }
}

// ---------------- final: tmp1 + tmp2 + patch2img(g2)/mask, relu ----------------
__global__ void final_kernel(const float* __restrict__ in,
                             const float* __restrict__ proj,
                             const float* __restrict__ lam,
                             float* __restrict__ out) {
    int idx = blockIdx.x * 256 + threadIdx.x;
    if (idx >= BB * IMGD * IMGD) return;
    int x = idx & 255, y = (idx >> 8) & 255, b = idx >> 16;
    float lv = lam[0];
    float iv = in[idx], pv = proj[idx];
    float t1 = iv + lv * (pv - iv);
    float t2 = g_tmp2[idx];
    int tyv = y - 7;
    int py_lo = tyv > 0 ? (tyv + 3) >> 2 : 0;
    int py_hi = min(62, y >> 2);
    int txv = x - 7;
    int px_lo = txv > 0 ? (txv + 3) >> 2 : 0;
    int px_hi = min(62, x >> 2);
    float s = 0.f;
    int cnt = (py_hi - py_lo + 1) * (px_hi - px_lo + 1);
    for (int py = py_lo; py <= py_hi; py++) {
        int i = y - 4 * py;
        for (int px = px_lo; px <= px_hi; px++) {
            int j = x - 4 * px;
            s += g_g2[((long)b * NPAT + (py * PH + px)) * PPF + i * 8 + j];
        }
    }
    float v = t1 + t2 + s / (float)cnt;
    out[idx] = fmaxf(v, 0.f);
}

// ---------------- launch ----------------
extern "C" void kernel_launch(void* const* d_in, const int* in_sizes, int n_in,
                              void* d_out, int out_size) {
    const float* input = (const float*)d_in[0];
    const float* proj  = (const float*)d_in[1];
    const float* adj   = (const float*)d_in[2];
    const float* lam   = (const float*)d_in[3];
    const float* w1 = (const float*)d_in[4];
    const float* b1 = (const float*)d_in[5];
    const float* w2 = (const float*)d_in[6];
    const float* b2 = (const float*)d_in[7];
    const float* w3 = (const float*)d_in[8];
    const float* b3 = (const float*)d_in[9];
    const float* gw3 = (const float*)d_in[10];
    const float* gb3 = (const float*)d_in[11];
    const float* gw4 = (const float*)d_in[12];
    const float* gb4 = (const float*)d_in[13];
    float* out = (float*)d_out;

    float *p_patch, *p_sup, *p_g, *p_gsup, *p_g2;
    cudaGetSymbolAddress((void**)&p_patch, g_patch);
    cudaGetSymbolAddress((void**)&p_sup, g_sup);
    cudaGetSymbolAddress((void**)&p_g, g_g);
    cudaGetSymbolAddress((void**)&p_gsup, g_gsup);
    cudaGetSymbolAddress((void**)&p_g2, g_g2);

    // CNN branch
    conv1_kernel<<<dim3(4, 16, BB), 256>>>(input, w1, b1);
    conv2_kernel<<<dim3(8, 16, BB), 256>>>(w2, b2);
    conv3_kernel<<<dim3(4, 16, BB), 256>>>(w3, b3);

    // GCN branch
    patch_kernel<<<(BB * NPAT * 8 + 255) / 256, 256>>>(input);
    // support = patch @ W3          [3969,64]x[64,128]
    gemm_kernel<8><<<dim3(32, 1, BB), 256>>>(
        p_patch, (long)NPAT * PPF, PPF, gw3, 0, GHD,
        p_sup, (long)NPAT * GHD, NPAT, PPF, nullptr, 0);
    // g = relu(adj @ support + b3)  [3969,3969]x[3969,128]
    gemm_kernel<8><<<dim3(32, 1, BB), 256>>>(
        adj, (long)NPAT * NPAT, NPAT, p_sup, (long)NPAT * GHD, GHD,
        p_g, (long)NPAT * GHD, NPAT, NPAT, gb3, 1);
    // gsup = g @ W4                 [3969,128]x[128,64]
    gemm_kernel<4><<<dim3(32, 1, BB), 256>>>(
        p_g, (long)NPAT * GHD, GHD, gw4, 0, PPF,
        p_gsup, (long)NPAT * PPF, NPAT, GHD, nullptr, 0);
    // g2 = adj @ gsup + b4          [3969,3969]x[3969,64]
    gemm_kernel<4><<<dim3(32, 1, BB), 256>>>(
        adj, (long)NPAT * NPAT, NPAT, p_gsup, (long)NPAT * PPF, PPF,
        p_g2, (long)NPAT * PPF, NPAT, NPAT, gb4, 0);

    // combine
    final_kernel<<<(BB * IMGD * IMGD + 255) / 256, 256>>>(input, proj, lam, out);
}

// round 4
// speedup vs baseline: 1.8385x; 1.2316x over previous
#include <cuda_runtime.h>
#include <cuda_bf16.h>
#include <cstdint>

// ---------------- problem constants ----------------
#define BB   4
#define IMGD 256
#define HID  64
#define PH   63
#define NPAT 3969   // 63*63
#define PPF  64     // 8*8 patch pixels
#define GHD  128
#define KPAD 4032   // 63*64, padded K for tensor GEMM (multiple of 32)
#define NCHUNK 126  // KPAD / 32

// ---------------- scratch (device globals; no runtime alloc) ----------------
__device__ float g_h1[(long)BB*HID*IMGD*IMGD];   // conv1 out
__device__ float g_h2[(long)BB*HID*IMGD*IMGD];   // conv2 out
__device__ float g_tmp2[BB*IMGD*IMGD];           // conv3 out
__device__ float g_patch[BB*NPAT*PPF];           // [b][n][64]
__device__ float g_g[(long)BB*NPAT*GHD];         // relu(adj@sup + b3) fp32
__device__ float g_g2[(long)BB*NPAT*PPF];        // adj@gsup + b4 fp32
__device__ __nv_bfloat16 g_supT[(long)BB*GHD*KPAD];   // (patch@W3)^T bf16, K-pad
__device__ __nv_bfloat16 g_gsupT[(long)BB*PPF*KPAD];  // (g@W4)^T bf16, K-pad

__device__ __forceinline__ uint32_t smem_to_u32(const void* p) {
    uint32_t a;
    asm("{ .reg .u64 t; cvta.to.shared.u64 t, %1; cvt.u32.u64 %0, t; }"
        : "=r"(a) : "l"(p));
    return a;
}

// ==================== conv branch (unchanged, proven) ====================
__global__ void __launch_bounds__(256) conv1_kernel(const float* __restrict__ in,
                             const float* __restrict__ w,
                             const float* __restrict__ bias) {
    __shared__ float sIn[18][66];
    __shared__ float sW[576];
    __shared__ float sB[64];
    int b = blockIdx.z;
    int x0 = blockIdx.x * 64, y0 = blockIdx.y * 16;
    int tid = threadIdx.x;
    for (int i = tid; i < 576; i += 256) sW[i] = w[i];
    if (tid < 64) sB[tid] = bias[tid];
    for (int i = tid; i < 18 * 66; i += 256) {
        int yy = i / 66, xx = i - yy * 66;
        int gy = y0 + yy - 1, gx = x0 + xx - 1;
        float v = 0.f;
        if (gy >= 0 && gy < IMGD && gx >= 0 && gx < IMGD)
            v = in[(long)b * IMGD * IMGD + gy * IMGD + gx];
        sIn[yy][xx] = v;
    }
    __syncthreads();
    int tx = tid & 15, ty = tid >> 4;
    float r[3][6];
#pragma unroll
    for (int dy = 0; dy < 3; dy++)
#pragma unroll
        for (int dx = 0; dx < 6; dx++)
            r[dy][dx] = sIn[ty + dy][tx * 4 + dx];
    int gy = y0 + ty, gx = x0 + tx * 4;
    long obase = (long)b * HID * IMGD * IMGD + gy * IMGD + gx;
#pragma unroll 2
    for (int oc = 0; oc < 64; oc++) {
        float wv[9];
#pragma unroll
        for (int t = 0; t < 9; t++) wv[t] = sW[oc * 9 + t];
        float acc[4];
#pragma unroll
        for (int p = 0; p < 4; p++) acc[p] = sB[oc];
#pragma unroll
        for (int dy = 0; dy < 3; dy++)
#pragma unroll
            for (int dx = 0; dx < 3; dx++)
#pragma unroll
                for (int p = 0; p < 4; p++)
                    acc[p] += r[dy][p + dx] * wv[dy * 3 + dx];
        float4 o;
        o.x = fmaxf(acc[0], 0.f); o.y = fmaxf(acc[1], 0.f);
        o.z = fmaxf(acc[2], 0.f); o.w = fmaxf(acc[3], 0.f);
        *(float4*)&g_h1[obase + (long)oc * IMGD * IMGD] = o;
    }
}

__global__ void __launch_bounds__(256) conv2_kernel(const float* __restrict__ w,
                             const float* __restrict__ bias) {
    __shared__ float sIn[8 * 18 * 34];
    __shared__ float sW[16 * 8 * 9];
    int b = blockIdx.z;
    int x0 = blockIdx.x * 32, y0 = blockIdx.y * 16;
    int tid = threadIdx.x;
    int tx = tid & 7, ty = (tid >> 3) & 15, to = tid >> 7;
    int gy = y0 + ty, gx = x0 + tx * 4;

    for (int occ = 0; occ < 4; occ++) {
        float acc[8][4];
#pragma unroll
        for (int o = 0; o < 8; o++)
#pragma unroll
            for (int p = 0; p < 4; p++) acc[o][p] = 0.f;

        for (int icc = 0; icc < 8; icc++) {
            __syncthreads();
            for (int i = tid; i < 8 * 18 * 34; i += 256) {
                int ic = i / 612;
                int rem = i - ic * 612;
                int yy = rem / 34, xx = rem - yy * 34;
                int iy = y0 + yy - 1, ix = x0 + xx - 1;
                float v = 0.f;
                if (iy >= 0 && iy < IMGD && ix >= 0 && ix < IMGD)
                    v = g_h1[((long)b * HID + icc * 8 + ic) * (IMGD * IMGD) + iy * IMGD + ix];
                sIn[i] = v;
            }
            for (int i = tid; i < 16 * 8 * 9; i += 256) {
                int o = i / 72;
                int rem = i - o * 72;
                int ic = rem / 9, t = rem - ic * 9;
                sW[i] = w[(occ * 16 + o) * 576 + (icc * 8 + ic) * 9 + t];
            }
            __syncthreads();

#pragma unroll 1
            for (int ic = 0; ic < 8; ic++) {
                float rin[3][6];
#pragma unroll
                for (int dy = 0; dy < 3; dy++)
#pragma unroll
                    for (int dx = 0; dx < 6; dx++)
                        rin[dy][dx] = sIn[ic * 612 + (ty + dy) * 34 + (tx * 4 + dx)];
#pragma unroll
                for (int o = 0; o < 8; o++) {
                    const float* wr = &sW[(to * 8 + o) * 72 + ic * 9];
                    float wv[9];
#pragma unroll
                    for (int t = 0; t < 9; t++) wv[t] = wr[t];
#pragma unroll
                    for (int dy = 0; dy < 3; dy++)
#pragma unroll
                        for (int dx = 0; dx < 3; dx++)
#pragma unroll
                            for (int p = 0; p < 4; p++)
                                acc[o][p] += rin[dy][p + dx] * wv[dy * 3 + dx];
                }
            }
        }
        int ocb = occ * 16 + to * 8;
        long obase = ((long)b * HID + ocb) * (IMGD * IMGD) + gy * IMGD + gx;
#pragma unroll
        for (int o = 0; o < 8; o++) {
            float bv = bias[ocb + o];
            float4 ov;
            ov.x = fmaxf(acc[o][0] + bv, 0.f);
            ov.y = fmaxf(acc[o][1] + bv, 0.f);
            ov.z = fmaxf(acc[o][2] + bv, 0.f);
            ov.w = fmaxf(acc[o][3] + bv, 0.f);
            *(float4*)&g_h2[obase + (long)o * IMGD * IMGD] = ov;
        }
    }
}

__global__ void __launch_bounds__(256) conv3_kernel(const float* __restrict__ w,
                             const float* __restrict__ bias) {
    __shared__ float sIn[4 * 18 * 66];
    __shared__ float sW[576];
    int b = blockIdx.z;
    int x0 = blockIdx.x * 64, y0 = blockIdx.y * 16;
    int tid = threadIdx.x;
    for (int i = tid; i < 576; i += 256) sW[i] = w[i];
    int tx = tid & 15, ty = tid >> 4;
    float acc[4] = {0.f, 0.f, 0.f, 0.f};
    for (int cc = 0; cc < 16; cc++) {
        __syncthreads();
        for (int i = tid; i < 4 * 18 * 66; i += 256) {
            int ic = i / 1188;
            int rem = i - ic * 1188;
            int yy = rem / 66, xx = rem - yy * 66;
            int gy = y0 + yy - 1, gx = x0 + xx - 1;
            float v = 0.f;
            if (gy >= 0 && gy < IMGD && gx >= 0 && gx < IMGD)
                v = g_h2[((long)b * HID + cc * 4 + ic) * (IMGD * IMGD) + gy * IMGD + gx];
            sIn[i] = v;
        }
        __syncthreads();
#pragma unroll
        for (int ic = 0; ic < 4; ic++) {
            float rin[3][6];
#pragma unroll
            for (int dy = 0; dy < 3; dy++)
#pragma unroll
                for (int dx = 0; dx < 6; dx++)
                    rin[dy][dx] = sIn[ic * 1188 + (ty + dy) * 66 + (tx * 4 + dx)];
            float wv[9];
#pragma unroll
            for (int t = 0; t < 9; t++) wv[t] = sW[(cc * 4 + ic) * 9 + t];
#pragma unroll
            for (int dy = 0; dy < 3; dy++)
#pragma unroll
                for (int dx = 0; dx < 3; dx++)
#pragma unroll
                    for (int p = 0; p < 4; p++)
                        acc[p] += rin[dy][p + dx] * wv[dy * 3 + dx];
        }
    }
    float bv = bias[0];
    float4 o;
    o.x = acc[0] + bv; o.y = acc[1] + bv; o.z = acc[2] + bv; o.w = acc[3] + bv;
    *(float4*)&g_tmp2[(long)b * IMGD * IMGD + (y0 + ty) * IMGD + x0 + tx * 4] = o;
}

// ==================== GCN branch ====================

__global__ void patch_kernel(const float* __restrict__ in) {
    int idx = blockIdx.x * 256 + threadIdx.x;
    if (idx >= BB * NPAT * 8) return;
    int i = idx & 7;
    int t = idx >> 3;
    int n = t % NPAT;
    int b = t / NPAT;
    int py = n / PH, px = n - py * PH;
    const float* src = in + (long)b * IMGD * IMGD + (py * 4 + i) * IMGD + px * 4;
    float* dst = g_patch + ((long)b * NPAT + n) * PPF + i * 8;
    *(float4*)dst = *(const float4*)src;
    *(float4*)(dst + 4) = *(const float4*)(src + 4);
}

// supT[b][g][n] = sum_k patch[b][n][k] * w3[k][g]   (bf16, K-padded w/ zeros)
__global__ void __launch_bounds__(128) gemmA_kernel(const float* __restrict__ w3) {
    __shared__ float sP[32][65];
    __shared__ float sW[64][128];
    int b = blockIdx.y;
    int n0 = blockIdx.x * 32;
    int tid = threadIdx.x;
    for (int l = 0; l < 64; l++) {
        int idx = tid + l * 128;
        sW[idx >> 7][idx & 127] = w3[idx];
    }
    for (int l = 0; l < 16; l++) {
        int idx = tid + l * 128;
        int n = idx >> 6, k = idx & 63;
        float v = 0.f;
        if (n0 + n < NPAT) v = g_patch[((long)b * NPAT + n0 + n) * PPF + k];
        sP[n][k] = v;
    }
    __syncthreads();
    int g = tid;
    float acc[32];
#pragma unroll
    for (int n = 0; n < 32; n++) acc[n] = 0.f;
    for (int k = 0; k < 64; k++) {
        float wv = sW[k][g];
#pragma unroll
        for (int n = 0; n < 32; n++) acc[n] += sP[n][k] * wv;
    }
    __nv_bfloat16* dst = g_supT + ((long)b * GHD + g) * KPAD + n0;
#pragma unroll
    for (int n = 0; n < 32; n++)
        dst[n] = (n0 + n < NPAT) ? __float2bfloat16(acc[n]) : __float2bfloat16(0.f);
}

// gsupT[b][p][n] = sum_g g[b][n][g] * w4[g][p]   (bf16, K-padded w/ zeros)
__global__ void __launch_bounds__(128) gemmB_kernel(const float* __restrict__ w4) {
    __shared__ float sG[32][129];
    __shared__ float sW[64][64];
    int b = blockIdx.y;
    int n0 = blockIdx.x * 32;
    int tid = threadIdx.x;
    int p = tid & 63, half = tid >> 6;
    float acc[16];
#pragma unroll
    for (int i = 0; i < 16; i++) acc[i] = 0.f;
    for (int kc = 0; kc < 2; kc++) {
        __syncthreads();
        for (int l = 0; l < 32; l++) {
            int idx = tid + l * 128;
            int kk = idx >> 6, pp = idx & 63;
            sW[kk][pp] = w4[(kc * 64 + kk) * 64 + pp];
        }
        for (int l = 0; l < 16; l++) {
            int idx = tid + l * 128;
            int n = idx >> 6, kk = idx & 63;
            float v = 0.f;
            if (n0 + n < NPAT) v = g_g[((long)b * NPAT + n0 + n) * GHD + kc * 64 + kk];
            sG[n][kk] = v;
        }
        __syncthreads();
        for (int kk = 0; kk < 64; kk++) {
            float wv = sW[kk][p];
#pragma unroll
            for (int i = 0; i < 16; i++) acc[i] += sG[half * 16 + i][kk] * wv;
        }
    }
    __nv_bfloat16* dst = g_gsupT + ((long)b * PPF + p) * KPAD + n0 + half * 16;
#pragma unroll
    for (int i = 0; i < 16; i++)
        dst[i] = (n0 + half * 16 + i < NPAT) ? __float2bfloat16(acc[i]) : __float2bfloat16(0.f);
}

// ---------------- big HMMA GEMM: C[b][m][NN] = adj @ B^T + bias ----------------
// A: adj fp32 [b][NPAT][NPAT] (converted to bf16 in-flight)
// B: bf16 [b][NN][KPAD] K-major (zero-padded)
// BM=128, BK=32, 8 warps (2 M x 4 N), warp tile 64 x NN/4, m16n8k16 atoms.
#define LDT 40   // smem row stride in bf16 elements (80 bytes)

__device__ __forceinline__ void ldmatrix_x4(uint32_t* r, uint32_t addr) {
    asm volatile("ldmatrix.sync.aligned.m8n8.x4.shared.b16 {%0,%1,%2,%3}, [%4];"
                 : "=r"(r[0]), "=r"(r[1]), "=r"(r[2]), "=r"(r[3]) : "r"(addr));
}
__device__ __forceinline__ void ldmatrix_x2(uint32_t* r, uint32_t addr) {
    asm volatile("ldmatrix.sync.aligned.m8n8.x2.shared.b16 {%0,%1}, [%2];"
                 : "=r"(r[0]), "=r"(r[1]) : "r"(addr));
}
__device__ __forceinline__ void mma16816(float* d, const uint32_t* a, const uint32_t* b) {
    asm volatile(
        "mma.sync.aligned.m16n8k16.row.col.f32.bf16.bf16.f32 "
        "{%0,%1,%2,%3}, {%4,%5,%6,%7}, {%8,%9}, {%0,%1,%2,%3};"
        : "+f"(d[0]), "+f"(d[1]), "+f"(d[2]), "+f"(d[3])
        : "r"(a[0]), "r"(a[1]), "r"(a[2]), "r"(a[3]), "r"(b[0]), "r"(b[1]));
}

template<int NN>
__global__ void __launch_bounds__(256) mma_gemm_kernel(
        const float* __restrict__ Aadj,
        const __nv_bfloat16* __restrict__ B,
        float* __restrict__ C,
        const float* __restrict__ bias, int relu) {
    constexpr int WN = NN / 4;        // warp N extent (32 or 16)
    constexpr int NA = WN / 8;        // B atoms per warp (4 or 2)
    __shared__ __align__(16) __nv_bfloat16 A_s[2][128 * LDT];
    __shared__ __align__(16) __nv_bfloat16 B_s[2][NN * LDT];

    int tid = threadIdx.x;
    int lane = tid & 31;
    int wid = tid >> 5;
    int wm = (wid & 1) * 64;          // warp m offset
    int wn = (wid >> 1) * WN;         // warp n offset
    int bz = blockIdx.z;
    int m0 = blockIdx.x * 128;

    const float* Ab = Aadj + (long)bz * NPAT * NPAT;
    const __nv_bfloat16* Bb = B + (long)bz * NN * KPAD;
    float* Cb = C + (long)bz * NPAT * NN;

    float acc[4][NA][4];
#pragma unroll
    for (int i = 0; i < 4; i++)
#pragma unroll
        for (int j = 0; j < NA; j++)
#pragma unroll
            for (int q = 0; q < 4; q++) acc[i][j][q] = 0.f;

    // loader roles
    int ar = tid >> 1;                 // A row 0..127
    int ah = tid & 1;                  // A k-half (16 elements)
    int gm = m0 + ar;
    bool bact = tid < NN * 2;
    int bn = tid >> 1;                 // B row
    int bh = tid & 1;

    uint32_t pa[8];                    // staged A (16 bf16)
    uint4 rb0, rb1;                    // staged B (16 bf16)

    // ---- prologue: chunk 0 ----
    {
        const float* arow = Ab + (long)gm * NPAT + ah * 16;
#pragma unroll
        for (int j = 0; j < 8; j++) {
            int gk0 = ah * 16 + 2 * j;
            float f0 = (gm < NPAT && gk0 < NPAT) ? arow[2 * j] : 0.f;
            float f1 = (gm < NPAT && gk0 + 1 < NPAT) ? arow[2 * j + 1] : 0.f;
            __nv_bfloat162 h = __floats2bfloat162_rn(f0, f1);
            pa[j] = *(uint32_t*)&h;
        }
        if (bact) {
            const __nv_bfloat16* brow = Bb + (long)bn * KPAD + bh * 16;
            rb0 = *(const uint4*)brow;
            rb1 = *(const uint4*)(brow + 8);
        }
        uint32_t* ad = (uint32_t*)&A_s[0][ar * LDT + ah * 16];
        *(uint4*)ad = make_uint4(pa[0], pa[1], pa[2], pa[3]);
        *(uint4*)(ad + 4) = make_uint4(pa[4], pa[5], pa[6], pa[7]);
        if (bact) {
            __nv_bfloat16* bd = &B_s[0][bn * LDT + bh * 16];
            *(uint4*)bd = rb0;
            *(uint4*)(bd + 8) = rb1;
        }
    }
    __syncthreads();

    for (int c = 0; c < NCHUNK; c++) {
        int cur = c & 1;
        // stage next chunk
        if (c + 1 < NCHUNK) {
            int kb = (c + 1) * 32 + ah * 16;
            const float* arow = Ab + (long)gm * NPAT + kb;
#pragma unroll
            for (int j = 0; j < 8; j++) {
                int gk0 = kb + 2 * j;
                float f0 = (gm < NPAT && gk0 < NPAT) ? arow[2 * j] : 0.f;
                float f1 = (gm < NPAT && gk0 + 1 < NPAT) ? arow[2 * j + 1] : 0.f;
                __nv_bfloat162 h = __floats2bfloat162_rn(f0, f1);
                pa[j] = *(uint32_t*)&h;
            }
            if (bact) {
                const __nv_bfloat16* brow = Bb + (long)bn * KPAD + (c + 1) * 32 + bh * 16;
                rb0 = *(const uint4*)brow;
                rb1 = *(const uint4*)(brow + 8);
            }
        }
        // compute on cur
        uint32_t a_base = smem_to_u32(&A_s[cur][0]);
        uint32_t b_base = smem_to_u32(&B_s[cur][0]);
#pragma unroll
        for (int ks = 0; ks < 2; ks++) {
            uint32_t af[4][4];
#pragma unroll
            for (int am = 0; am < 4; am++) {
                uint32_t addr = a_base +
                    (uint32_t)((wm + am * 16 + (lane & 15)) * (LDT * 2)) +
                    (uint32_t)(ks * 32 + (lane >> 4) * 16);
                ldmatrix_x4(af[am], addr);
            }
            uint32_t bf[NA][2];
#pragma unroll
            for (int an = 0; an < NA; an++) {
                uint32_t addr = b_base +
                    (uint32_t)((wn + an * 8 + (lane & 7)) * (LDT * 2)) +
                    (uint32_t)(ks * 32 + ((lane >> 3) & 1) * 16);
                ldmatrix_x2(bf[an], addr);
            }
#pragma unroll
            for (int am = 0; am < 4; am++)
#pragma unroll
                for (int an = 0; an < NA; an++)
                    mma16816(acc[am][an], af[am], bf[an]);
        }
        // store staged -> next buffer
        if (c + 1 < NCHUNK) {
            int nxt = cur ^ 1;
            uint32_t* ad = (uint32_t*)&A_s[nxt][ar * LDT + ah * 16];
            *(uint4*)ad = make_uint4(pa[0], pa[1], pa[2], pa[3]);
            *(uint4*)(ad + 4) = make_uint4(pa[4], pa[5], pa[6], pa[7]);
            if (bact) {
                __nv_bfloat16* bd = &B_s[nxt][bn * LDT + bh * 16];
                *(uint4*)bd = rb0;
                *(uint4*)(bd + 8) = rb1;
            }
        }
        __syncthreads();
    }

    // ---- epilogue ----
    int r0 = lane >> 2, c0 = (lane & 3) * 2;
#pragma unroll
    for (int am = 0; am < 4; am++) {
#pragma unroll
        for (int an = 0; an < NA; an++) {
            int gn = wn + an * 8 + c0;
            float b0 = bias[gn], b1 = bias[gn + 1];
            int gr0 = m0 + wm + am * 16 + r0;
            float v0 = acc[am][an][0] + b0;
            float v1 = acc[am][an][1] + b1;
            float v2 = acc[am][an][2] + b0;
            float v3 = acc[am][an][3] + b1;
            if (relu) {
                v0 = fmaxf(v0, 0.f); v1 = fmaxf(v1, 0.f);
                v2 = fmaxf(v2, 0.f); v3 = fmaxf(v3, 0.f);
            }
            if (gr0 < NPAT) {
                Cb[(long)gr0 * NN + gn] = v0;
                Cb[(long)gr0 * NN + gn + 1] = v1;
            }
            if (gr0 + 8 < NPAT) {
                Cb[(long)(gr0 + 8) * NN + gn] = v2;
                Cb[(long)(gr0 + 8) * NN + gn + 1] = v3;
            }
        }
    }
}

// ---------------- final: tmp1 + tmp2 + patch2img(g2)/mask, relu ----------------
__global__ void final_kernel(const float* __restrict__ in,
                             const float* __restrict__ proj,
                             const float* __restrict__ lam,
                             float* __restrict__ out) {
    int idx = blockIdx.x * 256 + threadIdx.x;
    if (idx >= BB * IMGD * IMGD) return;
    int x = idx & 255, y = (idx >> 8) & 255, b = idx >> 16;
    float lv = lam[0];
    float iv = in[idx], pv = proj[idx];
    float t1 = iv + lv * (pv - iv);
    float t2 = g_tmp2[idx];
    int tyv = y - 7;
    int py_lo = tyv > 0 ? (tyv + 3) >> 2 : 0;
    int py_hi = min(62, y >> 2);
    int txv = x - 7;
    int px_lo = txv > 0 ? (txv + 3) >> 2 : 0;
    int px_hi = min(62, x >> 2);
    float s = 0.f;
    int cnt = (py_hi - py_lo + 1) * (px_hi - px_lo + 1);
    for (int py = py_lo; py <= py_hi; py++) {
        int i = y - 4 * py;
        for (int px = px_lo; px <= px_hi; px++) {
            int j = x - 4 * px;
            s += g_g2[((long)b * NPAT + (py * PH + px)) * PPF + i * 8 + j];
        }
    }
    float v = t1 + t2 + s / (float)cnt;
    out[idx] = fmaxf(v, 0.f);
}

// ---------------- launch ----------------
extern "C" void kernel_launch(void* const* d_in, const int* in_sizes, int n_in,
                              void* d_out, int out_size) {
    const float* input = (const float*)d_in[0];
    const float* proj  = (const float*)d_in[1];
    const float* adj   = (const float*)d_in[2];
    const float* lam   = (const float*)d_in[3];
    const float* w1 = (const float*)d_in[4];
    const float* b1 = (const float*)d_in[5];
    const float* w2 = (const float*)d_in[6];
    const float* b2 = (const float*)d_in[7];
    const float* w3 = (const float*)d_in[8];
    const float* b3 = (const float*)d_in[9];
    const float* gw3 = (const float*)d_in[10];
    const float* gb3 = (const float*)d_in[11];
    const float* gw4 = (const float*)d_in[12];
    const float* gb4 = (const float*)d_in[13];
    float* out = (float*)d_out;

    __nv_bfloat16 *p_supT, *p_gsupT;
    float *p_g, *p_g2;
    cudaGetSymbolAddress((void**)&p_supT, g_supT);
    cudaGetSymbolAddress((void**)&p_gsupT, g_gsupT);
    cudaGetSymbolAddress((void**)&p_g, g_g);
    cudaGetSymbolAddress((void**)&p_g2, g_g2);

    // CNN branch
    conv1_kernel<<<dim3(4, 16, BB), 256>>>(input, w1, b1);
    conv2_kernel<<<dim3(8, 16, BB), 256>>>(w2, b2);
    conv3_kernel<<<dim3(4, 16, BB), 256>>>(w3, b3);

    // GCN branch
    patch_kernel<<<(BB * NPAT * 8 + 255) / 256, 256>>>(input);
    gemmA_kernel<<<dim3(KPAD / 32, BB), 128>>>(gw3);
    // g = relu(adj @ support + b3)
    mma_gemm_kernel<128><<<dim3(32, 1, BB), 256>>>(adj, p_supT, p_g, gb3, 1);
    gemmB_kernel<<<dim3(KPAD / 32, BB), 128>>>(gw4);
    // g2 = adj @ gsup + b4
    mma_gemm_kernel<64><<<dim3(32, 1, BB), 256>>>(adj, p_gsupT, p_g2, gb4, 0);

    // combine
    final_kernel<<<(BB * IMGD * IMGD + 255) / 256, 256>>>(input, proj, lam, out);
}

// round 5
// speedup vs baseline: 4.4230x; 2.4058x over previous
#include <cuda_runtime.h>
#include <cuda_bf16.h>
#include <cuda_fp16.h>
#include <cstdint>

// ---------------- problem constants ----------------
#define BB   4
#define IMGD 256
#define HID  64
#define PH   63
#define NPAT 3969   // 63*63
#define PPF  64     // 8*8 patch pixels
#define GHD  128
#define KPAD 4032   // 63*64, padded K for tensor GEMM
#define NCHUNK 126  // KPAD / 32

// ---------------- scratch (device globals; no runtime alloc) ----------------
__device__ __half g_h1h[(long)BB*HID*IMGD*IMGD];      // conv1 out (fp16)
__device__ float g_h2[(long)BB*HID*IMGD*IMGD];        // conv2 out (fp32)
__device__ float g_tmp2[BB*IMGD*IMGD];                // conv3 out
__device__ float g_patch[BB*NPAT*PPF];                // [b][n][64]
__device__ float g_g[(long)BB*NPAT*GHD];              // relu(adj@sup+b3)
__device__ float g_g2[(long)BB*NPAT*PPF];             // adj@gsup+b4
__device__ __nv_bfloat16 g_adjb[(long)BB*NPAT*KPAD];  // adj bf16 K-padded
__device__ __nv_bfloat16 g_supT[(long)BB*GHD*KPAD];   // (patch@W3)^T bf16
__device__ __nv_bfloat16 g_gsupT[(long)BB*PPF*KPAD];  // (g@W4)^T bf16
__device__ __half g_w2t[9*64*64];                     // w2 [tap][oc][ic] fp16

__device__ __forceinline__ uint32_t smem_to_u32(const void* p) {
    uint32_t a;
    asm("{ .reg .u64 t; cvta.to.shared.u64 t, %1; cvt.u32.u64 %0, t; }"
        : "=r"(a) : "l"(p));
    return a;
}
__device__ __forceinline__ void ldmatrix_x4(uint32_t* r, uint32_t addr) {
    asm volatile("ldmatrix.sync.aligned.m8n8.x4.shared.b16 {%0,%1,%2,%3}, [%4];"
                 : "=r"(r[0]), "=r"(r[1]), "=r"(r[2]), "=r"(r[3]) : "r"(addr));
}
__device__ __forceinline__ void ldmatrix_x2(uint32_t* r, uint32_t addr) {
    asm volatile("ldmatrix.sync.aligned.m8n8.x2.shared.b16 {%0,%1}, [%2];"
                 : "=r"(r[0]), "=r"(r[1]) : "r"(addr));
}
__device__ __forceinline__ void mma16816_bf16(float* d, const uint32_t* a, const uint32_t* b) {
    asm volatile(
        "mma.sync.aligned.m16n8k16.row.col.f32.bf16.bf16.f32 "
        "{%0,%1,%2,%3}, {%4,%5,%6,%7}, {%8,%9}, {%0,%1,%2,%3};"
        : "+f"(d[0]), "+f"(d[1]), "+f"(d[2]), "+f"(d[3])
        : "r"(a[0]), "r"(a[1]), "r"(a[2]), "r"(a[3]), "r"(b[0]), "r"(b[1]));
}
__device__ __forceinline__ void mma16816_f16(float* d, const uint32_t* a, const uint32_t* b) {
    asm volatile(
        "mma.sync.aligned.m16n8k16.row.col.f32.f16.f16.f32 "
        "{%0,%1,%2,%3}, {%4,%5,%6,%7}, {%8,%9}, {%0,%1,%2,%3};"
        : "+f"(d[0]), "+f"(d[1]), "+f"(d[2]), "+f"(d[3])
        : "r"(a[0]), "r"(a[1]), "r"(a[2]), "r"(a[3]), "r"(b[0]), "r"(b[1]));
}

// ==================== weight transform: w2 OIHW -> [tap][oc][ic] fp16 =========
__global__ void wt_kernel(const float* __restrict__ w2) {
    int idx = blockIdx.x * 256 + threadIdx.x;
    if (idx >= 64 * 64 * 9) return;
    int oc = idx / 576, r = idx - oc * 576;
    int ic = r / 9, t = r - ic * 9;
    g_w2t[t * 4096 + oc * 64 + ic] = __float2half(w2[idx]);
}

// ==================== conv1: 1 -> 64, 3x3 SAME, relu, fp16 out ================
__global__ void __launch_bounds__(256) conv1_kernel(const float* __restrict__ in,
                             const float* __restrict__ w,
                             const float* __restrict__ bias) {
    __shared__ float sIn[18][66];
    __shared__ float sW[576];
    __shared__ float sB[64];
    int b = blockIdx.z;
    int x0 = blockIdx.x * 64, y0 = blockIdx.y * 16;
    int tid = threadIdx.x;
    for (int i = tid; i < 576; i += 256) sW[i] = w[i];
    if (tid < 64) sB[tid] = bias[tid];
    for (int i = tid; i < 18 * 66; i += 256) {
        int yy = i / 66, xx = i - yy * 66;
        int gy = y0 + yy - 1, gx = x0 + xx - 1;
        float v = 0.f;
        if (gy >= 0 && gy < IMGD && gx >= 0 && gx < IMGD)
            v = in[(long)b * IMGD * IMGD + gy * IMGD + gx];
        sIn[yy][xx] = v;
    }
    __syncthreads();
    int tx = tid & 15, ty = tid >> 4;
    float r[3][6];
#pragma unroll
    for (int dy = 0; dy < 3; dy++)
#pragma unroll
        for (int dx = 0; dx < 6; dx++)
            r[dy][dx] = sIn[ty + dy][tx * 4 + dx];
    int gy = y0 + ty, gx = x0 + tx * 4;
    long obase = (long)b * HID * IMGD * IMGD + gy * IMGD + gx;
#pragma unroll 2
    for (int oc = 0; oc < 64; oc++) {
        float wv[9];
#pragma unroll
        for (int t = 0; t < 9; t++) wv[t] = sW[oc * 9 + t];
        float acc[4];
#pragma unroll
        for (int p = 0; p < 4; p++) acc[p] = sB[oc];
#pragma unroll
        for (int dy = 0; dy < 3; dy++)
#pragma unroll
            for (int dx = 0; dx < 3; dx++)
#pragma unroll
                for (int p = 0; p < 4; p++)
                    acc[p] += r[dy][p + dx] * wv[dy * 3 + dx];
        __half2 p0 = __floats2half2_rn(fmaxf(acc[0], 0.f), fmaxf(acc[1], 0.f));
        __half2 p1 = __floats2half2_rn(fmaxf(acc[2], 0.f), fmaxf(acc[3], 0.f));
        uint2 u;
        u.x = *(uint32_t*)&p0; u.y = *(uint32_t*)&p1;
        *(uint2*)&g_h1h[obase + (long)oc * IMGD * IMGD] = u;
    }
}

// ==================== conv2: fp16 HMMA, 9-tap shifted GEMM ====================
// CTA tile: 4 rows x 32 px = 128 px, all 64 oc. 8 warps = 4M x 2N (32px x 32oc).
__global__ void __launch_bounds__(256) conv2mma_kernel(const float* __restrict__ bias) {
    __shared__ __half X_s[6 * 34 * 72];   // [win 6x34 pos][ic 64 +pad8]
    __shared__ __half W_s[64 * 72];       // [oc][ic +pad8]
    int tid = threadIdx.x, lane = tid & 31, wid = tid >> 5;
    int b = blockIdx.z, y0 = blockIdx.y * 4, x0 = blockIdx.x * 32;
    int wm = (wid & 3) * 32;
    int wn = (wid >> 2) * 32;

    // fill input window (rows y0-1..y0+4, cols x0-1..x0+32), zeros outside
    for (int idx = tid; idx < 6 * 34 * 64; idx += 256) {
        int ic = idx / 204;
        int pos = idx - ic * 204;
        int row = pos / 34, col = pos - row * 34;
        int gy = y0 + row - 1, gx = x0 + col - 1;
        __half v = __ushort_as_half(0);
        if (gy >= 0 && gy < IMGD && gx >= 0 && gx < IMGD)
            v = g_h1h[(((long)b * HID + ic) << 16) + (gy << 8) + gx];
        X_s[pos * 72 + ic] = v;
    }

    float acc[2][4][4];
#pragma unroll
    for (int i = 0; i < 2; i++)
#pragma unroll
        for (int j = 0; j < 4; j++)
#pragma unroll
            for (int q = 0; q < 4; q++) acc[i][j][q] = 0.f;

    uint32_t xbase = smem_to_u32(X_s), wbase = smem_to_u32(W_s);

    for (int tap = 0; tap < 9; tap++) {
        __syncthreads();
#pragma unroll
        for (int l = 0; l < 4; l++) {
            int idx = tid + l * 256;
            int oc = idx >> 4, part = idx & 15;
            *(uint2*)&W_s[oc * 72 + part * 4] =
                ((const uint2*)(g_w2t + tap * 4096 + oc * 64))[part];
        }
        __syncthreads();
        int dy = tap / 3, dx = tap - dy * 3;
#pragma unroll
        for (int kb = 0; kb < 64; kb += 16) {
            uint32_t af[2][4], bf[4][2];
#pragma unroll
            for (int am = 0; am < 2; am++) {
                int pxw = wm + am * 16;
                int rr = pxw >> 5, cc = pxw & 31;
                uint32_t addr = xbase +
                    (uint32_t)(((rr + dy) * 34 + cc + dx + (lane & 15)) * 144) +
                    (uint32_t)(kb * 2 + (lane >> 4) * 16);
                ldmatrix_x4(af[am], addr);
            }
#pragma unroll
            for (int an = 0; an < 4; an++) {
                uint32_t addr = wbase +
                    (uint32_t)((wn + an * 8 + (lane & 7)) * 144) +
                    (uint32_t)(kb * 2 + ((lane >> 3) & 1) * 16);
                ldmatrix_x2(bf[an], addr);
            }
#pragma unroll
            for (int am = 0; am < 2; am++)
#pragma unroll
                for (int an = 0; an < 4; an++)
                    mma16816_f16(acc[am][an], af[am], bf[an]);
        }
    }

    // epilogue: C[px][oc] -> h2[oc plane][y][x], bias + relu
    int r0 = lane >> 2, c0l = (lane & 3) * 2;
#pragma unroll
    for (int am = 0; am < 2; am++) {
#pragma unroll
        for (int an = 0; an < 4; an++) {
            int oc = wn + an * 8 + c0l;
            float b0 = bias[oc], b1 = bias[oc + 1];
#pragma unroll
            for (int h = 0; h < 2; h++) {
                int px = wm + am * 16 + r0 + h * 8;
                int rr = px >> 5, cc = px & 31;
                long o = (((long)b * HID + oc) << 16) + ((y0 + rr) << 8) + (x0 + cc);
                g_h2[o] = fmaxf(acc[am][an][h * 2 + 0] + b0, 0.f);
                g_h2[o + (1L << 16)] = fmaxf(acc[am][an][h * 2 + 1] + b1, 0.f);
            }
        }
    }
}

// ==================== conv3: 64 -> 1, 3x3 SAME (fp32) =========================
__global__ void __launch_bounds__(256) conv3_kernel(const float* __restrict__ w,
                             const float* __restrict__ bias) {
    __shared__ float sIn[4 * 18 * 66];
    __shared__ float sW[576];
    int b = blockIdx.z;
    int x0 = blockIdx.x * 64, y0 = blockIdx.y * 16;
    int tid = threadIdx.x;
    for (int i = tid; i < 576; i += 256) sW[i] = w[i];
    int tx = tid & 15, ty = tid >> 4;
    float acc[4] = {0.f, 0.f, 0.f, 0.f};
    for (int cc = 0; cc < 16; cc++) {
        __syncthreads();
        for (int i = tid; i < 4 * 18 * 66; i += 256) {
            int ic = i / 1188;
            int rem = i - ic * 1188;
            int yy = rem / 66, xx = rem - yy * 66;
            int gy = y0 + yy - 1, gx = x0 + xx - 1;
            float v = 0.f;
            if (gy >= 0 && gy < IMGD && gx >= 0 && gx < IMGD)
                v = g_h2[((long)b * HID + cc * 4 + ic) * (IMGD * IMGD) + gy * IMGD + gx];
            sIn[i] = v;
        }
        __syncthreads();
#pragma unroll
        for (int ic = 0; ic < 4; ic++) {
            float rin[3][6];
#pragma unroll
            for (int dy = 0; dy < 3; dy++)
#pragma unroll
                for (int dx = 0; dx < 6; dx++)
                    rin[dy][dx] = sIn[ic * 1188 + (ty + dy) * 66 + (tx * 4 + dx)];
            float wv[9];
#pragma unroll
            for (int t = 0; t < 9; t++) wv[t] = sW[(cc * 4 + ic) * 9 + t];
#pragma unroll
            for (int dy = 0; dy < 3; dy++)
#pragma unroll
                for (int dx = 0; dx < 3; dx++)
#pragma unroll
                    for (int p = 0; p < 4; p++)
                        acc[p] += rin[dy][p + dx] * wv[dy * 3 + dx];
        }
    }
    float bv = bias[0];
    float4 o;
    o.x = acc[0] + bv; o.y = acc[1] + bv; o.z = acc[2] + bv; o.w = acc[3] + bv;
    *(float4*)&g_tmp2[(long)b * IMGD * IMGD + (y0 + ty) * IMGD + x0 + tx * 4] = o;
}

// ==================== GCN branch ====================

__global__ void patch_kernel(const float* __restrict__ in) {
    int idx = blockIdx.x * 256 + threadIdx.x;
    if (idx >= BB * NPAT * 8) return;
    int i = idx & 7;
    int t = idx >> 3;
    int n = t % NPAT;
    int b = t / NPAT;
    int py = n / PH, px = n - py * PH;
    const float* src = in + (long)b * IMGD * IMGD + (py * 4 + i) * IMGD + px * 4;
    float* dst = g_patch + ((long)b * NPAT + n) * PPF + i * 8;
    *(float4*)dst = *(const float4*)src;
    *(float4*)(dst + 4) = *(const float4*)(src + 4);
}

// adj fp32 -> bf16 K-padded; flat-aligned float4 loads over all batches
__global__ void __launch_bounds__(256) adjconv_kernel(const float* __restrict__ adj) {
    long t = (long)blockIdx.x * 256 + threadIdx.x;
    const long TOT4 = 15752961;  // 4*NPAT*NPAT/4 (exact)
    if (t >= TOT4) return;
    float4 v = ((const float4*)adj)[t];
    long e = 4 * t;
    int b = (int)(e / ((long)NPAT * NPAT));
    int rem = (int)(e - (long)b * NPAT * NPAT);
    int m = rem / NPAT;
    int k = rem - m * NPAT;
    float vals[4] = {v.x, v.y, v.z, v.w};
#pragma unroll
    for (int j = 0; j < 4; j++) {
        g_adjb[((long)b * NPAT + m) * KPAD + k] = __float2bfloat16(vals[j]);
        if (++k == NPAT) { k = 0; if (++m == NPAT) { m = 0; b++; } }
    }
}

// zero pad columns k in [NPAT, KPAD)
__global__ void adjpad_kernel() {
    long idx = (long)blockIdx.x * 256 + threadIdx.x;
    const long total = (long)BB * NPAT * (KPAD - NPAT);
    if (idx >= total) return;
    int j = (int)(idx % (KPAD - NPAT));
    long t = idx / (KPAD - NPAT);
    g_adjb[t * KPAD + NPAT + j] = __float2bfloat16(0.f);
}

// supT[b][g][n] = sum_k patch[b][n][k] * w3[k][g]
__global__ void __launch_bounds__(128) gemmA_kernel(const float* __restrict__ w3) {
    __shared__ float sP[32][65];
    __shared__ float sW[64][128];
    int b = blockIdx.y;
    int n0 = blockIdx.x * 32;
    int tid = threadIdx.x;
    for (int l = 0; l < 64; l++) {
        int idx = tid + l * 128;
        sW[idx >> 7][idx & 127] = w3[idx];
    }
    for (int l = 0; l < 16; l++) {
        int idx = tid + l * 128;
        int n = idx >> 6, k = idx & 63;
        float v = 0.f;
        if (n0 + n < NPAT) v = g_patch[((long)b * NPAT + n0 + n) * PPF + k];
        sP[n][k] = v;
    }
    __syncthreads();
    int g = tid;
    float acc[32];
#pragma unroll
    for (int n = 0; n < 32; n++) acc[n] = 0.f;
    for (int k = 0; k < 64; k++) {
        float wv = sW[k][g];
#pragma unroll
        for (int n = 0; n < 32; n++) acc[n] += sP[n][k] * wv;
    }
    __nv_bfloat16* dst = g_supT + ((long)b * GHD + g) * KPAD + n0;
#pragma unroll
    for (int n = 0; n < 32; n++)
        dst[n] = (n0 + n < NPAT) ? __float2bfloat16(acc[n]) : __float2bfloat16(0.f);
}

// gsupT[b][p][n] = sum_g g[b][n][g] * w4[g][p]
__global__ void __launch_bounds__(128) gemmB_kernel(const float* __restrict__ w4) {
    __shared__ float sG[32][129];
    __shared__ float sW[64][64];
    int b = blockIdx.y;
    int n0 = blockIdx.x * 32;
    int tid = threadIdx.x;
    int p = tid & 63, half = tid >> 6;
    float acc[16];
#pragma unroll
    for (int i = 0; i < 16; i++) acc[i] = 0.f;
    for (int kc = 0; kc < 2; kc++) {
        __syncthreads();
        for (int l = 0; l < 32; l++) {
            int idx = tid + l * 128;
            int kk = idx >> 6, pp = idx & 63;
            sW[kk][pp] = w4[(kc * 64 + kk) * 64 + pp];
        }
        for (int l = 0; l < 16; l++) {
            int idx = tid + l * 128;
            int n = idx >> 6, kk = idx & 63;
            float v = 0.f;
            if (n0 + n < NPAT) v = g_g[((long)b * NPAT + n0 + n) * GHD + kc * 64 + kk];
            sG[n][kk] = v;
        }
        __syncthreads();
        for (int kk = 0; kk < 64; kk++) {
            float wv = sW[kk][p];
#pragma unroll
            for (int i = 0; i < 16; i++) acc[i] += sG[half * 16 + i][kk] * wv;
        }
    }
    __nv_bfloat16* dst = g_gsupT + ((long)b * PPF + p) * KPAD + n0 + half * 16;
#pragma unroll
    for (int i = 0; i < 16; i++)
        dst[i] = (n0 + half * 16 + i < NPAT) ? __float2bfloat16(acc[i]) : __float2bfloat16(0.f);
}

// ---------------- big HMMA GEMM: C[b][m][NN] = adjb @ B^T + bias --------------
// A: bf16 [b][NPAT][KPAD], B: bf16 [b][NN][KPAD]; BM=128, BK=32, 8 warps.
#define LDT 40   // smem row stride bf16 (80 B, conflict-free ldmatrix)

template<int NN>
__global__ void __launch_bounds__(256) mma_gemm_kernel(
        const __nv_bfloat16* __restrict__ A,
        const __nv_bfloat16* __restrict__ B,
        float* __restrict__ C,
        const float* __restrict__ bias, int relu) {
    constexpr int WN = NN / 4;
    constexpr int NA = WN / 8;
    __shared__ __align__(16) __nv_bfloat16 A_s[2][128 * LDT];
    __shared__ __align__(16) __nv_bfloat16 B_s[2][NN * LDT];

    int tid = threadIdx.x;
    int lane = tid & 31;
    int wid = tid >> 5;
    int wm = (wid & 1) * 64;
    int wn = (wid >> 1) * WN;
    int bz = blockIdx.z;
    int m0 = blockIdx.x * 128;

    const __nv_bfloat16* Ab = A + (long)bz * NPAT * KPAD;
    const __nv_bfloat16* Bb = B + (long)bz * NN * KPAD;
    float* Cb = C + (long)bz * NPAT * NN;

    float acc[4][NA][4];
#pragma unroll
    for (int i = 0; i < 4; i++)
#pragma unroll
        for (int j = 0; j < NA; j++)
#pragma unroll
            for (int q = 0; q < 4; q++) acc[i][j][q] = 0.f;

    int ar = tid >> 1, aq = tid & 1;
    int gm = m0 + ar;
    bool bact = tid < NN * 2;
    int bn = tid >> 1, bh = tid & 1;

    uint4 ra0, ra1;
    uint4 rb0, rb1;

    // prologue: chunk 0
    {
        ra0 = make_uint4(0u, 0u, 0u, 0u); ra1 = ra0;
        if (gm < NPAT) {
            const uint4* p = (const uint4*)(Ab + (long)gm * KPAD + aq * 16);
            ra0 = p[0]; ra1 = p[1];
        }
        if (bact) {
            const __nv_bfloat16* brow = Bb + (long)bn * KPAD + bh * 16;
            rb0 = *(const uint4*)brow;
            rb1 = *(const uint4*)(brow + 8);
        }
        uint4* ad = (uint4*)&A_s[0][ar * LDT + aq * 16];
        ad[0] = ra0; ad[1] = ra1;
        if (bact) {
            __nv_bfloat16* bd = &B_s[0][bn * LDT + bh * 16];
            *(uint4*)bd = rb0;
            *(uint4*)(bd + 8) = rb1;
        }
    }
    __syncthreads();

    for (int c = 0; c < NCHUNK; c++) {
        int cur = c & 1;
        if (c + 1 < NCHUNK) {
            long kb = (long)(c + 1) * 32;
            ra0 = make_uint4(0u, 0u, 0u, 0u); ra1 = ra0;
            if (gm < NPAT) {
                const uint4* p = (const uint4*)(Ab + (long)gm * KPAD + kb + aq * 16);
                ra0 = p[0]; ra1 = p[1];
            }
            if (bact) {
                const __nv_bfloat16* brow = Bb + (long)bn * KPAD + kb + bh * 16;
                rb0 = *(const uint4*)brow;
                rb1 = *(const uint4*)(brow + 8);
            }
        }
        uint32_t a_base = smem_to_u32(&A_s[cur][0]);
        uint32_t b_base = smem_to_u32(&B_s[cur][0]);
#pragma unroll
        for (int ks = 0; ks < 2; ks++) {
            uint32_t af[4][4];
#pragma unroll
            for (int am = 0; am < 4; am++) {
                uint32_t addr = a_base +
                    (uint32_t)((wm + am * 16 + (lane & 15)) * (LDT * 2)) +
                    (uint32_t)(ks * 32 + (lane >> 4) * 16);
                ldmatrix_x4(af[am], addr);
            }
            uint32_t bf[NA][2];
#pragma unroll
            for (int an = 0; an < NA; an++) {
                uint32_t addr = b_base +
                    (uint32_t)((wn + an * 8 + (lane & 7)) * (LDT * 2)) +
                    (uint32_t)(ks * 32 + ((lane >> 3) & 1) * 16);
                ldmatrix_x2(bf[an], addr);
            }
#pragma unroll
            for (int am = 0; am < 4; am++)
#pragma unroll
                for (int an = 0; an < NA; an++)
                    mma16816_bf16(acc[am][an], af[am], bf[an]);
        }
        if (c + 1 < NCHUNK) {
            int nxt = cur ^ 1;
            uint4* ad = (uint4*)&A_s[nxt][ar * LDT + aq * 16];
            ad[0] = ra0; ad[1] = ra1;
            if (bact) {
                __nv_bfloat16* bd = &B_s[nxt][bn * LDT + bh * 16];
                *(uint4*)bd = rb0;
                *(uint4*)(bd + 8) = rb1;
            }
        }
        __syncthreads();
    }

    int r0 = lane >> 2, c0 = (lane & 3) * 2;
#pragma unroll
    for (int am = 0; am < 4; am++) {
#pragma unroll
        for (int an = 0; an < NA; an++) {
            int gn = wn + an * 8 + c0;
            float b0 = bias[gn], b1 = bias[gn + 1];
            int gr0 = m0 + wm + am * 16 + r0;
            float v0 = acc[am][an][0] + b0;
            float v1 = acc[am][an][1] + b1;
            float v2 = acc[am][an][2] + b0;
            float v3 = acc[am][an][3] + b1;
            if (relu) {
                v0 = fmaxf(v0, 0.f); v1 = fmaxf(v1, 0.f);
                v2 = fmaxf(v2, 0.f); v3 = fmaxf(v3, 0.f);
            }
            if (gr0 < NPAT) {
                Cb[(long)gr0 * NN + gn] = v0;
                Cb[(long)gr0 * NN + gn + 1] = v1;
            }
            if (gr0 + 8 < NPAT) {
                Cb[(long)(gr0 + 8) * NN + gn] = v2;
                Cb[(long)(gr0 + 8) * NN + gn + 1] = v3;
            }
        }
    }
}

// ---------------- final: tmp1 + tmp2 + patch2img(g2)/mask, relu --------------
__global__ void final_kernel(const float* __restrict__ in,
                             const float* __restrict__ proj,
                             const float* __restrict__ lam,
                             float* __restrict__ out) {
    int idx = blockIdx.x * 256 + threadIdx.x;
    if (idx >= BB * IMGD * IMGD) return;
    int x = idx & 255, y = (idx >> 8) & 255, b = idx >> 16;
    float lv = lam[0];
    float iv = in[idx], pv = proj[idx];
    float t1 = iv + lv * (pv - iv);
    float t2 = g_tmp2[idx];
    int tyv = y - 7;
    int py_lo = tyv > 0 ? (tyv + 3) >> 2 : 0;
    int py_hi = min(62, y >> 2);
    int txv = x - 7;
    int px_lo = txv > 0 ? (txv + 3) >> 2 : 0;
    int px_hi = min(62, x >> 2);
    float s = 0.f;
    int cnt = (py_hi - py_lo + 1) * (px_hi - px_lo + 1);
    for (int py = py_lo; py <= py_hi; py++) {
        int i = y - 4 * py;
        for (int px = px_lo; px <= px_hi; px++) {
            int j = x - 4 * px;
            s += g_g2[((long)b * NPAT + (py * PH + px)) * PPF + i * 8 + j];
        }
    }
    float v = t1 + t2 + s / (float)cnt;
    out[idx] = fmaxf(v, 0.f);
}

// ---------------- launch ----------------
extern "C" void kernel_launch(void* const* d_in, const int* in_sizes, int n_in,
                              void* d_out, int out_size) {
    const float* input = (const float*)d_in[0];
    const float* proj  = (const float*)d_in[1];
    const float* adj   = (const float*)d_in[2];
    const float* lam   = (const float*)d_in[3];
    const float* w1 = (const float*)d_in[4];
    const float* b1 = (const float*)d_in[5];
    const float* w2 = (const float*)d_in[6];
    const float* b2 = (const float*)d_in[7];
    const float* w3 = (const float*)d_in[8];
    const float* b3 = (const float*)d_in[9];
    const float* gw3 = (const float*)d_in[10];
    const float* gb3 = (const float*)d_in[11];
    const float* gw4 = (const float*)d_in[12];
    const float* gb4 = (const float*)d_in[13];
    float* out = (float*)d_out;

    __nv_bfloat16 *p_adjb, *p_supT, *p_gsupT;
    float *p_g, *p_g2;
    cudaGetSymbolAddress((void**)&p_adjb, g_adjb);
    cudaGetSymbolAddress((void**)&p_supT, g_supT);
    cudaGetSymbolAddress((void**)&p_gsupT, g_gsupT);
    cudaGetSymbolAddress((void**)&p_g, g_g);
    cudaGetSymbolAddress((void**)&p_g2, g_g2);

    // order chosen so conv2mma is the 4th user kernel (ncu -s 5 slot)
    wt_kernel<<<144, 256>>>(w2);
    conv1_kernel<<<dim3(4, 16, BB), 256>>>(input, w1, b1);
    patch_kernel<<<(BB * NPAT * 8 + 255) / 256, 256>>>(input);
    conv2mma_kernel<<<dim3(8, 64, BB), 256>>>(b2);

    adjconv_kernel<<<(15752961 + 255) / 256, 256>>>(adj);
    adjpad_kernel<<<(int)(((long)BB * NPAT * (KPAD - NPAT) + 255) / 256), 256>>>();
    gemmA_kernel<<<dim3(KPAD / 32, BB), 128>>>(gw3);
    mma_gemm_kernel<128><<<dim3(32, 1, BB), 256>>>(p_adjb, p_supT, p_g, gb3, 1);
    conv3_kernel<<<dim3(4, 16, BB), 256>>>(w3, b3);
    gemmB_kernel<<<dim3(KPAD / 32, BB), 128>>>(gw4);
    mma_gemm_kernel<64><<<dim3(32, 1, BB), 256>>>(p_adjb, p_gsupT, p_g2, gb4, 0);

    final_kernel<<<(BB * IMGD * IMGD + 255) / 256, 256>>>(input, proj, lam, out);
}

// round 6
// speedup vs baseline: 4.5455x; 1.0277x over previous
#include <cuda_runtime.h>
#include <cuda_bf16.h>
#include <cuda_fp16.h>
#include <cstdint>

// ---------------- problem constants ----------------
#define BB   4
#define IMGD 256
#define HID  64
#define PH   63
#define NPAT 3969   // 63*63
#define PPF  64     // 8*8 patch pixels
#define GHD  128
#define KPAD 4032   // 63*64, padded K for tensor GEMM
#define NCHUNK 126  // KPAD / 32

// ---------------- scratch (device globals; no runtime alloc) ----------------
__device__ __half g_h1i[(long)BB*IMGD*IMGD*HID];      // conv1 out, [b][y][x][ic] fp16
__device__ __half g_h2h[(long)BB*HID*IMGD*IMGD];      // conv2 out, [b][oc][y][x] fp16
__device__ float g_tmp2[BB*IMGD*IMGD];                // conv3 out
__device__ float g_patch[BB*NPAT*PPF];                // [b][n][64]
__device__ float g_g[(long)BB*NPAT*GHD];              // relu(adj@sup+b3)
__device__ float g_g2[(long)BB*NPAT*PPF];             // adj@gsup+b4
__device__ __nv_bfloat16 g_adjb[(long)BB*NPAT*KPAD];  // adj bf16 K-padded
__device__ __nv_bfloat16 g_supT[(long)BB*GHD*KPAD];   // (patch@W3)^T bf16
__device__ __nv_bfloat16 g_gsupT[(long)BB*PPF*KPAD];  // (g@W4)^T bf16
__device__ __half g_w2t[9*64*64];                     // w2 [tap][oc][ic] fp16

__device__ __forceinline__ uint32_t smem_to_u32(const void* p) {
    uint32_t a;
    asm("{ .reg .u64 t; cvta.to.shared.u64 t, %1; cvt.u32.u64 %0, t; }"
        : "=r"(a) : "l"(p));
    return a;
}
__device__ __forceinline__ void ldmatrix_x4(uint32_t* r, uint32_t addr) {
    asm volatile("ldmatrix.sync.aligned.m8n8.x4.shared.b16 {%0,%1,%2,%3}, [%4];"
                 : "=r"(r[0]), "=r"(r[1]), "=r"(r[2]), "=r"(r[3]) : "r"(addr));
}
__device__ __forceinline__ void ldmatrix_x2(uint32_t* r, uint32_t addr) {
    asm volatile("ldmatrix.sync.aligned.m8n8.x2.shared.b16 {%0,%1}, [%2];"
                 : "=r"(r[0]), "=r"(r[1]) : "r"(addr));
}
__device__ __forceinline__ void mma16816_bf16(float* d, const uint32_t* a, const uint32_t* b) {
    asm volatile(
        "mma.sync.aligned.m16n8k16.row.col.f32.bf16.bf16.f32 "
        "{%0,%1,%2,%3}, {%4,%5,%6,%7}, {%8,%9}, {%0,%1,%2,%3};"
        : "+f"(d[0]), "+f"(d[1]), "+f"(d[2]), "+f"(d[3])
        : "r"(a[0]), "r"(a[1]), "r"(a[2]), "r"(a[3]), "r"(b[0]), "r"(b[1]));
}
__device__ __forceinline__ void mma16816_f16(float* d, const uint32_t* a, const uint32_t* b) {
    asm volatile(
        "mma.sync.aligned.m16n8k16.row.col.f32.f16.f16.f32 "
        "{%0,%1,%2,%3}, {%4,%5,%6,%7}, {%8,%9}, {%0,%1,%2,%3};"
        : "+f"(d[0]), "+f"(d[1]), "+f"(d[2]), "+f"(d[3])
        : "r"(a[0]), "r"(a[1]), "r"(a[2]), "r"(a[3]), "r"(b[0]), "r"(b[1]));
}

// ==================== weight transform: w2 OIHW -> [tap][oc][ic] fp16 =========
__global__ void wt_kernel(const float* __restrict__ w2) {
    int idx = blockIdx.x * 256 + threadIdx.x;
    if (idx >= 64 * 64 * 9) return;
    int oc = idx / 576, r = idx - oc * 576;
    int ic = r / 9, t = r - ic * 9;
    g_w2t[t * 4096 + oc * 64 + ic] = __float2half(w2[idx]);
}

// ==================== conv1: 1 -> 64, relu, interleaved fp16 out =============
// 16x16 px tile, thread = 1 px, oc in chunks of 8; staged via smem for
// fully-coalesced uint4 stores of the [y][x][ic] layout.
__global__ void __launch_bounds__(256) conv1_kernel(const float* __restrict__ in,
                             const float* __restrict__ w,
                             const float* __restrict__ bias) {
    __shared__ float sIn[18][18];
    __shared__ float sW[576];
    __shared__ float sB[64];
    __shared__ __half sOut[16 * 16 * 64];   // 32 KB
    int b = blockIdx.z;
    int x0 = blockIdx.x * 16, y0 = blockIdx.y * 16;
    int tid = threadIdx.x;
    for (int i = tid; i < 576; i += 256) sW[i] = w[i];
    if (tid < 64) sB[tid] = bias[tid];
    for (int i = tid; i < 324; i += 256) {
        int yy = i / 18, xx = i - yy * 18;
        int gy = y0 + yy - 1, gx = x0 + xx - 1;
        float v = 0.f;
        if (gy >= 0 && gy < IMGD && gx >= 0 && gx < IMGD)
            v = in[(long)b * IMGD * IMGD + gy * IMGD + gx];
        sIn[yy][xx] = v;
    }
    __syncthreads();
    int tx = tid & 15, ty = tid >> 4;
    float r[9];
#pragma unroll
    for (int dy = 0; dy < 3; dy++)
#pragma unroll
        for (int dx = 0; dx < 3; dx++)
            r[dy * 3 + dx] = sIn[ty + dy][tx + dx];
#pragma unroll 1
    for (int oc0 = 0; oc0 < 64; oc0 += 8) {
        __half hv[8];
#pragma unroll
        for (int o = 0; o < 8; o++) {
            float acc = sB[oc0 + o];
#pragma unroll
            for (int t = 0; t < 9; t++) acc += r[t] * sW[(oc0 + o) * 9 + t];
            hv[o] = __float2half(fmaxf(acc, 0.f));
        }
        *(uint4*)&sOut[tid * 64 + oc0] = *(uint4*)hv;
    }
    __syncthreads();
    // copy out: per gy row, 16 px x 64 ic = 1024 halves contiguous
    for (int i = tid; i < 2048; i += 256) {
        int row = i >> 7;        // 128 uint4 per row
        int c = i & 127;
        long e = (((long)b * IMGD * IMGD + (y0 + row) * IMGD + x0) << 6) + c * 8;
        *(uint4*)&g_h1i[e] = *(uint4*)&sOut[row * 1024 + c * 8];
    }
}

// ==================== conv2: fp16 HMMA, 9-tap shifted GEMM (v2) ===============
// CTA tile: 8 rows x 32 px = 256 px, 64 oc. 8 warps = 4M x 2N (64px x 32oc).
// X window [10][34][64ic] interleaved; W double-buffered, 1 barrier per tap.
#define C2_XH (340 * 72)          // X halves
#define C2_WH (64 * 72)           // W halves per buffer
__global__ void __launch_bounds__(256) conv2mma_kernel(const float* __restrict__ bias) {
    extern __shared__ __half dsm[];
    __half* X_s = dsm;                       // [pos 340][72]
    __half* W_s[2] = {dsm + C2_XH, dsm + C2_XH + C2_WH};
    int tid = threadIdx.x, lane = tid & 31, wid = tid >> 5;
    int b = blockIdx.z, y0 = blockIdx.y * 8, x0 = blockIdx.x * 32;
    int wm = (wid & 3) * 64;
    int wn = (wid >> 2) * 32;

    // X fill: 340 pos x 8 uint4, coalesced from interleaved layout
    for (int i = tid; i < 2720; i += 256) {
        int pos = i >> 3, q = i & 7;
        int row = pos / 34, col = pos - row * 34;
        int gy = y0 + row - 1, gx = x0 + col - 1;
        uint4 v = make_uint4(0u, 0u, 0u, 0u);
        if (gy >= 0 && gy < IMGD && gx >= 0 && gx < IMGD)
            v = *(const uint4*)&g_h1i[(((long)b * IMGD * IMGD + gy * IMGD + gx) << 6) + q * 8];
        *(uint4*)&X_s[pos * 72 + q * 8] = v;
    }
    // W tap 0
    for (int i = tid; i < 512; i += 256) {
        int oc = i >> 3, q = i & 7;
        *(uint4*)&W_s[0][oc * 72 + q * 8] = *(const uint4*)&g_w2t[oc * 64 + q * 8];
    }
    __syncthreads();

    float acc[4][4][4];
#pragma unroll
    for (int i = 0; i < 4; i++)
#pragma unroll
        for (int j = 0; j < 4; j++)
#pragma unroll
            for (int q = 0; q < 4; q++) acc[i][j][q] = 0.f;

    uint32_t xb = smem_to_u32(X_s);
    uint32_t wb[2] = {smem_to_u32(W_s[0]), smem_to_u32(W_s[1])};

    // per-am A base (row of 16 px stays within one 32-px window row)
    uint32_t abase[4];
#pragma unroll
    for (int am = 0; am < 4; am++) {
        int p0 = wm + am * 16;
        abase[am] = xb + (uint32_t)((((p0 >> 5) * 34) + (p0 & 31) + (lane & 15)) * 144)
                       + (uint32_t)((lane >> 4) * 16);
    }
    uint32_t bbase[4];
#pragma unroll
    for (int an = 0; an < 4; an++)
        bbase[an] = (uint32_t)((wn + an * 8 + (lane & 7)) * 144)
                  + (uint32_t)(((lane >> 3) & 1) * 16);

    for (int tap = 0; tap < 9; tap++) {
        int cur = tap & 1;
        if (tap < 8) {
            const __half* src = g_w2t + (tap + 1) * 4096;
            for (int i = tid; i < 512; i += 256) {
                int oc = i >> 3, q = i & 7;
                *(uint4*)&W_s[cur ^ 1][oc * 72 + q * 8] = *(const uint4*)&src[oc * 64 + q * 8];
            }
        }
        int dy = tap / 3, dx = tap - dy * 3;
        uint32_t toff = (uint32_t)((dy * 34 + dx) * 144);
#pragma unroll
        for (int kb = 0; kb < 64; kb += 16) {
            uint32_t af[4][4], bf[4][2];
#pragma unroll
            for (int am = 0; am < 4; am++)
                ldmatrix_x4(af[am], abase[am] + toff + kb * 2);
#pragma unroll
            for (int an = 0; an < 4; an++)
                ldmatrix_x2(bf[an], wb[cur] + bbase[an] + kb * 2);
#pragma unroll
            for (int am = 0; am < 4; am++)
#pragma unroll
                for (int an = 0; an < 4; an++)
                    mma16816_f16(acc[am][an], af[am], bf[an]);
        }
        __syncthreads();
    }

    // epilogue: plane-major fp16 out, bias + relu
    int r0 = lane >> 2, c0l = (lane & 3) * 2;
#pragma unroll
    for (int am = 0; am < 4; am++) {
#pragma unroll
        for (int an = 0; an < 4; an++) {
            int oc = wn + an * 8 + c0l;
            float b0 = bias[oc], b1 = bias[oc + 1];
#pragma unroll
            for (int h = 0; h < 2; h++) {
                int p = wm + am * 16 + r0 + h * 8;
                int rr = p >> 5, cc = p & 31;
                long o = (((long)b * HID + oc) << 16) + ((y0 + rr) << 8) + (x0 + cc);
                g_h2h[o] = __float2half(fmaxf(acc[am][an][h * 2 + 0] + b0, 0.f));
                g_h2h[o + (1L << 16)] = __float2half(fmaxf(acc[am][an][h * 2 + 1] + b1, 0.f));
            }
        }
    }
}

// ==================== conv3: 64 -> 1, 3x3 SAME (fp32 math, fp16 in) ===========
__global__ void __launch_bounds__(256) conv3_kernel(const float* __restrict__ w,
                             const float* __restrict__ bias) {
    __shared__ float sIn[4 * 18 * 66];
    __shared__ float sW[576];
    int b = blockIdx.z;
    int x0 = blockIdx.x * 64, y0 = blockIdx.y * 16;
    int tid = threadIdx.x;
    for (int i = tid; i < 576; i += 256) sW[i] = w[i];
    int tx = tid & 15, ty = tid >> 4;
    float acc[4] = {0.f, 0.f, 0.f, 0.f};
    for (int cc = 0; cc < 16; cc++) {
        __syncthreads();
        for (int i = tid; i < 4 * 18 * 66; i += 256) {
            int ic = i / 1188;
            int rem = i - ic * 1188;
            int yy = rem / 66, xx = rem - yy * 66;
            int gy = y0 + yy - 1, gx = x0 + xx - 1;
            float v = 0.f;
            if (gy >= 0 && gy < IMGD && gx >= 0 && gx < IMGD)
                v = __half2float(g_h2h[(((long)b * HID + cc * 4 + ic) << 16) + (gy << 8) + gx]);
            sIn[i] = v;
        }
        __syncthreads();
#pragma unroll
        for (int ic = 0; ic < 4; ic++) {
            float rin[3][6];
#pragma unroll
            for (int dy = 0; dy < 3; dy++)
#pragma unroll
                for (int dx = 0; dx < 6; dx++)
                    rin[dy][dx] = sIn[ic * 1188 + (ty + dy) * 66 + (tx * 4 + dx)];
            float wv[9];
#pragma unroll
            for (int t = 0; t < 9; t++) wv[t] = sW[(cc * 4 + ic) * 9 + t];
#pragma unroll
            for (int dy = 0; dy < 3; dy++)
#pragma unroll
                for (int dx = 0; dx < 3; dx++)
#pragma unroll
                    for (int p = 0; p < 4; p++)
                        acc[p] += rin[dy][p + dx] * wv[dy * 3 + dx];
        }
    }
    float bv = bias[0];
    float4 o;
    o.x = acc[0] + bv; o.y = acc[1] + bv; o.z = acc[2] + bv; o.w = acc[3] + bv;
    *(float4*)&g_tmp2[(long)b * IMGD * IMGD + (y0 + ty) * IMGD + x0 + tx * 4] = o;
}

// ==================== GCN branch ====================

__global__ void patch_kernel(const float* __restrict__ in) {
    int idx = blockIdx.x * 256 + threadIdx.x;
    if (idx >= BB * NPAT * 8) return;
    int i = idx & 7;
    int t = idx >> 3;
    int n = t % NPAT;
    int b = t / NPAT;
    int py = n / PH, px = n - py * PH;
    const float* src = in + (long)b * IMGD * IMGD + (py * 4 + i) * IMGD + px * 4;
    float* dst = g_patch + ((long)b * NPAT + n) * PPF + i * 8;
    *(float4*)dst = *(const float4*)src;
    *(float4*)(dst + 4) = *(const float4*)(src + 4);
}

// adj fp32 -> bf16 K-padded (output-driven: thread owns 8 k's, one STG.128)
__global__ void __launch_bounds__(256) adjconv_kernel(const float* __restrict__ adj) {
    long idx = (long)blockIdx.x * 256 + threadIdx.x;
    const long TOT = (long)BB * NPAT * (KPAD / 8);   // 8001504
    if (idx >= TOT) return;
    int kq = (int)(idx % (KPAD / 8));
    long row = idx / (KPAD / 8);                     // b*NPAT + m
    int k0 = kq * 8;
    const float* src = adj + row * NPAT + k0;
    __nv_bfloat16 o[8];
#pragma unroll
    for (int j = 0; j < 8; j++) {
        float v = (k0 + j < NPAT) ? src[j] : 0.f;
        o[j] = __float2bfloat16(v);
    }
    *(uint4*)&g_adjb[row * KPAD + k0] = *(uint4*)o;
}

// supT[b][g][n] = sum_k patch[b][n][k] * w3[k][g]
__global__ void __launch_bounds__(128) gemmA_kernel(const float* __restrict__ w3) {
    __shared__ float sP[32][65];
    __shared__ float sW[64][128];
    int b = blockIdx.y;
    int n0 = blockIdx.x * 32;
    int tid = threadIdx.x;
    for (int l = 0; l < 64; l++) {
        int idx = tid + l * 128;
        sW[idx >> 7][idx & 127] = w3[idx];
    }
    for (int l = 0; l < 16; l++) {
        int idx = tid + l * 128;
        int n = idx >> 6, k = idx & 63;
        float v = 0.f;
        if (n0 + n < NPAT) v = g_patch[((long)b * NPAT + n0 + n) * PPF + k];
        sP[n][k] = v;
    }
    __syncthreads();
    int g = tid;
    float acc[32];
#pragma unroll
    for (int n = 0; n < 32; n++) acc[n] = 0.f;
    for (int k = 0; k < 64; k++) {
        float wv = sW[k][g];
#pragma unroll
        for (int n = 0; n < 32; n++) acc[n] += sP[n][k] * wv;
    }
    __nv_bfloat16* dst = g_supT + ((long)b * GHD + g) * KPAD + n0;
#pragma unroll
    for (int n = 0; n < 32; n++)
        dst[n] = (n0 + n < NPAT) ? __float2bfloat16(acc[n]) : __float2bfloat16(0.f);
}

// gsupT[b][p][n] = sum_g g[b][n][g] * w4[g][p]
__global__ void __launch_bounds__(128) gemmB_kernel(const float* __restrict__ w4) {
    __shared__ float sG[32][129];
    __shared__ float sW[64][64];
    int b = blockIdx.y;
    int n0 = blockIdx.x * 32;
    int tid = threadIdx.x;
    int p = tid & 63, half = tid >> 6;
    float acc[16];
#pragma unroll
    for (int i = 0; i < 16; i++) acc[i] = 0.f;
    for (int kc = 0; kc < 2; kc++) {
        __syncthreads();
        for (int l = 0; l < 32; l++) {
            int idx = tid + l * 128;
            int kk = idx >> 6, pp = idx & 63;
            sW[kk][pp] = w4[(kc * 64 + kk) * 64 + pp];
        }
        for (int l = 0; l < 16; l++) {
            int idx = tid + l * 128;
            int n = idx >> 6, kk = idx & 63;
            float v = 0.f;
            if (n0 + n < NPAT) v = g_g[((long)b * NPAT + n0 + n) * GHD + kc * 64 + kk];
            sG[n][kk] = v;
        }
        __syncthreads();
        for (int kk = 0; kk < 64; kk++) {
            float wv = sW[kk][p];
#pragma unroll
            for (int i = 0; i < 16; i++) acc[i] += sG[half * 16 + i][kk] * wv;
        }
    }
    __nv_bfloat16* dst = g_gsupT + ((long)b * PPF + p) * KPAD + n0 + half * 16;
#pragma unroll
    for (int i = 0; i < 16; i++)
        dst[i] = (n0 + half * 16 + i < NPAT) ? __float2bfloat16(acc[i]) : __float2bfloat16(0.f);
}

// ---------------- big HMMA GEMM: C[b][m][NN] = adjb @ B^T + bias --------------
#define LDT 40

template<int NN>
__global__ void __launch_bounds__(256) mma_gemm_kernel(
        const __nv_bfloat16* __restrict__ A,
        const __nv_bfloat16* __restrict__ B,
        float* __restrict__ C,
        const float* __restrict__ bias, int relu) {
    constexpr int WN = NN / 4;
    constexpr int NA = WN / 8;
    __shared__ __align__(16) __nv_bfloat16 A_s[2][128 * LDT];
    __shared__ __align__(16) __nv_bfloat16 B_s[2][NN * LDT];

    int tid = threadIdx.x;
    int lane = tid & 31;
    int wid = tid >> 5;
    int wm = (wid & 1) * 64;
    int wn = (wid >> 1) * WN;
    int bz = blockIdx.z;
    int m0 = blockIdx.x * 128;

    const __nv_bfloat16* Ab = A + (long)bz * NPAT * KPAD;
    const __nv_bfloat16* Bb = B + (long)bz * NN * KPAD;
    float* Cb = C + (long)bz * NPAT * NN;

    float acc[4][NA][4];
#pragma unroll
    for (int i = 0; i < 4; i++)
#pragma unroll
        for (int j = 0; j < NA; j++)
#pragma unroll
            for (int q = 0; q < 4; q++) acc[i][j][q] = 0.f;

    int ar = tid >> 1, aq = tid & 1;
    int gm = m0 + ar;
    bool bact = tid < NN * 2;
    int bn = tid >> 1, bh = tid & 1;

    uint4 ra0, ra1, rb0, rb1;

    {
        ra0 = make_uint4(0u, 0u, 0u, 0u); ra1 = ra0;
        if (gm < NPAT) {
            const uint4* p = (const uint4*)(Ab + (long)gm * KPAD + aq * 16);
            ra0 = p[0]; ra1 = p[1];
        }
        if (bact) {
            const __nv_bfloat16* brow = Bb + (long)bn * KPAD + bh * 16;
            rb0 = *(const uint4*)brow;
            rb1 = *(const uint4*)(brow + 8);
        }
        uint4* ad = (uint4*)&A_s[0][ar * LDT + aq * 16];
        ad[0] = ra0; ad[1] = ra1;
        if (bact) {
            __nv_bfloat16* bd = &B_s[0][bn * LDT + bh * 16];
            *(uint4*)bd = rb0;
            *(uint4*)(bd + 8) = rb1;
        }
    }
    __syncthreads();

    for (int c = 0; c < NCHUNK; c++) {
        int cur = c & 1;
        if (c + 1 < NCHUNK) {
            long kb = (long)(c + 1) * 32;
            ra0 = make_uint4(0u, 0u, 0u, 0u); ra1 = ra0;
            if (gm < NPAT) {
                const uint4* p = (const uint4*)(Ab + (long)gm * KPAD + kb + aq * 16);
                ra0 = p[0]; ra1 = p[1];
            }
            if (bact) {
                const __nv_bfloat16* brow = Bb + (long)bn * KPAD + kb + bh * 16;
                rb0 = *(const uint4*)brow;
                rb1 = *(const uint4*)(brow + 8);
            }
        }
        uint32_t a_base = smem_to_u32(&A_s[cur][0]);
        uint32_t b_base = smem_to_u32(&B_s[cur][0]);
#pragma unroll
        for (int ks = 0; ks < 2; ks++) {
            uint32_t af[4][4];
#pragma unroll
            for (int am = 0; am < 4; am++) {
                uint32_t addr = a_base +
                    (uint32_t)((wm + am * 16 + (lane & 15)) * (LDT * 2)) +
                    (uint32_t)(ks * 32 + (lane >> 4) * 16);
                ldmatrix_x4(af[am], addr);
            }
            uint32_t bf[NA][2];
#pragma unroll
            for (int an = 0; an < NA; an++) {
                uint32_t addr = b_base +
                    (uint32_t)((wn + an * 8 + (lane & 7)) * (LDT * 2)) +
                    (uint32_t)(ks * 32 + ((lane >> 3) & 1) * 16);
                ldmatrix_x2(bf[an], addr);
            }
#pragma unroll
            for (int am = 0; am < 4; am++)
#pragma unroll
                for (int an = 0; an < NA; an++)
                    mma16816_bf16(acc[am][an], af[am], bf[an]);
        }
        if (c + 1 < NCHUNK) {
            int nxt = cur ^ 1;
            uint4* ad = (uint4*)&A_s[nxt][ar * LDT + aq * 16];
            ad[0] = ra0; ad[1] = ra1;
            if (bact) {
                __nv_bfloat16* bd = &B_s[nxt][bn * LDT + bh * 16];
                *(uint4*)bd = rb0;
                *(uint4*)(bd + 8) = rb1;
            }
        }
        __syncthreads();
    }

    int r0 = lane >> 2, c0 = (lane & 3) * 2;
#pragma unroll
    for (int am = 0; am < 4; am++) {
#pragma unroll
        for (int an = 0; an < NA; an++) {
            int gn = wn + an * 8 + c0;
            float b0 = bias[gn], b1 = bias[gn + 1];
            int gr0 = m0 + wm + am * 16 + r0;
            float v0 = acc[am][an][0] + b0;
            float v1 = acc[am][an][1] + b1;
            float v2 = acc[am][an][2] + b0;
            float v3 = acc[am][an][3] + b1;
            if (relu) {
                v0 = fmaxf(v0, 0.f); v1 = fmaxf(v1, 0.f);
                v2 = fmaxf(v2, 0.f); v3 = fmaxf(v3, 0.f);
            }
            if (gr0 < NPAT) {
                Cb[(long)gr0 * NN + gn] = v0;
                Cb[(long)gr0 * NN + gn + 1] = v1;
            }
            if (gr0 + 8 < NPAT) {
                Cb[(long)(gr0 + 8) * NN + gn] = v2;
                Cb[(long)(gr0 + 8) * NN + gn + 1] = v3;
            }
        }
    }
}

// ---------------- final: tmp1 + tmp2 + patch2img(g2)/mask, relu --------------
__global__ void final_kernel(const float* __restrict__ in,
                             const float* __restrict__ proj,
                             const float* __restrict__ lam,
                             float* __restrict__ out) {
    int idx = blockIdx.x * 256 + threadIdx.x;
    if (idx >= BB * IMGD * IMGD) return;
    int x = idx & 255, y = (idx >> 8) & 255, b = idx >> 16;
    float lv = lam[0];
    float iv = in[idx], pv = proj[idx];
    float t1 = iv + lv * (pv - iv);
    float t2 = g_tmp2[idx];
    int tyv = y - 7;
    int py_lo = tyv > 0 ? (tyv + 3) >> 2 : 0;
    int py_hi = min(62, y >> 2);
    int txv = x - 7;
    int px_lo = txv > 0 ? (txv + 3) >> 2 : 0;
    int px_hi = min(62, x >> 2);
    float s = 0.f;
    int cnt = (py_hi - py_lo + 1) * (px_hi - px_lo + 1);
    for (int py = py_lo; py <= py_hi; py++) {
        int i = y - 4 * py;
        for (int px = px_lo; px <= px_hi; px++) {
            int j = x - 4 * px;
            s += g_g2[((long)b * NPAT + (py * PH + px)) * PPF + i * 8 + j];
        }
    }
    float v = t1 + t2 + s / (float)cnt;
    out[idx] = fmaxf(v, 0.f);
}

// ---------------- launch ----------------
extern "C" void kernel_launch(void* const* d_in, const int* in_sizes, int n_in,
                              void* d_out, int out_size) {
    const float* input = (const float*)d_in[0];
    const float* proj  = (const float*)d_in[1];
    const float* adj   = (const float*)d_in[2];
    const float* lam   = (const float*)d_in[3];
    const float* w1 = (const float*)d_in[4];
    const float* b1 = (const float*)d_in[5];
    const float* w2 = (const float*)d_in[6];
    const float* b2 = (const float*)d_in[7];
    const float* w3 = (const float*)d_in[8];
    const float* b3 = (const float*)d_in[9];
    const float* gw3 = (const float*)d_in[10];
    const float* gb3 = (const float*)d_in[11];
    const float* gw4 = (const float*)d_in[12];
    const float* gb4 = (const float*)d_in[13];
    float* out = (float*)d_out;

    __nv_bfloat16 *p_adjb, *p_supT, *p_gsupT;
    float *p_g, *p_g2;
    cudaGetSymbolAddress((void**)&p_adjb, g_adjb);
    cudaGetSymbolAddress((void**)&p_supT, g_supT);
    cudaGetSymbolAddress((void**)&p_gsupT, g_gsupT);
    cudaGetSymbolAddress((void**)&p_g, g_g);
    cudaGetSymbolAddress((void**)&p_g2, g_g2);

    const int C2_SMEM = (C2_XH + 2 * C2_WH) * 2;   // 67392 B
    cudaFuncSetAttribute((const void*)conv2mma_kernel,
                         cudaFuncAttributeMaxDynamicSharedMemorySize, C2_SMEM);

    // order: mma_gemm<128> at launch index 3 (profiled slot)
    {
        long TOT = (long)BB * NPAT * (KPAD / 8);
        adjconv_kernel<<<(int)((TOT + 255) / 256), 256>>>(adj);
    }
    patch_kernel<<<(BB * NPAT * 8 + 255) / 256, 256>>>(input);
    gemmA_kernel<<<dim3(KPAD / 32, BB), 128>>>(gw3);
    mma_gemm_kernel<128><<<dim3(32, 1, BB), 256>>>(p_adjb, p_supT, p_g, gb3, 1);

    wt_kernel<<<144, 256>>>(w2);
    conv1_kernel<<<dim3(16, 16, BB), 256>>>(input, w1, b1);
    conv2mma_kernel<<<dim3(8, 32, BB), 256, C2_SMEM>>>(b2);
    conv3_kernel<<<dim3(4, 16, BB), 256>>>(w3, b3);

    gemmB_kernel<<<dim3(KPAD / 32, BB), 128>>>(gw4);
    mma_gemm_kernel<64><<<dim3(32, 1, BB), 256>>>(p_adjb, p_gsupT, p_g2, gb4, 0);

    final_kernel<<<(BB * IMGD * IMGD + 255) / 256, 256>>>(input, proj, lam, out);
}

// round 7
// speedup vs baseline: 5.7415x; 1.2631x over previous
#include <cuda_runtime.h>
#include <cuda_bf16.h>
#include <cuda_fp16.h>
#include <cstdint>

// ---------------- problem constants ----------------
#define BB   4
#define IMGD 256
#define HID  64
#define PH   63
#define NPAT 3969   // 63*63
#define PPF  64     // 8*8 patch pixels
#define GHD  128
#define KPAD 4032   // 63*64, padded K for tensor GEMM
#define NCHUNK 126  // KPAD / 32

// ---------------- scratch (device globals; no runtime alloc) ----------------
__device__ __half g_h1i[(long)BB*IMGD*IMGD*HID];      // conv1 out, [b][y][x][ic] fp16
__device__ __half g_h2h[(long)BB*HID*IMGD*IMGD];      // conv2 out, [b][oc][y][x] fp16
__device__ float g_tmp2[BB*IMGD*IMGD];                // conv3 out
__device__ float g_patch[BB*NPAT*PPF];                // [b][n][64]
__device__ float g_g[(long)BB*NPAT*GHD];              // relu(adj@sup+b3)
__device__ float g_g2[(long)BB*NPAT*PPF];             // adj@gsup+b4
__device__ __nv_bfloat16 g_adjb[(long)BB*NPAT*KPAD];  // adj bf16 K-padded
__device__ __nv_bfloat16 g_supT[(long)BB*GHD*KPAD];   // (patch@W3)^T bf16
__device__ __nv_bfloat16 g_gsupT[(long)BB*PPF*KPAD];  // (g@W4)^T bf16
__device__ __half g_w2t[9*64*64];                     // w2 [tap][oc][ic] fp16

__device__ __forceinline__ uint32_t smem_to_u32(const void* p) {
    uint32_t a;
    asm("{ .reg .u64 t; cvta.to.shared.u64 t, %1; cvt.u32.u64 %0, t; }"
        : "=r"(a) : "l"(p));
    return a;
}
__device__ __forceinline__ void ldmatrix_x4(uint32_t* r, uint32_t addr) {
    asm volatile("ldmatrix.sync.aligned.m8n8.x4.shared.b16 {%0,%1,%2,%3}, [%4];"
                 : "=r"(r[0]), "=r"(r[1]), "=r"(r[2]), "=r"(r[3]) : "r"(addr));
}
__device__ __forceinline__ void ldmatrix_x2(uint32_t* r, uint32_t addr) {
    asm volatile("ldmatrix.sync.aligned.m8n8.x2.shared.b16 {%0,%1}, [%2];"
                 : "=r"(r[0]), "=r"(r[1]) : "r"(addr));
}
__device__ __forceinline__ void mma16816_bf16(float* d, const uint32_t* a, const uint32_t* b) {
    asm volatile(
        "mma.sync.aligned.m16n8k16.row.col.f32.bf16.bf16.f32 "
        "{%0,%1,%2,%3}, {%4,%5,%6,%7}, {%8,%9}, {%0,%1,%2,%3};"
        : "+f"(d[0]), "+f"(d[1]), "+f"(d[2]), "+f"(d[3])
        : "r"(a[0]), "r"(a[1]), "r"(a[2]), "r"(a[3]), "r"(b[0]), "r"(b[1]));
}
__device__ __forceinline__ void mma16816_f16(float* d, const uint32_t* a, const uint32_t* b) {
    asm volatile(
        "mma.sync.aligned.m16n8k16.row.col.f32.f16.f16.f32 "
        "{%0,%1,%2,%3}, {%4,%5,%6,%7}, {%8,%9}, {%0,%1,%2,%3};"
        : "+f"(d[0]), "+f"(d[1]), "+f"(d[2]), "+f"(d[3])
        : "r"(a[0]), "r"(a[1]), "r"(a[2]), "r"(a[3]), "r"(b[0]), "r"(b[1]));
}
__device__ __forceinline__ void cp_async16(uint32_t dst, const void* src, uint32_t bytes) {
    asm volatile("cp.async.cg.shared.global [%0], [%1], 16, %2;"
                 :: "r"(dst), "l"(src), "r"(bytes));
}
#define CP_COMMIT() asm volatile("cp.async.commit_group;" ::: "memory")
#define CP_WAIT(n)  asm volatile("cp.async.wait_group %0;" :: "n"(n) : "memory")

// ==================== weight transform: w2 OIHW -> [tap][oc][ic] fp16 =========
__global__ void wt_kernel(const float* __restrict__ w2) {
    int idx = blockIdx.x * 256 + threadIdx.x;
    if (idx >= 64 * 64 * 9) return;
    int oc = idx / 576, r = idx - oc * 576;
    int ic = r / 9, t = r - ic * 9;
    g_w2t[t * 4096 + oc * 64 + ic] = __float2half(w2[idx]);
}

// ==================== conv1: 1 -> 64, relu, interleaved fp16 out =============
__global__ void __launch_bounds__(256) conv1_kernel(const float* __restrict__ in,
                             const float* __restrict__ w,
                             const float* __restrict__ bias) {
    __shared__ float sIn[18][18];
    __shared__ float sW[576];
    __shared__ float sB[64];
    __shared__ __half sOut[16 * 16 * 64];
    int b = blockIdx.z;
    int x0 = blockIdx.x * 16, y0 = blockIdx.y * 16;
    int tid = threadIdx.x;
    for (int i = tid; i < 576; i += 256) sW[i] = w[i];
    if (tid < 64) sB[tid] = bias[tid];
    for (int i = tid; i < 324; i += 256) {
        int yy = i / 18, xx = i - yy * 18;
        int gy = y0 + yy - 1, gx = x0 + xx - 1;
        float v = 0.f;
        if (gy >= 0 && gy < IMGD && gx >= 0 && gx < IMGD)
            v = in[(long)b * IMGD * IMGD + gy * IMGD + gx];
        sIn[yy][xx] = v;
    }
    __syncthreads();
    int tx = tid & 15, ty = tid >> 4;
    float r[9];
#pragma unroll
    for (int dy = 0; dy < 3; dy++)
#pragma unroll
        for (int dx = 0; dx < 3; dx++)
            r[dy * 3 + dx] = sIn[ty + dy][tx + dx];
#pragma unroll 1
    for (int oc0 = 0; oc0 < 64; oc0 += 8) {
        __half hv[8];
#pragma unroll
        for (int o = 0; o < 8; o++) {
            float acc = sB[oc0 + o];
#pragma unroll
            for (int t = 0; t < 9; t++) acc += r[t] * sW[(oc0 + o) * 9 + t];
            hv[o] = __float2half(fmaxf(acc, 0.f));
        }
        *(uint4*)&sOut[tid * 64 + oc0] = *(uint4*)hv;
    }
    __syncthreads();
    for (int i = tid; i < 2048; i += 256) {
        int row = i >> 7;
        int c = i & 127;
        long e = (((long)b * IMGD * IMGD + (y0 + row) * IMGD + x0) << 6) + c * 8;
        *(uint4*)&g_h1i[e] = *(uint4*)&sOut[row * 1024 + c * 8];
    }
}

// ==================== conv2: fp16 HMMA, 9-tap shifted GEMM ====================
#define C2_XH (340 * 72)
#define C2_WH (64 * 72)
__global__ void __launch_bounds__(256) conv2mma_kernel(const float* __restrict__ bias) {
    extern __shared__ __half dsm[];
    __half* X_s = dsm;
    __half* W_s[2] = {dsm + C2_XH, dsm + C2_XH + C2_WH};
    int tid = threadIdx.x, lane = tid & 31, wid = tid >> 5;
    int b = blockIdx.z, y0 = blockIdx.y * 8, x0 = blockIdx.x * 32;
    int wm = (wid & 3) * 64;
    int wn = (wid >> 2) * 32;

    for (int i = tid; i < 2720; i += 256) {
        int pos = i >> 3, q = i & 7;
        int row = pos / 34, col = pos - row * 34;
        int gy = y0 + row - 1, gx = x0 + col - 1;
        uint4 v = make_uint4(0u, 0u, 0u, 0u);
        if (gy >= 0 && gy < IMGD && gx >= 0 && gx < IMGD)
            v = *(const uint4*)&g_h1i[(((long)b * IMGD * IMGD + gy * IMGD + gx) << 6) + q * 8];
        *(uint4*)&X_s[pos * 72 + q * 8] = v;
    }
    for (int i = tid; i < 512; i += 256) {
        int oc = i >> 3, q = i & 7;
        *(uint4*)&W_s[0][oc * 72 + q * 8] = *(const uint4*)&g_w2t[oc * 64 + q * 8];
    }
    __syncthreads();

    float acc[4][4][4];
#pragma unroll
    for (int i = 0; i < 4; i++)
#pragma unroll
        for (int j = 0; j < 4; j++)
#pragma unroll
            for (int q = 0; q < 4; q++) acc[i][j][q] = 0.f;

    uint32_t xb = smem_to_u32(X_s);
    uint32_t wb[2] = {smem_to_u32(W_s[0]), smem_to_u32(W_s[1])};

    uint32_t abase[4];
#pragma unroll
    for (int am = 0; am < 4; am++) {
        int p0 = wm + am * 16;
        abase[am] = xb + (uint32_t)((((p0 >> 5) * 34) + (p0 & 31) + (lane & 15)) * 144)
                       + (uint32_t)((lane >> 4) * 16);
    }
    uint32_t bbase[4];
#pragma unroll
    for (int an = 0; an < 4; an++)
        bbase[an] = (uint32_t)((wn + an * 8 + (lane & 7)) * 144)
                  + (uint32_t)(((lane >> 3) & 1) * 16);

    for (int tap = 0; tap < 9; tap++) {
        int cur = tap & 1;
        if (tap < 8) {
            const __half* src = g_w2t + (tap + 1) * 4096;
            for (int i = tid; i < 512; i += 256) {
                int oc = i >> 3, q = i & 7;
                *(uint4*)&W_s[cur ^ 1][oc * 72 + q * 8] = *(const uint4*)&src[oc * 64 + q * 8];
            }
        }
        int dy = tap / 3, dx = tap - dy * 3;
        uint32_t toff = (uint32_t)((dy * 34 + dx) * 144);
#pragma unroll
        for (int kb = 0; kb < 64; kb += 16) {
            uint32_t af[4][4], bf[4][2];
#pragma unroll
            for (int am = 0; am < 4; am++)
                ldmatrix_x4(af[am], abase[am] + toff + kb * 2);
#pragma unroll
            for (int an = 0; an < 4; an++)
                ldmatrix_x2(bf[an], wb[cur] + bbase[an] + kb * 2);
#pragma unroll
            for (int am = 0; am < 4; am++)
#pragma unroll
                for (int an = 0; an < 4; an++)
                    mma16816_f16(acc[am][an], af[am], bf[an]);
        }
        __syncthreads();
    }

    int r0 = lane >> 2, c0l = (lane & 3) * 2;
#pragma unroll
    for (int am = 0; am < 4; am++) {
#pragma unroll
        for (int an = 0; an < 4; an++) {
            int oc = wn + an * 8 + c0l;
            float b0 = bias[oc], b1 = bias[oc + 1];
#pragma unroll
            for (int h = 0; h < 2; h++) {
                int p = wm + am * 16 + r0 + h * 8;
                int rr = p >> 5, cc = p & 31;
                long o = (((long)b * HID + oc) << 16) + ((y0 + rr) << 8) + (x0 + cc);
                g_h2h[o] = __float2half(fmaxf(acc[am][an][h * 2 + 0] + b0, 0.f));
                g_h2h[o + (1L << 16)] = __float2half(fmaxf(acc[am][an][h * 2 + 1] + b1, 0.f));
            }
        }
    }
}

// ==================== conv3: 64 -> 1, 3x3 SAME (vectorized fp16 fill) =========
__global__ void __launch_bounds__(256) conv3_kernel(const float* __restrict__ w,
                             const float* __restrict__ bias) {
    __shared__ float sIn[4 * 18 * 66];
    __shared__ float sW[576];
    int b = blockIdx.z;
    int x0 = blockIdx.x * 64, y0 = blockIdx.y * 16;
    int tid = threadIdx.x;
    for (int i = tid; i < 576; i += 256) sW[i] = w[i];
    int tx = tid & 15, ty = tid >> 4;
    float acc[4] = {0.f, 0.f, 0.f, 0.f};
    for (int cc = 0; cc < 16; cc++) {
        __syncthreads();
        // body: aligned uint4 loads of 8 halves (cols x0+8q .. x0+8q+7)
        for (int i = tid; i < 576; i += 256) {
            int ic = i / 144;
            int rem = i - ic * 144;
            int yy = rem >> 3, q = rem & 7;
            int gy = y0 + yy - 1;
            uint4 v = make_uint4(0u, 0u, 0u, 0u);
            if (gy >= 0 && gy < IMGD)
                v = *(const uint4*)&g_h2h[(((long)b * HID + cc * 4 + ic) << 16)
                                          + (gy << 8) + x0 + q * 8];
            const __half* h = (const __half*)&v;
            float* d = &sIn[ic * 1188 + yy * 66 + 1 + q * 8];
#pragma unroll
            for (int j = 0; j < 8; j++) d[j] = __half2float(h[j]);
        }
        // edges: col x0-1 (idx 0) and x0+64 (idx 65)
        for (int i = tid; i < 144; i += 256) {
            int ic = i / 36;
            int rem = i - ic * 36;
            int yy = rem >> 1, side = rem & 1;
            int gy = y0 + yy - 1;
            int gx = side ? x0 + 64 : x0 - 1;
            float v = 0.f;
            if (gy >= 0 && gy < IMGD && gx >= 0 && gx < IMGD)
                v = __half2float(g_h2h[(((long)b * HID + cc * 4 + ic) << 16) + (gy << 8) + gx]);
            sIn[ic * 1188 + yy * 66 + (side ? 65 : 0)] = v;
        }
        __syncthreads();
#pragma unroll
        for (int ic = 0; ic < 4; ic++) {
            float rin[3][6];
#pragma unroll
            for (int dy = 0; dy < 3; dy++)
#pragma unroll
                for (int dx = 0; dx < 6; dx++)
                    rin[dy][dx] = sIn[ic * 1188 + (ty + dy) * 66 + (tx * 4 + dx)];
            float wv[9];
#pragma unroll
            for (int t = 0; t < 9; t++) wv[t] = sW[(cc * 4 + ic) * 9 + t];
#pragma unroll
            for (int dy = 0; dy < 3; dy++)
#pragma unroll
                for (int dx = 0; dx < 3; dx++)
#pragma unroll
                    for (int p = 0; p < 4; p++)
                        acc[p] += rin[dy][p + dx] * wv[dy * 3 + dx];
        }
    }
    float bv = bias[0];
    float4 o;
    o.x = acc[0] + bv; o.y = acc[1] + bv; o.z = acc[2] + bv; o.w = acc[3] + bv;
    *(float4*)&g_tmp2[(long)b * IMGD * IMGD + (y0 + ty) * IMGD + x0 + tx * 4] = o;
}

// ==================== GCN branch ====================

__global__ void patch_kernel(const float* __restrict__ in) {
    int idx = blockIdx.x * 256 + threadIdx.x;
    if (idx >= BB * NPAT * 8) return;
    int i = idx & 7;
    int t = idx >> 3;
    int n = t % NPAT;
    int b = t / NPAT;
    int py = n / PH, px = n - py * PH;
    const float* src = in + (long)b * IMGD * IMGD + (py * 4 + i) * IMGD + px * 4;
    float* dst = g_patch + ((long)b * NPAT + n) * PPF + i * 8;
    *(float4*)dst = *(const float4*)src;
    *(float4*)(dst + 4) = *(const float4*)(src + 4);
}

__global__ void __launch_bounds__(256) adjconv_kernel(const float* __restrict__ adj) {
    long idx = (long)blockIdx.x * 256 + threadIdx.x;
    const long TOT = (long)BB * NPAT * (KPAD / 8);
    if (idx >= TOT) return;
    int kq = (int)(idx % (KPAD / 8));
    long row = idx / (KPAD / 8);
    int k0 = kq * 8;
    const float* src = adj + row * NPAT + k0;
    __nv_bfloat16 o[8];
#pragma unroll
    for (int j = 0; j < 8; j++) {
        float v = (k0 + j < NPAT) ? src[j] : 0.f;
        o[j] = __float2bfloat16(v);
    }
    *(uint4*)&g_adjb[row * KPAD + k0] = *(uint4*)o;
}

__global__ void __launch_bounds__(128) gemmA_kernel(const float* __restrict__ w3) {
    __shared__ float sP[32][65];
    __shared__ float sW[64][128];
    int b = blockIdx.y;
    int n0 = blockIdx.x * 32;
    int tid = threadIdx.x;
    for (int l = 0; l < 64; l++) {
        int idx = tid + l * 128;
        sW[idx >> 7][idx & 127] = w3[idx];
    }
    for (int l = 0; l < 16; l++) {
        int idx = tid + l * 128;
        int n = idx >> 6, k = idx & 63;
        float v = 0.f;
        if (n0 + n < NPAT) v = g_patch[((long)b * NPAT + n0 + n) * PPF + k];
        sP[n][k] = v;
    }
    __syncthreads();
    int g = tid;
    float acc[32];
#pragma unroll
    for (int n = 0; n < 32; n++) acc[n] = 0.f;
    for (int k = 0; k < 64; k++) {
        float wv = sW[k][g];
#pragma unroll
        for (int n = 0; n < 32; n++) acc[n] += sP[n][k] * wv;
    }
    __nv_bfloat16* dst = g_supT + ((long)b * GHD + g) * KPAD + n0;
#pragma unroll
    for (int n = 0; n < 32; n++)
        dst[n] = (n0 + n < NPAT) ? __float2bfloat16(acc[n]) : __float2bfloat16(0.f);
}

__global__ void __launch_bounds__(128) gemmB_kernel(const float* __restrict__ w4) {
    __shared__ float sG[32][129];
    __shared__ float sW[64][64];
    int b = blockIdx.y;
    int n0 = blockIdx.x * 32;
    int tid = threadIdx.x;
    int p = tid & 63, half = tid >> 6;
    float acc[16];
#pragma unroll
    for (int i = 0; i < 16; i++) acc[i] = 0.f;
    for (int kc = 0; kc < 2; kc++) {
        __syncthreads();
        for (int l = 0; l < 32; l++) {
            int idx = tid + l * 128;
            int kk = idx >> 6, pp = idx & 63;
            sW[kk][pp] = w4[(kc * 64 + kk) * 64 + pp];
        }
        for (int l = 0; l < 16; l++) {
            int idx = tid + l * 128;
            int n = idx >> 6, kk = idx & 63;
            float v = 0.f;
            if (n0 + n < NPAT) v = g_g[((long)b * NPAT + n0 + n) * GHD + kc * 64 + kk];
            sG[n][kk] = v;
        }
        __syncthreads();
        for (int kk = 0; kk < 64; kk++) {
            float wv = sW[kk][p];
#pragma unroll
            for (int i = 0; i < 16; i++) acc[i] += sG[half * 16 + i][kk] * wv;
        }
    }
    __nv_bfloat16* dst = g_gsupT + ((long)b * PPF + p) * KPAD + n0 + half * 16;
#pragma unroll
    for (int i = 0; i < 16; i++)
        dst[i] = (n0 + half * 16 + i < NPAT) ? __float2bfloat16(acc[i]) : __float2bfloat16(0.f);
}

// ---------------- big HMMA GEMM, cp.async 4-stage pipeline -------------------
#define LDT 40
#define STAGES 4

template<int NN>
__global__ void __launch_bounds__(256) mma_gemm_kernel(
        const __nv_bfloat16* __restrict__ A,
        const __nv_bfloat16* __restrict__ B,
        float* __restrict__ C,
        const float* __restrict__ bias, int relu) {
    constexpr int WN = NN / 4;
    constexpr int NA = WN / 8;
    constexpr int ASTG = 128 * LDT;      // halves per A stage
    constexpr int BSTG = NN * LDT;
    constexpr int NBU = NN * 4 / 256;    // B 16B-units per thread (2 or 1)
    extern __shared__ __nv_bfloat16 gsm[];
    __nv_bfloat16* A_s = gsm;                       // [STAGES][ASTG]
    __nv_bfloat16* B_s = gsm + STAGES * ASTG;       // [STAGES][BSTG]

    int tid = threadIdx.x;
    int lane = tid & 31;
    int wid = tid >> 5;
    int wm = (wid & 1) * 64;
    int wn = (wid >> 1) * WN;
    int bz = blockIdx.z;
    int m0 = blockIdx.x * 128;

    const __nv_bfloat16* Ab = A + (long)bz * NPAT * KPAD;
    const __nv_bfloat16* Bb = B + (long)bz * NN * KPAD;
    float* Cb = C + (long)bz * NPAT * NN;

    float acc[4][NA][4];
#pragma unroll
    for (int i = 0; i < 4; i++)
#pragma unroll
        for (int j = 0; j < NA; j++)
#pragma unroll
            for (int q = 0; q < 4; q++) acc[i][j][q] = 0.f;

    // loader geometry: unit = 8 halves (16 B); A: 512 units (2/thread)
    int a_row[2], a_part[2];
    uint32_t a_dst[2];
    const __nv_bfloat16* a_srcb[2];
    uint32_t a_bytes[2];
#pragma unroll
    for (int l = 0; l < 2; l++) {
        int u = tid + l * 256;
        a_row[l] = u >> 2; a_part[l] = u & 3;
        int gm = m0 + a_row[l];
        a_bytes[l] = (gm < NPAT) ? 16u : 0u;
        int gmc = gm < NPAT ? gm : NPAT - 1;
        a_srcb[l] = Ab + (long)gmc * KPAD + a_part[l] * 8;
        a_dst[l] = smem_to_u32(&A_s[a_row[l] * LDT + a_part[l] * 8]);
    }
    uint32_t b_dst[NBU];
    const __nv_bfloat16* b_srcb[NBU];
#pragma unroll
    for (int l = 0; l < NBU; l++) {
        int u = tid + l * 256;
        int row = u >> 2, part = u & 3;
        b_srcb[l] = Bb + (long)row * KPAD + part * 8;
        b_dst[l] = smem_to_u32(&B_s[row * LDT + part * 8]);
    }

    auto issue = [&](int c) {
        int s = c % STAGES;
        long kb = (long)c * 32;
#pragma unroll
        for (int l = 0; l < 2; l++)
            cp_async16(a_dst[l] + s * (ASTG * 2), a_srcb[l] + kb, a_bytes[l]);
#pragma unroll
        for (int l = 0; l < NBU; l++)
            cp_async16(b_dst[l] + s * (BSTG * 2), b_srcb[l] + kb, 16u);
        CP_COMMIT();
    };

    // prologue: stages 0..STAGES-2
#pragma unroll
    for (int s = 0; s < STAGES - 1; s++) issue(s);

    uint32_t a_base0 = smem_to_u32(A_s);
    uint32_t b_base0 = smem_to_u32(B_s);

    for (int c = 0; c < NCHUNK; c++) {
        CP_WAIT(STAGES - 2);
        __syncthreads();
        int s = c % STAGES;
        uint32_t a_base = a_base0 + s * (ASTG * 2);
        uint32_t b_base = b_base0 + s * (BSTG * 2);
#pragma unroll
        for (int ks = 0; ks < 2; ks++) {
            uint32_t af[4][4];
#pragma unroll
            for (int am = 0; am < 4; am++) {
                uint32_t addr = a_base +
                    (uint32_t)((wm + am * 16 + (lane & 15)) * (LDT * 2)) +
                    (uint32_t)(ks * 32 + (lane >> 4) * 16);
                ldmatrix_x4(af[am], addr);
            }
            uint32_t bf[NA][2];
#pragma unroll
            for (int an = 0; an < NA; an++) {
                uint32_t addr = b_base +
                    (uint32_t)((wn + an * 8 + (lane & 7)) * (LDT * 2)) +
                    (uint32_t)(ks * 32 + ((lane >> 3) & 1) * 16);
                ldmatrix_x2(bf[an], addr);
            }
#pragma unroll
            for (int am = 0; am < 4; am++)
#pragma unroll
                for (int an = 0; an < NA; an++)
                    mma16816_bf16(acc[am][an], af[am], bf[an]);
        }
        if (c + STAGES - 1 < NCHUNK) issue(c + STAGES - 1);
        else CP_COMMIT();   // keep group count in step for the wait
    }

    int r0 = lane >> 2, c0 = (lane & 3) * 2;
#pragma unroll
    for (int am = 0; am < 4; am++) {
#pragma unroll
        for (int an = 0; an < NA; an++) {
            int gn = wn + an * 8 + c0;
            float b0 = bias[gn], b1 = bias[gn + 1];
            int gr0 = m0 + wm + am * 16 + r0;
            float v0 = acc[am][an][0] + b0;
            float v1 = acc[am][an][1] + b1;
            float v2 = acc[am][an][2] + b0;
            float v3 = acc[am][an][3] + b1;
            if (relu) {
                v0 = fmaxf(v0, 0.f); v1 = fmaxf(v1, 0.f);
                v2 = fmaxf(v2, 0.f); v3 = fmaxf(v3, 0.f);
            }
            if (gr0 < NPAT) {
                Cb[(long)gr0 * NN + gn] = v0;
                Cb[(long)gr0 * NN + gn + 1] = v1;
            }
            if (gr0 + 8 < NPAT) {
                Cb[(long)(gr0 + 8) * NN + gn] = v2;
                Cb[(long)(gr0 + 8) * NN + gn + 1] = v3;
            }
        }
    }
}

// ---------------- final: tmp1 + tmp2 + patch2img(g2)/mask, relu --------------
__global__ void final_kernel(const float* __restrict__ in,
                             const float* __restrict__ proj,
                             const float* __restrict__ lam,
                             float* __restrict__ out) {
    int idx = blockIdx.x * 256 + threadIdx.x;
    if (idx >= BB * IMGD * IMGD) return;
    int x = idx & 255, y = (idx >> 8) & 255, b = idx >> 16;
    float lv = lam[0];
    float iv = in[idx], pv = proj[idx];
    float t1 = iv + lv * (pv - iv);
    float t2 = g_tmp2[idx];
    int tyv = y - 7;
    int py_lo = tyv > 0 ? (tyv + 3) >> 2 : 0;
    int py_hi = min(62, y >> 2);
    int txv = x - 7;
    int px_lo = txv > 0 ? (txv + 3) >> 2 : 0;
    int px_hi = min(62, x >> 2);
    float s = 0.f;
    int cnt = (py_hi - py_lo + 1) * (px_hi - px_lo + 1);
    for (int py = py_lo; py <= py_hi; py++) {
        int i = y - 4 * py;
        for (int px = px_lo; px <= px_hi; px++) {
            int j = x - 4 * px;
            s += g_g2[((long)b * NPAT + (py * PH + px)) * PPF + i * 8 + j];
        }
    }
    float v = t1 + t2 + s / (float)cnt;
    out[idx] = fmaxf(v, 0.f);
}

// ---------------- launch ----------------
extern "C" void kernel_launch(void* const* d_in, const int* in_sizes, int n_in,
                              void* d_out, int out_size) {
    const float* input = (const float*)d_in[0];
    const float* proj  = (const float*)d_in[1];
    const float* adj   = (const float*)d_in[2];
    const float* lam   = (const float*)d_in[3];
    const float* w1 = (const float*)d_in[4];
    const float* b1 = (const float*)d_in[5];
    const float* w2 = (const float*)d_in[6];
    const float* b2 = (const float*)d_in[7];
    const float* w3 = (const float*)d_in[8];
    const float* b3 = (const float*)d_in[9];
    const float* gw3 = (const float*)d_in[10];
    const float* gb3 = (const float*)d_in[11];
    const float* gw4 = (const float*)d_in[12];
    const float* gb4 = (const float*)d_in[13];
    float* out = (float*)d_out;

    __nv_bfloat16 *p_adjb, *p_supT, *p_gsupT;
    float *p_g, *p_g2;
    cudaGetSymbolAddress((void**)&p_adjb, g_adjb);
    cudaGetSymbolAddress((void**)&p_supT, g_supT);
    cudaGetSymbolAddress((void**)&p_gsupT, g_gsupT);
    cudaGetSymbolAddress((void**)&p_g, g_g);
    cudaGetSymbolAddress((void**)&p_g2, g_g2);

    const int C2_SMEM = (C2_XH + 2 * C2_WH) * 2;
    cudaFuncSetAttribute((const void*)conv2mma_kernel,
                         cudaFuncAttributeMaxDynamicSharedMemorySize, C2_SMEM);
    const int G1_SMEM = STAGES * (128 * LDT + 128 * LDT) * 2;  // 81920
    const int G2_SMEM = STAGES * (128 * LDT + 64 * LDT) * 2;   // 61440
    cudaFuncSetAttribute((const void*)mma_gemm_kernel<128>,
                         cudaFuncAttributeMaxDynamicSharedMemorySize, G1_SMEM);
    cudaFuncSetAttribute((const void*)mma_gemm_kernel<64>,
                         cudaFuncAttributeMaxDynamicSharedMemorySize, G2_SMEM);

    {
        long TOT = (long)BB * NPAT * (KPAD / 8);
        adjconv_kernel<<<(int)((TOT + 255) / 256), 256>>>(adj);
    }
    patch_kernel<<<(BB * NPAT * 8 + 255) / 256, 256>>>(input);
    gemmA_kernel<<<dim3(KPAD / 32, BB), 128>>>(gw3);
    mma_gemm_kernel<128><<<dim3(32, 1, BB), 256, G1_SMEM>>>(p_adjb, p_supT, p_g, gb3, 1);

    wt_kernel<<<144, 256>>>(w2);
    conv1_kernel<<<dim3(16, 16, BB), 256>>>(input, w1, b1);
    conv2mma_kernel<<<dim3(8, 32, BB), 256, C2_SMEM>>>(b2);
    conv3_kernel<<<dim3(4, 16, BB), 256>>>(w3, b3);

    gemmB_kernel<<<dim3(KPAD / 32, BB), 128>>>(gw4);
    mma_gemm_kernel<64><<<dim3(32, 1, BB), 256, G2_SMEM>>>(p_adjb, p_gsupT, p_g2, gb4, 0);

    final_kernel<<<(BB * IMGD * IMGD + 255) / 256, 256>>>(input, proj, lam, out);
}

// round 8
// speedup vs baseline: 5.8016x; 1.0105x over previous
#include <cuda_runtime.h>
#include <cuda_bf16.h>
#include <cuda_fp16.h>
#include <cstdint>

// ---------------- problem constants ----------------
#define BB   4
#define IMGD 256
#define HID  64
#define PH   63
#define NPAT 3969   // 63*63
#define PPF  64     // 8*8 patch pixels
#define GHD  128
#define KPAD 4032   // 63*64, padded K for tensor GEMM
#define NCHUNK 126  // KPAD / 32

// ---------------- scratch (device globals; no runtime alloc) ----------------
__device__ __half g_h1i[(long)BB*IMGD*IMGD*HID];      // conv1 out, [b][y][x][ic] fp16
__device__ __half g_h2h[(long)BB*HID*IMGD*IMGD];      // conv2 out, [b][oc][y][x] fp16
__device__ float g_tmp2[BB*IMGD*IMGD];                // conv3 out
__device__ float g_patch[BB*NPAT*PPF];                // [b][n][64]
__device__ float g_g[(long)BB*NPAT*GHD];              // relu(adj@sup+b3)
__device__ float g_g2[(long)BB*NPAT*PPF];             // adj@gsup+b4
__device__ __nv_bfloat16 g_adjb[(long)BB*NPAT*KPAD];  // adj bf16 K-padded
__device__ __nv_bfloat16 g_supT[(long)BB*GHD*KPAD];   // (patch@W3)^T bf16
__device__ __nv_bfloat16 g_gsupT[(long)BB*PPF*KPAD];  // (g@W4)^T bf16
__device__ __half g_w2t[9*64*64];                     // w2 [tap][oc][ic] fp16

__device__ __forceinline__ uint32_t smem_to_u32(const void* p) {
    uint32_t a;
    asm("{ .reg .u64 t; cvta.to.shared.u64 t, %1; cvt.u32.u64 %0, t; }"
        : "=r"(a) : "l"(p));
    return a;
}
__device__ __forceinline__ void ldmatrix_x4(uint32_t* r, uint32_t addr) {
    asm volatile("ldmatrix.sync.aligned.m8n8.x4.shared.b16 {%0,%1,%2,%3}, [%4];"
                 : "=r"(r[0]), "=r"(r[1]), "=r"(r[2]), "=r"(r[3]) : "r"(addr));
}
__device__ __forceinline__ void ldmatrix_x2(uint32_t* r, uint32_t addr) {
    asm volatile("ldmatrix.sync.aligned.m8n8.x2.shared.b16 {%0,%1}, [%2];"
                 : "=r"(r[0]), "=r"(r[1]) : "r"(addr));
}
__device__ __forceinline__ void mma16816_bf16(float* d, const uint32_t* a, const uint32_t* b) {
    asm volatile(
        "mma.sync.aligned.m16n8k16.row.col.f32.bf16.bf16.f32 "
        "{%0,%1,%2,%3}, {%4,%5,%6,%7}, {%8,%9}, {%0,%1,%2,%3};"
        : "+f"(d[0]), "+f"(d[1]), "+f"(d[2]), "+f"(d[3])
        : "r"(a[0]), "r"(a[1]), "r"(a[2]), "r"(a[3]), "r"(b[0]), "r"(b[1]));
}
__device__ __forceinline__ void mma16816_f16(float* d, const uint32_t* a, const uint32_t* b) {
    asm volatile(
        "mma.sync.aligned.m16n8k16.row.col.f32.f16.f16.f32 "
        "{%0,%1,%2,%3}, {%4,%5,%6,%7}, {%8,%9}, {%0,%1,%2,%3};"
        : "+f"(d[0]), "+f"(d[1]), "+f"(d[2]), "+f"(d[3])
        : "r"(a[0]), "r"(a[1]), "r"(a[2]), "r"(a[3]), "r"(b[0]), "r"(b[1]));
}
__device__ __forceinline__ void cp_async16(uint32_t dst, const void* src, uint32_t bytes) {
    asm volatile("cp.async.cg.shared.global [%0], [%1], 16, %2;"
                 :: "r"(dst), "l"(src), "r"(bytes));
}
#define CP_COMMIT() asm volatile("cp.async.commit_group;" ::: "memory")
#define CP_WAIT(n)  asm volatile("cp.async.wait_group %0;" :: "n"(n) : "memory")

// ==================== weight transform: w2 OIHW -> [tap][oc][ic] fp16 =========
__global__ void wt_kernel(const float* __restrict__ w2) {
    int idx = blockIdx.x * 256 + threadIdx.x;
    if (idx >= 64 * 64 * 9) return;
    int oc = idx / 576, r = idx - oc * 576;
    int ic = r / 9, t = r - ic * 9;
    g_w2t[t * 4096 + oc * 64 + ic] = __float2half(w2[idx]);
}

// ==================== conv1: 1 -> 64, relu, interleaved fp16 out =============
__global__ void __launch_bounds__(256) conv1_kernel(const float* __restrict__ in,
                             const float* __restrict__ w,
                             const float* __restrict__ bias) {
    __shared__ float sIn[18][18];
    __shared__ float sW[576];
    __shared__ float sB[64];
    __shared__ __half sOut[16 * 16 * 64];
    int b = blockIdx.z;
    int x0 = blockIdx.x * 16, y0 = blockIdx.y * 16;
    int tid = threadIdx.x;
    for (int i = tid; i < 576; i += 256) sW[i] = w[i];
    if (tid < 64) sB[tid] = bias[tid];
    for (int i = tid; i < 324; i += 256) {
        int yy = i / 18, xx = i - yy * 18;
        int gy = y0 + yy - 1, gx = x0 + xx - 1;
        float v = 0.f;
        if (gy >= 0 && gy < IMGD && gx >= 0 && gx < IMGD)
            v = in[(long)b * IMGD * IMGD + gy * IMGD + gx];
        sIn[yy][xx] = v;
    }
    __syncthreads();
    int tx = tid & 15, ty = tid >> 4;
    float r[9];
#pragma unroll
    for (int dy = 0; dy < 3; dy++)
#pragma unroll
        for (int dx = 0; dx < 3; dx++)
            r[dy * 3 + dx] = sIn[ty + dy][tx + dx];
#pragma unroll 1
    for (int oc0 = 0; oc0 < 64; oc0 += 8) {
        __half hv[8];
#pragma unroll
        for (int o = 0; o < 8; o++) {
            float acc = sB[oc0 + o];
#pragma unroll
            for (int t = 0; t < 9; t++) acc += r[t] * sW[(oc0 + o) * 9 + t];
            hv[o] = __float2half(fmaxf(acc, 0.f));
        }
        *(uint4*)&sOut[tid * 64 + oc0] = *(uint4*)hv;
    }
    __syncthreads();
    for (int i = tid; i < 2048; i += 256) {
        int row = i >> 7;
        int c = i & 127;
        long e = (((long)b * IMGD * IMGD + (y0 + row) * IMGD + x0) << 6) + c * 8;
        *(uint4*)&g_h1i[e] = *(uint4*)&sOut[row * 1024 + c * 8];
    }
}

// ==================== conv2: fp16 HMMA, 9-tap shifted GEMM ====================
#define C2_XH (340 * 72)
#define C2_WH (64 * 72)
__global__ void __launch_bounds__(256) conv2mma_kernel(const float* __restrict__ bias) {
    extern __shared__ __half dsm[];
    __half* X_s = dsm;
    __half* W_s[2] = {dsm + C2_XH, dsm + C2_XH + C2_WH};
    int tid = threadIdx.x, lane = tid & 31, wid = tid >> 5;
    int b = blockIdx.z, y0 = blockIdx.y * 8, x0 = blockIdx.x * 32;
    int wm = (wid & 3) * 64;
    int wn = (wid >> 2) * 32;

    for (int i = tid; i < 2720; i += 256) {
        int pos = i >> 3, q = i & 7;
        int row = pos / 34, col = pos - row * 34;
        int gy = y0 + row - 1, gx = x0 + col - 1;
        uint4 v = make_uint4(0u, 0u, 0u, 0u);
        if (gy >= 0 && gy < IMGD && gx >= 0 && gx < IMGD)
            v = *(const uint4*)&g_h1i[(((long)b * IMGD * IMGD + gy * IMGD + gx) << 6) + q * 8];
        *(uint4*)&X_s[pos * 72 + q * 8] = v;
    }
    for (int i = tid; i < 512; i += 256) {
        int oc = i >> 3, q = i & 7;
        *(uint4*)&W_s[0][oc * 72 + q * 8] = *(const uint4*)&g_w2t[oc * 64 + q * 8];
    }
    __syncthreads();

    float acc[4][4][4];
#pragma unroll
    for (int i = 0; i < 4; i++)
#pragma unroll
        for (int j = 0; j < 4; j++)
#pragma unroll
            for (int q = 0; q < 4; q++) acc[i][j][q] = 0.f;

    uint32_t xb = smem_to_u32(X_s);
    uint32_t wb[2] = {smem_to_u32(W_s[0]), smem_to_u32(W_s[1])};

    uint32_t abase[4];
#pragma unroll
    for (int am = 0; am < 4; am++) {
        int p0 = wm + am * 16;
        abase[am] = xb + (uint32_t)((((p0 >> 5) * 34) + (p0 & 31) + (lane & 15)) * 144)
                       + (uint32_t)((lane >> 4) * 16);
    }
    uint32_t bbase[4];
#pragma unroll
    for (int an = 0; an < 4; an++)
        bbase[an] = (uint32_t)((wn + an * 8 + (lane & 7)) * 144)
                  + (uint32_t)(((lane >> 3) & 1) * 16);

    for (int tap = 0; tap < 9; tap++) {
        int cur = tap & 1;
        if (tap < 8) {
            const __half* src = g_w2t + (tap + 1) * 4096;
            for (int i = tid; i < 512; i += 256) {
                int oc = i >> 3, q = i & 7;
                *(uint4*)&W_s[cur ^ 1][oc * 72 + q * 8] = *(const uint4*)&src[oc * 64 + q * 8];
            }
        }
        int dy = tap / 3, dx = tap - dy * 3;
        uint32_t toff = (uint32_t)((dy * 34 + dx) * 144);
#pragma unroll
        for (int kb = 0; kb < 64; kb += 16) {
            uint32_t af[4][4], bf[4][2];
#pragma unroll
            for (int am = 0; am < 4; am++)
                ldmatrix_x4(af[am], abase[am] + toff + kb * 2);
#pragma unroll
            for (int an = 0; an < 4; an++)
                ldmatrix_x2(bf[an], wb[cur] + bbase[an] + kb * 2);
#pragma unroll
            for (int am = 0; am < 4; am++)
#pragma unroll
                for (int an = 0; an < 4; an++)
                    mma16816_f16(acc[am][an], af[am], bf[an]);
        }
        __syncthreads();
    }

    int r0 = lane >> 2, c0l = (lane & 3) * 2;
#pragma unroll
    for (int am = 0; am < 4; am++) {
#pragma unroll
        for (int an = 0; an < 4; an++) {
            int oc = wn + an * 8 + c0l;
            float b0 = bias[oc], b1 = bias[oc + 1];
#pragma unroll
            for (int h = 0; h < 2; h++) {
                int p = wm + am * 16 + r0 + h * 8;
                int rr = p >> 5, cc = p & 31;
                long o = (((long)b * HID + oc) << 16) + ((y0 + rr) << 8) + (x0 + cc);
                g_h2h[o] = __float2half(fmaxf(acc[am][an][h * 2 + 0] + b0, 0.f));
                g_h2h[o + (1L << 16)] = __float2half(fmaxf(acc[am][an][h * 2 + 1] + b1, 0.f));
            }
        }
    }
}

// ==================== conv3: 64 -> 1, 3x3 SAME (vectorized fp16 fill) =========
__global__ void __launch_bounds__(256) conv3_kernel(const float* __restrict__ w,
                             const float* __restrict__ bias) {
    __shared__ float sIn[4 * 18 * 66];
    __shared__ float sW[576];
    int b = blockIdx.z;
    int x0 = blockIdx.x * 64, y0 = blockIdx.y * 16;
    int tid = threadIdx.x;
    for (int i = tid; i < 576; i += 256) sW[i] = w[i];
    int tx = tid & 15, ty = tid >> 4;
    float acc[4] = {0.f, 0.f, 0.f, 0.f};
    for (int cc = 0; cc < 16; cc++) {
        __syncthreads();
        for (int i = tid; i < 576; i += 256) {
            int ic = i / 144;
            int rem = i - ic * 144;
            int yy = rem >> 3, q = rem & 7;
            int gy = y0 + yy - 1;
            uint4 v = make_uint4(0u, 0u, 0u, 0u);
            if (gy >= 0 && gy < IMGD)
                v = *(const uint4*)&g_h2h[(((long)b * HID + cc * 4 + ic) << 16)
                                          + (gy << 8) + x0 + q * 8];
            const __half* h = (const __half*)&v;
            float* d = &sIn[ic * 1188 + yy * 66 + 1 + q * 8];
#pragma unroll
            for (int j = 0; j < 8; j++) d[j] = __half2float(h[j]);
        }
        for (int i = tid; i < 144; i += 256) {
            int ic = i / 36;
            int rem = i - ic * 36;
            int yy = rem >> 1, side = rem & 1;
            int gy = y0 + yy - 1;
            int gx = side ? x0 + 64 : x0 - 1;
            float v = 0.f;
            if (gy >= 0 && gy < IMGD && gx >= 0 && gx < IMGD)
                v = __half2float(g_h2h[(((long)b * HID + cc * 4 + ic) << 16) + (gy << 8) + gx]);
            sIn[ic * 1188 + yy * 66 + (side ? 65 : 0)] = v;
        }
        __syncthreads();
#pragma unroll
        for (int ic = 0; ic < 4; ic++) {
            float rin[3][6];
#pragma unroll
            for (int dy = 0; dy < 3; dy++)
#pragma unroll
                for (int dx = 0; dx < 6; dx++)
                    rin[dy][dx] = sIn[ic * 1188 + (ty + dy) * 66 + (tx * 4 + dx)];
            float wv[9];
#pragma unroll
            for (int t = 0; t < 9; t++) wv[t] = sW[(cc * 4 + ic) * 9 + t];
#pragma unroll
            for (int dy = 0; dy < 3; dy++)
#pragma unroll
                for (int dx = 0; dx < 3; dx++)
#pragma unroll
                    for (int p = 0; p < 4; p++)
                        acc[p] += rin[dy][p + dx] * wv[dy * 3 + dx];
        }
    }
    float bv = bias[0];
    float4 o;
    o.x = acc[0] + bv; o.y = acc[1] + bv; o.z = acc[2] + bv; o.w = acc[3] + bv;
    *(float4*)&g_tmp2[(long)b * IMGD * IMGD + (y0 + ty) * IMGD + x0 + tx * 4] = o;
}

// ==================== GCN branch ====================

__global__ void patch_kernel(const float* __restrict__ in) {
    int idx = blockIdx.x * 256 + threadIdx.x;
    if (idx >= BB * NPAT * 8) return;
    int i = idx & 7;
    int t = idx >> 3;
    int n = t % NPAT;
    int b = t / NPAT;
    int py = n / PH, px = n - py * PH;
    const float* src = in + (long)b * IMGD * IMGD + (py * 4 + i) * IMGD + px * 4;
    float* dst = g_patch + ((long)b * NPAT + n) * PPF + i * 8;
    *(float4*)dst = *(const float4*)src;
    *(float4*)(dst + 4) = *(const float4*)(src + 4);
}

__global__ void __launch_bounds__(256) adjconv_kernel(const float* __restrict__ adj) {
    long idx = (long)blockIdx.x * 256 + threadIdx.x;
    const long TOT = (long)BB * NPAT * (KPAD / 8);
    if (idx >= TOT) return;
    int kq = (int)(idx % (KPAD / 8));
    long row = idx / (KPAD / 8);
    int k0 = kq * 8;
    const float* src = adj + row * NPAT + k0;
    __nv_bfloat16 o[8];
#pragma unroll
    for (int j = 0; j < 8; j++) {
        float v = (k0 + j < NPAT) ? src[j] : 0.f;
        o[j] = __float2bfloat16(v);
    }
    *(uint4*)&g_adjb[row * KPAD + k0] = *(uint4*)o;
}

__global__ void __launch_bounds__(128) gemmA_kernel(const float* __restrict__ w3) {
    __shared__ float sP[32][65];
    __shared__ float sW[64][128];
    int b = blockIdx.y;
    int n0 = blockIdx.x * 32;
    int tid = threadIdx.x;
    for (int l = 0; l < 64; l++) {
        int idx = tid + l * 128;
        sW[idx >> 7][idx & 127] = w3[idx];
    }
    for (int l = 0; l < 16; l++) {
        int idx = tid + l * 128;
        int n = idx >> 6, k = idx & 63;
        float v = 0.f;
        if (n0 + n < NPAT) v = g_patch[((long)b * NPAT + n0 + n) * PPF + k];
        sP[n][k] = v;
    }
    __syncthreads();
    int g = tid;
    float acc[32];
#pragma unroll
    for (int n = 0; n < 32; n++) acc[n] = 0.f;
    for (int k = 0; k < 64; k++) {
        float wv = sW[k][g];
#pragma unroll
        for (int n = 0; n < 32; n++) acc[n] += sP[n][k] * wv;
    }
    __nv_bfloat16* dst = g_supT + ((long)b * GHD + g) * KPAD + n0;
#pragma unroll
    for (int n = 0; n < 32; n++)
        dst[n] = (n0 + n < NPAT) ? __float2bfloat16(acc[n]) : __float2bfloat16(0.f);
}

__global__ void __launch_bounds__(128) gemmB_kernel(const float* __restrict__ w4) {
    __shared__ float sG[32][129];
    __shared__ float sW[64][64];
    int b = blockIdx.y;
    int n0 = blockIdx.x * 32;
    int tid = threadIdx.x;
    int p = tid & 63, half = tid >> 6;
    float acc[16];
#pragma unroll
    for (int i = 0; i < 16; i++) acc[i] = 0.f;
    for (int kc = 0; kc < 2; kc++) {
        __syncthreads();
        for (int l = 0; l < 32; l++) {
            int idx = tid + l * 128;
            int kk = idx >> 6, pp = idx & 63;
            sW[kk][pp] = w4[(kc * 64 + kk) * 64 + pp];
        }
        for (int l = 0; l < 16; l++) {
            int idx = tid + l * 128;
            int n = idx >> 6, kk = idx & 63;
            float v = 0.f;
            if (n0 + n < NPAT) v = g_g[((long)b * NPAT + n0 + n) * GHD + kc * 64 + kk];
            sG[n][kk] = v;
        }
        __syncthreads();
        for (int kk = 0; kk < 64; kk++) {
            float wv = sW[kk][p];
#pragma unroll
            for (int i = 0; i < 16; i++) acc[i] += sG[half * 16 + i][kk] * wv;
        }
    }
    __nv_bfloat16* dst = g_gsupT + ((long)b * PPF + p) * KPAD + n0 + half * 16;
#pragma unroll
    for (int i = 0; i < 16; i++)
        dst[i] = (n0 + half * 16 + i < NPAT) ? __float2bfloat16(acc[i]) : __float2bfloat16(0.f);
}

// ---------------- big HMMA GEMM, cp.async 4-stage, 512 threads ---------------
// 16 warps as 4M x 4N; warp tile 32 x (NN/4).
#define LDT 40
#define STAGES 4

template<int NN>
__global__ void __launch_bounds__(512) mma_gemm_kernel(
        const __nv_bfloat16* __restrict__ A,
        const __nv_bfloat16* __restrict__ B,
        float* __restrict__ C,
        const float* __restrict__ bias, int relu) {
    constexpr int WN = NN / 4;           // 32 or 16
    constexpr int NA = WN / 8;           // 4 or 2
    constexpr int ASTG = 128 * LDT;
    constexpr int BSTG = NN * LDT;
    extern __shared__ __nv_bfloat16 gsm[];
    __nv_bfloat16* A_s = gsm;
    __nv_bfloat16* B_s = gsm + STAGES * ASTG;

    int tid = threadIdx.x;
    int lane = tid & 31;
    int wid = tid >> 5;
    int wm = (wid & 3) * 32;
    int wn = (wid >> 2) * WN;
    int bz = blockIdx.z;
    int m0 = blockIdx.x * 128;

    const __nv_bfloat16* Ab = A + (long)bz * NPAT * KPAD;
    const __nv_bfloat16* Bb = B + (long)bz * NN * KPAD;
    float* Cb = C + (long)bz * NPAT * NN;

    float acc[2][NA][4];
#pragma unroll
    for (int i = 0; i < 2; i++)
#pragma unroll
        for (int j = 0; j < NA; j++)
#pragma unroll
            for (int q = 0; q < 4; q++) acc[i][j][q] = 0.f;

    // loader geometry: 16B units; A: 512 units -> 1/thread
    int a_row = tid >> 2, a_part = tid & 3;
    int gm = m0 + a_row;
    uint32_t a_bytes = (gm < NPAT) ? 16u : 0u;
    int gmc = gm < NPAT ? gm : NPAT - 1;
    const __nv_bfloat16* a_src = Ab + (long)gmc * KPAD + a_part * 8;
    uint32_t a_dst = smem_to_u32(&A_s[a_row * LDT + a_part * 8]);
    // B: NN*4 units (512 or 256)
    bool bact = tid < NN * 4;
    int b_row = tid >> 2, b_part = tid & 3;
    const __nv_bfloat16* b_src = Bb + (long)(bact ? b_row : 0) * KPAD + b_part * 8;
    uint32_t b_dst = smem_to_u32(&B_s[b_row * LDT + b_part * 8]);

    auto issue = [&](int c) {
        int s = c % STAGES;
        long kb = (long)c * 32;
        cp_async16(a_dst + s * (ASTG * 2), a_src + kb, a_bytes);
        if (bact) cp_async16(b_dst + s * (BSTG * 2), b_src + kb, 16u);
        CP_COMMIT();
    };

#pragma unroll
    for (int s = 0; s < STAGES - 1; s++) issue(s);

    uint32_t a_base0 = smem_to_u32(A_s);
    uint32_t b_base0 = smem_to_u32(B_s);

    for (int c = 0; c < NCHUNK; c++) {
        CP_WAIT(STAGES - 2);
        __syncthreads();
        int s = c % STAGES;
        uint32_t a_base = a_base0 + s * (ASTG * 2);
        uint32_t b_base = b_base0 + s * (BSTG * 2);
#pragma unroll
        for (int ks = 0; ks < 2; ks++) {
            uint32_t af[2][4];
#pragma unroll
            for (int am = 0; am < 2; am++) {
                uint32_t addr = a_base +
                    (uint32_t)((wm + am * 16 + (lane & 15)) * (LDT * 2)) +
                    (uint32_t)(ks * 32 + (lane >> 4) * 16);
                ldmatrix_x4(af[am], addr);
            }
            uint32_t bf[NA][2];
#pragma unroll
            for (int an = 0; an < NA; an++) {
                uint32_t addr = b_base +
                    (uint32_t)((wn + an * 8 + (lane & 7)) * (LDT * 2)) +
                    (uint32_t)(ks * 32 + ((lane >> 3) & 1) * 16);
                ldmatrix_x2(bf[an], addr);
            }
#pragma unroll
            for (int am = 0; am < 2; am++)
#pragma unroll
                for (int an = 0; an < NA; an++)
                    mma16816_bf16(acc[am][an], af[am], bf[an]);
        }
        if (c + STAGES - 1 < NCHUNK) issue(c + STAGES - 1);
        else CP_COMMIT();
    }

    int r0 = lane >> 2, c0 = (lane & 3) * 2;
#pragma unroll
    for (int am = 0; am < 2; am++) {
#pragma unroll
        for (int an = 0; an < NA; an++) {
            int gn = wn + an * 8 + c0;
            float b0 = bias[gn], b1 = bias[gn + 1];
            int gr0 = m0 + wm + am * 16 + r0;
            float v0 = acc[am][an][0] + b0;
            float v1 = acc[am][an][1] + b1;
            float v2 = acc[am][an][2] + b0;
            float v3 = acc[am][an][3] + b1;
            if (relu) {
                v0 = fmaxf(v0, 0.f); v1 = fmaxf(v1, 0.f);
                v2 = fmaxf(v2, 0.f); v3 = fmaxf(v3, 0.f);
            }
            if (gr0 < NPAT) {
                Cb[(long)gr0 * NN + gn] = v0;
                Cb[(long)gr0 * NN + gn + 1] = v1;
            }
            if (gr0 + 8 < NPAT) {
                Cb[(long)(gr0 + 8) * NN + gn] = v2;
                Cb[(long)(gr0 + 8) * NN + gn + 1] = v3;
            }
        }
    }
}

// ---------------- final: tmp1 + tmp2 + patch2img(g2)/mask, relu --------------
__global__ void final_kernel(const float* __restrict__ in,
                             const float* __restrict__ proj,
                             const float* __restrict__ lam,
                             float* __restrict__ out) {
    int idx = blockIdx.x * 256 + threadIdx.x;
    if (idx >= BB * IMGD * IMGD) return;
    int x = idx & 255, y = (idx >> 8) & 255, b = idx >> 16;
    float lv = lam[0];
    float iv = in[idx], pv = proj[idx];
    float t1 = iv + lv * (pv - iv);
    float t2 = g_tmp2[idx];
    int tyv = y - 7;
    int py_lo = tyv > 0 ? (tyv + 3) >> 2 : 0;
    int py_hi = min(62, y >> 2);
    int txv = x - 7;
    int px_lo = txv > 0 ? (txv + 3) >> 2 : 0;
    int px_hi = min(62, x >> 2);
    float s = 0.f;
    int cnt = (py_hi - py_lo + 1) * (px_hi - px_lo + 1);
    for (int py = py_lo; py <= py_hi; py++) {
        int i = y - 4 * py;
        for (int px = px_lo; px <= px_hi; px++) {
            int j = x - 4 * px;
            s += g_g2[((long)b * NPAT + (py * PH + px)) * PPF + i * 8 + j];
        }
    }
    float v = t1 + t2 + s / (float)cnt;
    out[idx] = fmaxf(v, 0.f);
}

// ---------------- launch ----------------
extern "C" void kernel_launch(void* const* d_in, const int* in_sizes, int n_in,
                              void* d_out, int out_size) {
    const float* input = (const float*)d_in[0];
    const float* proj  = (const float*)d_in[1];
    const float* adj   = (const float*)d_in[2];
    const float* lam   = (const float*)d_in[3];
    const float* w1 = (const float*)d_in[4];
    const float* b1 = (const float*)d_in[5];
    const float* w2 = (const float*)d_in[6];
    const float* b2 = (const float*)d_in[7];
    const float* w3 = (const float*)d_in[8];
    const float* b3 = (const float*)d_in[9];
    const float* gw3 = (const float*)d_in[10];
    const float* gb3 = (const float*)d_in[11];
    const float* gw4 = (const float*)d_in[12];
    const float* gb4 = (const float*)d_in[13];
    float* out = (float*)d_out;

    __nv_bfloat16 *p_adjb, *p_supT, *p_gsupT;
    float *p_g, *p_g2;
    cudaGetSymbolAddress((void**)&p_adjb, g_adjb);
    cudaGetSymbolAddress((void**)&p_supT, g_supT);
    cudaGetSymbolAddress((void**)&p_gsupT, g_gsupT);
    cudaGetSymbolAddress((void**)&p_g, g_g);
    cudaGetSymbolAddress((void**)&p_g2, g_g2);

    const int C2_SMEM = (C2_XH + 2 * C2_WH) * 2;
    cudaFuncSetAttribute((const void*)conv2mma_kernel,
                         cudaFuncAttributeMaxDynamicSharedMemorySize, C2_SMEM);
    const int G1_SMEM = STAGES * (128 * LDT + 128 * LDT) * 2;  // 81920
    const int G2_SMEM = STAGES * (128 * LDT + 64 * LDT) * 2;   // 61440
    cudaFuncSetAttribute((const void*)mma_gemm_kernel<128>,
                         cudaFuncAttributeMaxDynamicSharedMemorySize, G1_SMEM);
    cudaFuncSetAttribute((const void*)mma_gemm_kernel<64>,
                         cudaFuncAttributeMaxDynamicSharedMemorySize, G2_SMEM);

    {
        long TOT = (long)BB * NPAT * (KPAD / 8);
        adjconv_kernel<<<(int)((TOT + 255) / 256), 256>>>(adj);
    }
    patch_kernel<<<(BB * NPAT * 8 + 255) / 256, 256>>>(input);
    gemmA_kernel<<<dim3(KPAD / 32, BB), 128>>>(gw3);
    mma_gemm_kernel<128><<<dim3(32, 1, BB), 512, G1_SMEM>>>(p_adjb, p_supT, p_g, gb3, 1);

    wt_kernel<<<144, 256>>>(w2);
    conv1_kernel<<<dim3(16, 16, BB), 256>>>(input, w1, b1);
    conv2mma_kernel<<<dim3(8, 32, BB), 256, C2_SMEM>>>(b2);
    conv3_kernel<<<dim3(4, 16, BB), 256>>>(w3, b3);

    gemmB_kernel<<<dim3(KPAD / 32, BB), 128>>>(gw4);
    mma_gemm_kernel<64><<<dim3(32, 1, BB), 512, G2_SMEM>>>(p_adjb, p_gsupT, p_g2, gb4, 0);

    final_kernel<<<(BB * IMGD * IMGD + 255) / 256, 256>>>(input, proj, lam, out);
}

// round 9
// speedup vs baseline: 5.9293x; 1.0220x over previous
#include <cuda_runtime.h>
#include <cuda_bf16.h>
#include <cuda_fp16.h>
#include <cstdint>

// ---------------- problem constants ----------------
#define BB   4
#define IMGD 256
#define HID  64
#define PH   63
#define NPAT 3969   // 63*63
#define PPF  64     // 8*8 patch pixels
#define GHD  128
#define KPAD 4032   // 63*64, padded K for tensor GEMM
#define NCHUNK 126  // KPAD / 32

// ---------------- scratch (device globals; no runtime alloc) ----------------
__device__ __half g_h1i[(long)BB*IMGD*IMGD*HID];      // conv1 out, [b][y][x][ic] fp16
__device__ __half g_h2h[(long)BB*HID*IMGD*IMGD];      // conv2 out, [b][oc][y][x] fp16
__device__ float g_tmp2[BB*IMGD*IMGD];                // conv3 out
__device__ float g_patch[BB*NPAT*PPF];                // [b][n][64]
__device__ float g_g[(long)BB*NPAT*GHD];              // relu(adj@sup+b3)
__device__ float g_g2[(long)BB*NPAT*PPF];             // adj@gsup+b4
__device__ __nv_bfloat16 g_adjb[(long)BB*NPAT*KPAD];  // adj bf16 K-padded
__device__ __nv_bfloat16 g_supT[(long)BB*GHD*KPAD];   // (patch@W3)^T bf16
__device__ __nv_bfloat16 g_gsupT[(long)BB*PPF*KPAD];  // (g@W4)^T bf16
__device__ __half g_w2t[9*64*64];                     // w2 [tap][oc][ic] fp16

__device__ __forceinline__ uint32_t smem_to_u32(const void* p) {
    uint32_t a;
    asm("{ .reg .u64 t; cvta.to.shared.u64 t, %1; cvt.u32.u64 %0, t; }"
        : "=r"(a) : "l"(p));
    return a;
}
__device__ __forceinline__ void ldmatrix_x4(uint32_t* r, uint32_t addr) {
    asm volatile("ldmatrix.sync.aligned.m8n8.x4.shared.b16 {%0,%1,%2,%3}, [%4];"
                 : "=r"(r[0]), "=r"(r[1]), "=r"(r[2]), "=r"(r[3]) : "r"(addr));
}
__device__ __forceinline__ void ldmatrix_x2(uint32_t* r, uint32_t addr) {
    asm volatile("ldmatrix.sync.aligned.m8n8.x2.shared.b16 {%0,%1}, [%2];"
                 : "=r"(r[0]), "=r"(r[1]) : "r"(addr));
}
__device__ __forceinline__ void mma16816_bf16(float* d, const uint32_t* a, const uint32_t* b) {
    asm volatile(
        "mma.sync.aligned.m16n8k16.row.col.f32.bf16.bf16.f32 "
        "{%0,%1,%2,%3}, {%4,%5,%6,%7}, {%8,%9}, {%0,%1,%2,%3};"
        : "+f"(d[0]), "+f"(d[1]), "+f"(d[2]), "+f"(d[3])
        : "r"(a[0]), "r"(a[1]), "r"(a[2]), "r"(a[3]), "r"(b[0]), "r"(b[1]));
}
__device__ __forceinline__ void mma16816_f16(float* d, const uint32_t* a, const uint32_t* b) {
    asm volatile(
        "mma.sync.aligned.m16n8k16.row.col.f32.f16.f16.f32 "
        "{%0,%1,%2,%3}, {%4,%5,%6,%7}, {%8,%9}, {%0,%1,%2,%3};"
        : "+f"(d[0]), "+f"(d[1]), "+f"(d[2]), "+f"(d[3])
        : "r"(a[0]), "r"(a[1]), "r"(a[2]), "r"(a[3]), "r"(b[0]), "r"(b[1]));
}
__device__ __forceinline__ void cp_async16(uint32_t dst, const void* src, uint32_t bytes) {
    asm volatile("cp.async.cg.shared.global [%0], [%1], 16, %2;"
                 :: "r"(dst), "l"(src), "r"(bytes));
}
#define CP_COMMIT() asm volatile("cp.async.commit_group;" ::: "memory")
#define CP_WAIT(n)  asm volatile("cp.async.wait_group %0;" :: "n"(n) : "memory")

// ==================== weight transform: w2 OIHW -> [tap][oc][ic] fp16 =========
__global__ void wt_kernel(const float* __restrict__ w2) {
    int idx = blockIdx.x * 256 + threadIdx.x;
    if (idx >= 64 * 64 * 9) return;
    int oc = idx / 576, r = idx - oc * 576;
    int ic = r / 9, t = r - ic * 9;
    g_w2t[t * 4096 + oc * 64 + ic] = __float2half(w2[idx]);
}

// ==================== conv1: 1 -> 64, relu, interleaved fp16 out =============
__global__ void __launch_bounds__(256) conv1_kernel(const float* __restrict__ in,
                             const float* __restrict__ w,
                             const float* __restrict__ bias) {
    __shared__ float sIn[18][18];
    __shared__ float sW[576];
    __shared__ float sB[64];
    __shared__ __half sOut[16 * 16 * 64];
    int b = blockIdx.z;
    int x0 = blockIdx.x * 16, y0 = blockIdx.y * 16;
    int tid = threadIdx.x;
    for (int i = tid; i < 576; i += 256) sW[i] = w[i];
    if (tid < 64) sB[tid] = bias[tid];
    for (int i = tid; i < 324; i += 256) {
        int yy = i / 18, xx = i - yy * 18;
        int gy = y0 + yy - 1, gx = x0 + xx - 1;
        float v = 0.f;
        if (gy >= 0 && gy < IMGD && gx >= 0 && gx < IMGD)
            v = in[(long)b * IMGD * IMGD + gy * IMGD + gx];
        sIn[yy][xx] = v;
    }
    __syncthreads();
    int tx = tid & 15, ty = tid >> 4;
    float r[9];
#pragma unroll
    for (int dy = 0; dy < 3; dy++)
#pragma unroll
        for (int dx = 0; dx < 3; dx++)
            r[dy * 3 + dx] = sIn[ty + dy][tx + dx];
#pragma unroll 1
    for (int oc0 = 0; oc0 < 64; oc0 += 8) {
        __half hv[8];
#pragma unroll
        for (int o = 0; o < 8; o++) {
            float acc = sB[oc0 + o];
#pragma unroll
            for (int t = 0; t < 9; t++) acc += r[t] * sW[(oc0 + o) * 9 + t];
            hv[o] = __float2half(fmaxf(acc, 0.f));
        }
        *(uint4*)&sOut[tid * 64 + oc0] = *(uint4*)hv;
    }
    __syncthreads();
    for (int i = tid; i < 2048; i += 256) {
        int row = i >> 7;
        int c = i & 127;
        long e = (((long)b * IMGD * IMGD + (y0 + row) * IMGD + x0) << 6) + c * 8;
        *(uint4*)&g_h1i[e] = *(uint4*)&sOut[row * 1024 + c * 8];
    }
}

// ==================== conv2: fp16 HMMA, 9-tap shifted GEMM ====================
#define C2_XH (340 * 72)
#define C2_WH (64 * 72)
__global__ void __launch_bounds__(256) conv2mma_kernel(const float* __restrict__ bias) {
    extern __shared__ __half dsm[];
    __half* X_s = dsm;
    __half* W_s[2] = {dsm + C2_XH, dsm + C2_XH + C2_WH};
    int tid = threadIdx.x, lane = tid & 31, wid = tid >> 5;
    int b = blockIdx.z, y0 = blockIdx.y * 8, x0 = blockIdx.x * 32;
    int wm = (wid & 3) * 64;
    int wn = (wid >> 2) * 32;

    for (int i = tid; i < 2720; i += 256) {
        int pos = i >> 3, q = i & 7;
        int row = pos / 34, col = pos - row * 34;
        int gy = y0 + row - 1, gx = x0 + col - 1;
        uint4 v = make_uint4(0u, 0u, 0u, 0u);
        if (gy >= 0 && gy < IMGD && gx >= 0 && gx < IMGD)
            v = *(const uint4*)&g_h1i[(((long)b * IMGD * IMGD + gy * IMGD + gx) << 6) + q * 8];
        *(uint4*)&X_s[pos * 72 + q * 8] = v;
    }
    for (int i = tid; i < 512; i += 256) {
        int oc = i >> 3, q = i & 7;
        *(uint4*)&W_s[0][oc * 72 + q * 8] = *(const uint4*)&g_w2t[oc * 64 + q * 8];
    }
    __syncthreads();

    float acc[4][4][4];
#pragma unroll
    for (int i = 0; i < 4; i++)
#pragma unroll
        for (int j = 0; j < 4; j++)
#pragma unroll
            for (int q = 0; q < 4; q++) acc[i][j][q] = 0.f;

    uint32_t xb = smem_to_u32(X_s);
    uint32_t wb[2] = {smem_to_u32(W_s[0]), smem_to_u32(W_s[1])};

    uint32_t abase[4];
#pragma unroll
    for (int am = 0; am < 4; am++) {
        int p0 = wm + am * 16;
        abase[am] = xb + (uint32_t)((((p0 >> 5) * 34) + (p0 & 31) + (lane & 15)) * 144)
                       + (uint32_t)((lane >> 4) * 16);
    }
    uint32_t bbase[4];
#pragma unroll
    for (int an = 0; an < 4; an++)
        bbase[an] = (uint32_t)((wn + an * 8 + (lane & 7)) * 144)
                  + (uint32_t)(((lane >> 3) & 1) * 16);

    for (int tap = 0; tap < 9; tap++) {
        int cur = tap & 1;
        if (tap < 8) {
            const __half* src = g_w2t + (tap + 1) * 4096;
            for (int i = tid; i < 512; i += 256) {
                int oc = i >> 3, q = i & 7;
                *(uint4*)&W_s[cur ^ 1][oc * 72 + q * 8] = *(const uint4*)&src[oc * 64 + q * 8];
            }
        }
        int dy = tap / 3, dx = tap - dy * 3;
        uint32_t toff = (uint32_t)((dy * 34 + dx) * 144);
#pragma unroll
        for (int kb = 0; kb < 64; kb += 16) {
            uint32_t af[4][4], bf[4][2];
#pragma unroll
            for (int am = 0; am < 4; am++)
                ldmatrix_x4(af[am], abase[am] + toff + kb * 2);
#pragma unroll
            for (int an = 0; an < 4; an++)
                ldmatrix_x2(bf[an], wb[cur] + bbase[an] + kb * 2);
#pragma unroll
            for (int am = 0; am < 4; am++)
#pragma unroll
                for (int an = 0; an < 4; an++)
                    mma16816_f16(acc[am][an], af[am], bf[an]);
        }
        __syncthreads();
    }

    int r0 = lane >> 2, c0l = (lane & 3) * 2;
#pragma unroll
    for (int am = 0; am < 4; am++) {
#pragma unroll
        for (int an = 0; an < 4; an++) {
            int oc = wn + an * 8 + c0l;
            float b0 = bias[oc], b1 = bias[oc + 1];
#pragma unroll
            for (int h = 0; h < 2; h++) {
                int p = wm + am * 16 + r0 + h * 8;
                int rr = p >> 5, cc = p & 31;
                long o = (((long)b * HID + oc) << 16) + ((y0 + rr) << 8) + (x0 + cc);
                g_h2h[o] = __float2half(fmaxf(acc[am][an][h * 2 + 0] + b0, 0.f));
                g_h2h[o + (1L << 16)] = __float2half(fmaxf(acc[am][an][h * 2 + 1] + b1, 0.f));
            }
        }
    }
}

// ==================== conv3: 64 -> 1, 3x3 SAME (fp16 smem) ====================
// row layout (72 halves): [0..63]=cols x0..x0+63, [64]=col x0-1, [65]=col x0+64
__global__ void __launch_bounds__(256) conv3_kernel(const float* __restrict__ w,
                             const float* __restrict__ bias) {
    __shared__ __half sH[4][18][72];
    __shared__ float sW[576];
    int b = blockIdx.z;
    int x0 = blockIdx.x * 64, y0 = blockIdx.y * 16;
    int tid = threadIdx.x;
    for (int i = tid; i < 576; i += 256) sW[i] = w[i];
    int tx = tid & 15, ty = tid >> 4;
    float acc[4] = {0.f, 0.f, 0.f, 0.f};
    for (int cc = 0; cc < 16; cc++) {
        __syncthreads();
        // body: 4 ic x 18 rows x 8 uint4
        for (int i = tid; i < 576; i += 256) {
            int ic = i / 144;
            int rem = i - ic * 144;
            int yy = rem >> 3, q = rem & 7;
            int gy = y0 + yy - 1;
            uint4 v = make_uint4(0u, 0u, 0u, 0u);
            if (gy >= 0 && gy < IMGD)
                v = *(const uint4*)&g_h2h[(((long)b * HID + cc * 4 + ic) << 16)
                                          + (gy << 8) + x0 + q * 8];
            *(uint4*)&sH[ic][yy][q * 8] = v;
        }
        // edges
        for (int i = tid; i < 144; i += 256) {
            int ic = i / 36;
            int rem = i - ic * 36;
            int yy = rem >> 1, side = rem & 1;
            int gy = y0 + yy - 1;
            int gx = side ? x0 + 64 : x0 - 1;
            __half v = __ushort_as_half(0);
            if (gy >= 0 && gy < IMGD && gx >= 0 && gx < IMGD)
                v = g_h2h[(((long)b * HID + cc * 4 + ic) << 16) + (gy << 8) + gx];
            sH[ic][yy][64 + side] = v;
        }
        __syncthreads();
#pragma unroll
        for (int ic = 0; ic < 4; ic++) {
            float rin[3][6];
#pragma unroll
            for (int dy = 0; dy < 3; dy++)
#pragma unroll
                for (int j = 0; j < 6; j++) {
                    int c = tx * 4 + j - 1;
                    int cm = (c < 0) ? 64 : ((c > 63) ? 65 : c);
                    rin[dy][j] = __half2float(sH[ic][ty + dy][cm]);
                }
            float wv[9];
#pragma unroll
            for (int t = 0; t < 9; t++) wv[t] = sW[(cc * 4 + ic) * 9 + t];
#pragma unroll
            for (int dy = 0; dy < 3; dy++)
#pragma unroll
                for (int dx = 0; dx < 3; dx++)
#pragma unroll
                    for (int p = 0; p < 4; p++)
                        acc[p] += rin[dy][p + dx] * wv[dy * 3 + dx];
        }
    }
    float bv = bias[0];
    float4 o;
    o.x = acc[0] + bv; o.y = acc[1] + bv; o.z = acc[2] + bv; o.w = acc[3] + bv;
    *(float4*)&g_tmp2[(long)b * IMGD * IMGD + (y0 + ty) * IMGD + x0 + tx * 4] = o;
}

// ==================== GCN branch ====================

__global__ void patch_kernel(const float* __restrict__ in) {
    int idx = blockIdx.x * 256 + threadIdx.x;
    if (idx >= BB * NPAT * 8) return;
    int i = idx & 7;
    int t = idx >> 3;
    int n = t % NPAT;
    int b = t / NPAT;
    int py = n / PH, px = n - py * PH;
    const float* src = in + (long)b * IMGD * IMGD + (py * 4 + i) * IMGD + px * 4;
    float* dst = g_patch + ((long)b * NPAT + n) * PPF + i * 8;
    *(float4*)dst = *(const float4*)src;
    *(float4*)(dst + 4) = *(const float4*)(src + 4);
}

__global__ void __launch_bounds__(256) adjconv_kernel(const float* __restrict__ adj) {
    long idx = (long)blockIdx.x * 256 + threadIdx.x;
    const long TOT = (long)BB * NPAT * (KPAD / 8);
    if (idx >= TOT) return;
    int kq = (int)(idx % (KPAD / 8));
    long row = idx / (KPAD / 8);
    int k0 = kq * 8;
    const float* src = adj + row * NPAT + k0;
    __nv_bfloat16 o[8];
#pragma unroll
    for (int j = 0; j < 8; j++) {
        float v = (k0 + j < NPAT) ? src[j] : 0.f;
        o[j] = __float2bfloat16(v);
    }
    *(uint4*)&g_adjb[row * KPAD + k0] = *(uint4*)o;
}

__global__ void __launch_bounds__(128) gemmA_kernel(const float* __restrict__ w3) {
    __shared__ float sP[32][65];
    __shared__ float sW[64][128];
    int b = blockIdx.y;
    int n0 = blockIdx.x * 32;
    int tid = threadIdx.x;
    for (int l = 0; l < 64; l++) {
        int idx = tid + l * 128;
        sW[idx >> 7][idx & 127] = w3[idx];
    }
    for (int l = 0; l < 16; l++) {
        int idx = tid + l * 128;
        int n = idx >> 6, k = idx & 63;
        float v = 0.f;
        if (n0 + n < NPAT) v = g_patch[((long)b * NPAT + n0 + n) * PPF + k];
        sP[n][k] = v;
    }
    __syncthreads();
    int g = tid;
    float acc[32];
#pragma unroll
    for (int n = 0; n < 32; n++) acc[n] = 0.f;
    for (int k = 0; k < 64; k++) {
        float wv = sW[k][g];
#pragma unroll
        for (int n = 0; n < 32; n++) acc[n] += sP[n][k] * wv;
    }
    __nv_bfloat16* dst = g_supT + ((long)b * GHD + g) * KPAD + n0;
#pragma unroll
    for (int n = 0; n < 32; n++)
        dst[n] = (n0 + n < NPAT) ? __float2bfloat16(acc[n]) : __float2bfloat16(0.f);
}

__global__ void __launch_bounds__(128) gemmB_kernel(const float* __restrict__ w4) {
    __shared__ float sG[32][129];
    __shared__ float sW[64][64];
    int b = blockIdx.y;
    int n0 = blockIdx.x * 32;
    int tid = threadIdx.x;
    int p = tid & 63, half = tid >> 6;
    float acc[16];
#pragma unroll
    for (int i = 0; i < 16; i++) acc[i] = 0.f;
    for (int kc = 0; kc < 2; kc++) {
        __syncthreads();
        for (int l = 0; l < 32; l++) {
            int idx = tid + l * 128;
            int kk = idx >> 6, pp = idx & 63;
            sW[kk][pp] = w4[(kc * 64 + kk) * 64 + pp];
        }
        for (int l = 0; l < 16; l++) {
            int idx = tid + l * 128;
            int n = idx >> 6, kk = idx & 63;
            float v = 0.f;
            if (n0 + n < NPAT) v = g_g[((long)b * NPAT + n0 + n) * GHD + kc * 64 + kk];
            sG[n][kk] = v;
        }
        __syncthreads();
        for (int kk = 0; kk < 64; kk++) {
            float wv = sW[kk][p];
#pragma unroll
            for (int i = 0; i < 16; i++) acc[i] += sG[half * 16 + i][kk] * wv;
        }
    }
    __nv_bfloat16* dst = g_gsupT + ((long)b * PPF + p) * KPAD + n0 + half * 16;
#pragma unroll
    for (int i = 0; i < 16; i++)
        dst[i] = (n0 + half * 16 + i < NPAT) ? __float2bfloat16(acc[i]) : __float2bfloat16(0.f);
}

// ---------------- big HMMA GEMM, cp.async 4-stage, K-split warp grid ---------
// 8 warps as (2M x 2N x 2K); warp tile 64 x (NN/2) x 16.
// k-group 1 dumps accumulators to smem; k-group 0 reduces + epilogue.
#define LDT 40
#define STAGES 4

template<int NN>
__global__ void __launch_bounds__(256) mma_gemm_kernel(
        const __nv_bfloat16* __restrict__ A,
        const __nv_bfloat16* __restrict__ B,
        float* __restrict__ C,
        const float* __restrict__ bias, int relu) {
    constexpr int WNw = NN / 2;          // warp N tile: 64 or 32
    constexpr int NA = WNw / 8;          // 8 or 4
    constexpr int ASTG = 128 * LDT;
    constexpr int BSTG = NN * LDT;
    constexpr int NBU = NN * 4 / 256;    // B 16B units per thread (2 or 1)
    constexpr int RSTR = WNw + 1;        // reduction row stride (odd)
    extern __shared__ __nv_bfloat16 gsm[];
    __nv_bfloat16* A_s = gsm;
    __nv_bfloat16* B_s = gsm + STAGES * ASTG;

    int tid = threadIdx.x;
    int lane = tid & 31;
    int wid = tid >> 5;
    int mi = wid & 1, ni = (wid >> 1) & 1, kg = wid >> 2;
    int wm = mi * 64;
    int wn = ni * WNw;
    int bz = blockIdx.z;
    int m0 = blockIdx.x * 128;

    const __nv_bfloat16* Ab = A + (long)bz * NPAT * KPAD;
    const __nv_bfloat16* Bb = B + (long)bz * NN * KPAD;
    float* Cb = C + (long)bz * NPAT * NN;

    float acc[4][NA][4];
#pragma unroll
    for (int i = 0; i < 4; i++)
#pragma unroll
        for (int j = 0; j < NA; j++)
#pragma unroll
            for (int q = 0; q < 4; q++) acc[i][j][q] = 0.f;

    // loaders: 16B units. A: 512 units -> 2/thread; B: NN*4 units -> NBU/thread
    int a_row[2], a_part[2];
    uint32_t a_dst[2], a_bytes[2];
    const __nv_bfloat16* a_src[2];
#pragma unroll
    for (int l = 0; l < 2; l++) {
        int u = tid + l * 256;
        a_row[l] = u >> 2; a_part[l] = u & 3;
        int gm = m0 + a_row[l];
        a_bytes[l] = (gm < NPAT) ? 16u : 0u;
        int gmc = gm < NPAT ? gm : NPAT - 1;
        a_src[l] = Ab + (long)gmc * KPAD + a_part[l] * 8;
        a_dst[l] = smem_to_u32(&A_s[a_row[l] * LDT + a_part[l] * 8]);
    }
    uint32_t b_dst[NBU];
    const __nv_bfloat16* b_src[NBU];
#pragma unroll
    for (int l = 0; l < NBU; l++) {
        int u = tid + l * 256;
        int row = u >> 2, part = u & 3;
        b_src[l] = Bb + (long)row * KPAD + part * 8;
        b_dst[l] = smem_to_u32(&B_s[row * LDT + part * 8]);
    }

    auto issue = [&](int c) {
        int s = c % STAGES;
        long kb = (long)c * 32;
#pragma unroll
        for (int l = 0; l < 2; l++)
            cp_async16(a_dst[l] + s * (ASTG * 2), a_src[l] + kb, a_bytes[l]);
#pragma unroll
        for (int l = 0; l < NBU; l++)
            cp_async16(b_dst[l] + s * (BSTG * 2), b_src[l] + kb, 16u);
        CP_COMMIT();
    };

#pragma unroll
    for (int s = 0; s < STAGES - 1; s++) issue(s);

    uint32_t a_base0 = smem_to_u32(A_s);
    uint32_t b_base0 = smem_to_u32(B_s);
    uint32_t kks = (uint32_t)(kg * 32);   // byte offset of this warp's K half

    for (int c = 0; c < NCHUNK; c++) {
        CP_WAIT(STAGES - 2);
        __syncthreads();
        int s = c % STAGES;
        uint32_t a_base = a_base0 + s * (ASTG * 2);
        uint32_t b_base = b_base0 + s * (BSTG * 2);
        uint32_t af[4][4];
#pragma unroll
        for (int am = 0; am < 4; am++) {
            uint32_t addr = a_base +
                (uint32_t)((wm + am * 16 + (lane & 15)) * (LDT * 2)) +
                kks + (uint32_t)((lane >> 4) * 16);
            ldmatrix_x4(af[am], addr);
        }
        uint32_t bf[NA][2];
#pragma unroll
        for (int an = 0; an < NA; an++) {
            uint32_t addr = b_base +
                (uint32_t)((wn + an * 8 + (lane & 7)) * (LDT * 2)) +
                kks + (uint32_t)(((lane >> 3) & 1) * 16);
            ldmatrix_x2(bf[an], addr);
        }
#pragma unroll
        for (int am = 0; am < 4; am++)
#pragma unroll
            for (int an = 0; an < NA; an++)
                mma16816_bf16(acc[am][an], af[am], bf[an]);
        if (c + STAGES - 1 < NCHUNK) issue(c + STAGES - 1);
        else CP_COMMIT();
    }

    // ---- cross-k reduction via smem (reuse pipeline smem) ----
    CP_WAIT(0);
    __syncthreads();
    int r0 = lane >> 2, c0 = (lane & 3) * 2;
    float* red = (float*)gsm;
    int region = (mi * 2 + ni) * (64 * RSTR);
    if (kg == 1) {
#pragma unroll
        for (int am = 0; am < 4; am++)
#pragma unroll
            for (int an = 0; an < NA; an++)
#pragma unroll
                for (int q = 0; q < 4; q++) {
                    int row = am * 16 + r0 + ((q >> 1) << 3);
                    int col = an * 8 + c0 + (q & 1);
                    red[region + row * RSTR + col] = acc[am][an][q];
                }
    }
    __syncthreads();
    if (kg == 0) {
#pragma unroll
        for (int am = 0; am < 4; am++)
#pragma unroll
            for (int an = 0; an < NA; an++)
#pragma unroll
                for (int q = 0; q < 4; q++) {
                    int row = am * 16 + r0 + ((q >> 1) << 3);
                    int col = an * 8 + c0 + (q & 1);
                    acc[am][an][q] += red[region + row * RSTR + col];
                }
        // ---- epilogue (4 warps cover full 128 x NN tile) ----
#pragma unroll
        for (int am = 0; am < 4; am++) {
#pragma unroll
            for (int an = 0; an < NA; an++) {
                int gn = wn + an * 8 + c0;
                float b0 = bias[gn], b1 = bias[gn + 1];
                int gr0 = m0 + wm + am * 16 + r0;
                float v0 = acc[am][an][0] + b0;
                float v1 = acc[am][an][1] + b1;
                float v2 = acc[am][an][2] + b0;
                float v3 = acc[am][an][3] + b1;
                if (relu) {
                    v0 = fmaxf(v0, 0.f); v1 = fmaxf(v1, 0.f);
                    v2 = fmaxf(v2, 0.f); v3 = fmaxf(v3, 0.f);
                }
                if (gr0 < NPAT) {
                    Cb[(long)gr0 * NN + gn] = v0;
                    Cb[(long)gr0 * NN + gn + 1] = v1;
                }
                if (gr0 + 8 < NPAT) {
                    Cb[(long)(gr0 + 8) * NN + gn] = v2;
                    Cb[(long)(gr0 + 8) * NN + gn + 1] = v3;
                }
            }
        }
    }
}

// ---------------- final: tmp1 + tmp2 + patch2img(g2)/mask, relu --------------
__global__ void final_kernel(const float* __restrict__ in,
                             const float* __restrict__ proj,
                             const float* __restrict__ lam,
                             float* __restrict__ out) {
    int idx = blockIdx.x * 256 + threadIdx.x;
    if (idx >= BB * IMGD * IMGD) return;
    int x = idx & 255, y = (idx >> 8) & 255, b = idx >> 16;
    float lv = lam[0];
    float iv = in[idx], pv = proj[idx];
    float t1 = iv + lv * (pv - iv);
    float t2 = g_tmp2[idx];
    int tyv = y - 7;
    int py_lo = tyv > 0 ? (tyv + 3) >> 2 : 0;
    int py_hi = min(62, y >> 2);
    int txv = x - 7;
    int px_lo = txv > 0 ? (txv + 3) >> 2 : 0;
    int px_hi = min(62, x >> 2);
    float s = 0.f;
    int cnt = (py_hi - py_lo + 1) * (px_hi - px_lo + 1);
    for (int py = py_lo; py <= py_hi; py++) {
        int i = y - 4 * py;
        for (int px = px_lo; px <= px_hi; px++) {
            int j = x - 4 * px;
            s += g_g2[((long)b * NPAT + (py * PH + px)) * PPF + i * 8 + j];
        }
    }
    float v = t1 + t2 + s / (float)cnt;
    out[idx] = fmaxf(v, 0.f);
}

// ---------------- launch ----------------
extern "C" void kernel_launch(void* const* d_in, const int* in_sizes, int n_in,
                              void* d_out, int out_size) {
    const float* input = (const float*)d_in[0];
    const float* proj  = (const float*)d_in[1];
    const float* adj   = (const float*)d_in[2];
    const float* lam   = (const float*)d_in[3];
    const float* w1 = (const float*)d_in[4];
    const float* b1 = (const float*)d_in[5];
    const float* w2 = (const float*)d_in[6];
    const float* b2 = (const float*)d_in[7];
    const float* w3 = (const float*)d_in[8];
    const float* b3 = (const float*)d_in[9];
    const float* gw3 = (const float*)d_in[10];
    const float* gb3 = (const float*)d_in[11];
    const float* gw4 = (const float*)d_in[12];
    const float* gb4 = (const float*)d_in[13];
    float* out = (float*)d_out;

    __nv_bfloat16 *p_adjb, *p_supT, *p_gsupT;
    float *p_g, *p_g2;
    cudaGetSymbolAddress((void**)&p_adjb, g_adjb);
    cudaGetSymbolAddress((void**)&p_supT, g_supT);
    cudaGetSymbolAddress((void**)&p_gsupT, g_gsupT);
    cudaGetSymbolAddress((void**)&p_g, g_g);
    cudaGetSymbolAddress((void**)&p_g2, g_g2);

    const int C2_SMEM = (C2_XH + 2 * C2_WH) * 2;
    cudaFuncSetAttribute((const void*)conv2mma_kernel,
                         cudaFuncAttributeMaxDynamicSharedMemorySize, C2_SMEM);
    const int G1_SMEM = STAGES * (128 * LDT + 128 * LDT) * 2;  // 81920
    const int G2_SMEM = STAGES * (128 * LDT + 64 * LDT) * 2;   // 61440
    cudaFuncSetAttribute((const void*)mma_gemm_kernel<128>,
                         cudaFuncAttributeMaxDynamicSharedMemorySize, G1_SMEM);
    cudaFuncSetAttribute((const void*)mma_gemm_kernel<64>,
                         cudaFuncAttributeMaxDynamicSharedMemorySize, G2_SMEM);

    {
        long TOT = (long)BB * NPAT * (KPAD / 8);
        adjconv_kernel<<<(int)((TOT + 255) / 256), 256>>>(adj);
    }
    patch_kernel<<<(BB * NPAT * 8 + 255) / 256, 256>>>(input);
    gemmA_kernel<<<dim3(KPAD / 32, BB), 128>>>(gw3);
    mma_gemm_kernel<128><<<dim3(32, 1, BB), 256, G1_SMEM>>>(p_adjb, p_supT, p_g, gb3, 1);

    wt_kernel<<<144, 256>>>(w2);
    conv1_kernel<<<dim3(16, 16, BB), 256>>>(input, w1, b1);
    conv2mma_kernel<<<dim3(8, 32, BB), 256, C2_SMEM>>>(b2);
    conv3_kernel<<<dim3(4, 16, BB), 256>>>(w3, b3);

    gemmB_kernel<<<dim3(KPAD / 32, BB), 128>>>(gw4);
    mma_gemm_kernel<64><<<dim3(32, 1, BB), 256, G2_SMEM>>>(p_adjb, p_gsupT, p_g2, gb4, 0);

    final_kernel<<<(BB * IMGD * IMGD + 255) / 256, 256>>>(input, proj, lam, out);
}

// round 10
// speedup vs baseline: 5.9682x; 1.0066x over previous
#include <cuda_runtime.h>
#include <cuda_bf16.h>
#include <cuda_fp16.h>
#include <cstdint>

// ---------------- problem constants ----------------
#define BB   4
#define IMGD 256
#define HID  64
#define PH   63
#define NPAT 3969   // 63*63
#define PPF  64     // 8*8 patch pixels
#define GHD  128
#define KPAD 4032   // 63*64, padded K for tensor GEMM
#define NCHUNK 126  // KPAD / 32

// ---------------- scratch (device globals; no runtime alloc) ----------------
__device__ __half g_h1i[(long)BB*IMGD*IMGD*HID];      // conv1 out, [b][y][x][ic] fp16
__device__ __half g_h2h[(long)BB*HID*IMGD*IMGD];      // conv2 out, [b][oc][y][x] fp16
__device__ float g_tmp2[BB*IMGD*IMGD];                // conv3 out
__device__ float g_patch[BB*NPAT*PPF];                // [b][n][64]
__device__ float g_g[(long)BB*NPAT*GHD];              // relu(adj@sup+b3)
__device__ float g_g2[(long)BB*NPAT*PPF];             // adj@gsup+b4
__device__ __nv_bfloat16 g_adjb[(long)BB*NPAT*KPAD];  // adj bf16 K-padded
__device__ __nv_bfloat16 g_supT[(long)BB*GHD*KPAD];   // (patch@W3)^T bf16
__device__ __nv_bfloat16 g_gsupT[(long)BB*PPF*KPAD];  // (g@W4)^T bf16
__device__ __half g_w2t[9*64*64];                     // w2 [tap][oc][ic] fp16

__device__ __forceinline__ uint32_t smem_to_u32(const void* p) {
    uint32_t a;
    asm("{ .reg .u64 t; cvta.to.shared.u64 t, %1; cvt.u32.u64 %0, t; }"
        : "=r"(a) : "l"(p));
    return a;
}
__device__ __forceinline__ void ldmatrix_x4(uint32_t* r, uint32_t addr) {
    asm volatile("ldmatrix.sync.aligned.m8n8.x4.shared.b16 {%0,%1,%2,%3}, [%4];"
                 : "=r"(r[0]), "=r"(r[1]), "=r"(r[2]), "=r"(r[3]) : "r"(addr));
}
__device__ __forceinline__ void ldmatrix_x2(uint32_t* r, uint32_t addr) {
    asm volatile("ldmatrix.sync.aligned.m8n8.x2.shared.b16 {%0,%1}, [%2];"
                 : "=r"(r[0]), "=r"(r[1]) : "r"(addr));
}
__device__ __forceinline__ void mma16816_bf16(float* d, const uint32_t* a, const uint32_t* b) {
    asm volatile(
        "mma.sync.aligned.m16n8k16.row.col.f32.bf16.bf16.f32 "
        "{%0,%1,%2,%3}, {%4,%5,%6,%7}, {%8,%9}, {%0,%1,%2,%3};"
        : "+f"(d[0]), "+f"(d[1]), "+f"(d[2]), "+f"(d[3])
        : "r"(a[0]), "r"(a[1]), "r"(a[2]), "r"(a[3]), "r"(b[0]), "r"(b[1]));
}
__device__ __forceinline__ void mma16816_f16(float* d, const uint32_t* a, const uint32_t* b) {
    asm volatile(
        "mma.sync.aligned.m16n8k16.row.col.f32.f16.f16.f32 "
        "{%0,%1,%2,%3}, {%4,%5,%6,%7}, {%8,%9}, {%0,%1,%2,%3};"
        : "+f"(d[0]), "+f"(d[1]), "+f"(d[2]), "+f"(d[3])
        : "r"(a[0]), "r"(a[1]), "r"(a[2]), "r"(a[3]), "r"(b[0]), "r"(b[1]));
}
__device__ __forceinline__ void cp_async16(uint32_t dst, const void* src, uint32_t bytes) {
    asm volatile("cp.async.cg.shared.global [%0], [%1], 16, %2;"
                 :: "r"(dst), "l"(src), "r"(bytes));
}
#define CP_COMMIT() asm volatile("cp.async.commit_group;" ::: "memory")
#define CP_WAIT(n)  asm volatile("cp.async.wait_group %0;" :: "n"(n) : "memory")

// ==================== weight transform: w2 OIHW -> [tap][oc][ic] fp16 =========
__global__ void wt_kernel(const float* __restrict__ w2) {
    int idx = blockIdx.x * 256 + threadIdx.x;
    if (idx >= 64 * 64 * 9) return;
    int oc = idx / 576, r = idx - oc * 576;
    int ic = r / 9, t = r - ic * 9;
    g_w2t[t * 4096 + oc * 64 + ic] = __float2half(w2[idx]);
}

// ==================== conv1: 1 -> 64, relu, interleaved fp16 out =============
__global__ void __launch_bounds__(256) conv1_kernel(const float* __restrict__ in,
                             const float* __restrict__ w,
                             const float* __restrict__ bias) {
    __shared__ float sIn[18][18];
    __shared__ float sW[576];
    __shared__ float sB[64];
    __shared__ __half sOut[16 * 16 * 64];
    int b = blockIdx.z;
    int x0 = blockIdx.x * 16, y0 = blockIdx.y * 16;
    int tid = threadIdx.x;
    for (int i = tid; i < 576; i += 256) sW[i] = w[i];
    if (tid < 64) sB[tid] = bias[tid];
    for (int i = tid; i < 324; i += 256) {
        int yy = i / 18, xx = i - yy * 18;
        int gy = y0 + yy - 1, gx = x0 + xx - 1;
        float v = 0.f;
        if (gy >= 0 && gy < IMGD && gx >= 0 && gx < IMGD)
            v = in[(long)b * IMGD * IMGD + gy * IMGD + gx];
        sIn[yy][xx] = v;
    }
    __syncthreads();
    int tx = tid & 15, ty = tid >> 4;
    float r[9];
#pragma unroll
    for (int dy = 0; dy < 3; dy++)
#pragma unroll
        for (int dx = 0; dx < 3; dx++)
            r[dy * 3 + dx] = sIn[ty + dy][tx + dx];
#pragma unroll 1
    for (int oc0 = 0; oc0 < 64; oc0 += 8) {
        __half hv[8];
#pragma unroll
        for (int o = 0; o < 8; o++) {
            float acc = sB[oc0 + o];
#pragma unroll
            for (int t = 0; t < 9; t++) acc += r[t] * sW[(oc0 + o) * 9 + t];
            hv[o] = __float2half(fmaxf(acc, 0.f));
        }
        *(uint4*)&sOut[tid * 64 + oc0] = *(uint4*)hv;
    }
    __syncthreads();
    for (int i = tid; i < 2048; i += 256) {
        int row = i >> 7;
        int c = i & 127;
        long e = (((long)b * IMGD * IMGD + (y0 + row) * IMGD + x0) << 6) + c * 8;
        *(uint4*)&g_h1i[e] = *(uint4*)&sOut[row * 1024 + c * 8];
    }
}

// ==================== conv2: fp16 HMMA, 9-tap shifted GEMM ====================
#define C2_XH (340 * 72)
#define C2_WH (64 * 72)
__global__ void __launch_bounds__(256) conv2mma_kernel(const float* __restrict__ bias) {
    extern __shared__ __half dsm[];
    __half* X_s = dsm;
    __half* W_s[2] = {dsm + C2_XH, dsm + C2_XH + C2_WH};
    int tid = threadIdx.x, lane = tid & 31, wid = tid >> 5;
    int b = blockIdx.z, y0 = blockIdx.y * 8, x0 = blockIdx.x * 32;
    int wm = (wid & 3) * 64;
    int wn = (wid >> 2) * 32;

    for (int i = tid; i < 2720; i += 256) {
        int pos = i >> 3, q = i & 7;
        int row = pos / 34, col = pos - row * 34;
        int gy = y0 + row - 1, gx = x0 + col - 1;
        uint4 v = make_uint4(0u, 0u, 0u, 0u);
        if (gy >= 0 && gy < IMGD && gx >= 0 && gx < IMGD)
            v = *(const uint4*)&g_h1i[(((long)b * IMGD * IMGD + gy * IMGD + gx) << 6) + q * 8];
        *(uint4*)&X_s[pos * 72 + q * 8] = v;
    }
    for (int i = tid; i < 512; i += 256) {
        int oc = i >> 3, q = i & 7;
        *(uint4*)&W_s[0][oc * 72 + q * 8] = *(const uint4*)&g_w2t[oc * 64 + q * 8];
    }
    __syncthreads();

    float acc[4][4][4];
#pragma unroll
    for (int i = 0; i < 4; i++)
#pragma unroll
        for (int j = 0; j < 4; j++)
#pragma unroll
            for (int q = 0; q < 4; q++) acc[i][j][q] = 0.f;

    uint32_t xb = smem_to_u32(X_s);
    uint32_t wb[2] = {smem_to_u32(W_s[0]), smem_to_u32(W_s[1])};

    uint32_t abase[4];
#pragma unroll
    for (int am = 0; am < 4; am++) {
        int p0 = wm + am * 16;
        abase[am] = xb + (uint32_t)((((p0 >> 5) * 34) + (p0 & 31) + (lane & 15)) * 144)
                       + (uint32_t)((lane >> 4) * 16);
    }
    uint32_t bbase[4];
#pragma unroll
    for (int an = 0; an < 4; an++)
        bbase[an] = (uint32_t)((wn + an * 8 + (lane & 7)) * 144)
                  + (uint32_t)(((lane >> 3) & 1) * 16);

    for (int tap = 0; tap < 9; tap++) {
        int cur = tap & 1;
        if (tap < 8) {
            const __half* src = g_w2t + (tap + 1) * 4096;
            for (int i = tid; i < 512; i += 256) {
                int oc = i >> 3, q = i & 7;
                *(uint4*)&W_s[cur ^ 1][oc * 72 + q * 8] = *(const uint4*)&src[oc * 64 + q * 8];
            }
        }
        int dy = tap / 3, dx = tap - dy * 3;
        uint32_t toff = (uint32_t)((dy * 34 + dx) * 144);
#pragma unroll
        for (int kb = 0; kb < 64; kb += 16) {
            uint32_t af[4][4], bf[4][2];
#pragma unroll
            for (int am = 0; am < 4; am++)
                ldmatrix_x4(af[am], abase[am] + toff + kb * 2);
#pragma unroll
            for (int an = 0; an < 4; an++)
                ldmatrix_x2(bf[an], wb[cur] + bbase[an] + kb * 2);
#pragma unroll
            for (int am = 0; am < 4; am++)
#pragma unroll
                for (int an = 0; an < 4; an++)
                    mma16816_f16(acc[am][an], af[am], bf[an]);
        }
        __syncthreads();
    }

    int r0 = lane >> 2, c0l = (lane & 3) * 2;
#pragma unroll
    for (int am = 0; am < 4; am++) {
#pragma unroll
        for (int an = 0; an < 4; an++) {
            int oc = wn + an * 8 + c0l;
            float b0 = bias[oc], b1 = bias[oc + 1];
#pragma unroll
            for (int h = 0; h < 2; h++) {
                int p = wm + am * 16 + r0 + h * 8;
                int rr = p >> 5, cc = p & 31;
                long o = (((long)b * HID + oc) << 16) + ((y0 + rr) << 8) + (x0 + cc);
                g_h2h[o] = __float2half(fmaxf(acc[am][an][h * 2 + 0] + b0, 0.f));
                g_h2h[o + (1L << 16)] = __float2half(fmaxf(acc[am][an][h * 2 + 1] + b1, 0.f));
            }
        }
    }
}

// ==================== conv3: 64 -> 1, 3x3 SAME (fp16 smem) ====================
__global__ void __launch_bounds__(256) conv3_kernel(const float* __restrict__ w,
                             const float* __restrict__ bias) {
    __shared__ __half sH[4][18][72];
    __shared__ float sW[576];
    int b = blockIdx.z;
    int x0 = blockIdx.x * 64, y0 = blockIdx.y * 16;
    int tid = threadIdx.x;
    for (int i = tid; i < 576; i += 256) sW[i] = w[i];
    int tx = tid & 15, ty = tid >> 4;
    float acc[4] = {0.f, 0.f, 0.f, 0.f};
    for (int cc = 0; cc < 16; cc++) {
        __syncthreads();
        for (int i = tid; i < 576; i += 256) {
            int ic = i / 144;
            int rem = i - ic * 144;
            int yy = rem >> 3, q = rem & 7;
            int gy = y0 + yy - 1;
            uint4 v = make_uint4(0u, 0u, 0u, 0u);
            if (gy >= 0 && gy < IMGD)
                v = *(const uint4*)&g_h2h[(((long)b * HID + cc * 4 + ic) << 16)
                                          + (gy << 8) + x0 + q * 8];
            *(uint4*)&sH[ic][yy][q * 8] = v;
        }
        for (int i = tid; i < 144; i += 256) {
            int ic = i / 36;
            int rem = i - ic * 36;
            int yy = rem >> 1, side = rem & 1;
            int gy = y0 + yy - 1;
            int gx = side ? x0 + 64 : x0 - 1;
            __half v = __ushort_as_half(0);
            if (gy >= 0 && gy < IMGD && gx >= 0 && gx < IMGD)
                v = g_h2h[(((long)b * HID + cc * 4 + ic) << 16) + (gy << 8) + gx];
            sH[ic][yy][64 + side] = v;
        }
        __syncthreads();
#pragma unroll
        for (int ic = 0; ic < 4; ic++) {
            float rin[3][6];
#pragma unroll
            for (int dy = 0; dy < 3; dy++)
#pragma unroll
                for (int j = 0; j < 6; j++) {
                    int c = tx * 4 + j - 1;
                    int cm = (c < 0) ? 64 : ((c > 63) ? 65 : c);
                    rin[dy][j] = __half2float(sH[ic][ty + dy][cm]);
                }
            float wv[9];
#pragma unroll
            for (int t = 0; t < 9; t++) wv[t] = sW[(cc * 4 + ic) * 9 + t];
#pragma unroll
            for (int dy = 0; dy < 3; dy++)
#pragma unroll
                for (int dx = 0; dx < 3; dx++)
#pragma unroll
                    for (int p = 0; p < 4; p++)
                        acc[p] += rin[dy][p + dx] * wv[dy * 3 + dx];
        }
    }
    float bv = bias[0];
    float4 o;
    o.x = acc[0] + bv; o.y = acc[1] + bv; o.z = acc[2] + bv; o.w = acc[3] + bv;
    *(float4*)&g_tmp2[(long)b * IMGD * IMGD + (y0 + ty) * IMGD + x0 + tx * 4] = o;
}

// ==================== GCN branch ====================

__global__ void patch_kernel(const float* __restrict__ in) {
    int idx = blockIdx.x * 256 + threadIdx.x;
    if (idx >= BB * NPAT * 8) return;
    int i = idx & 7;
    int t = idx >> 3;
    int n = t % NPAT;
    int b = t / NPAT;
    int py = n / PH, px = n - py * PH;
    const float* src = in + (long)b * IMGD * IMGD + (py * 4 + i) * IMGD + px * 4;
    float* dst = g_patch + ((long)b * NPAT + n) * PPF + i * 8;
    *(float4*)dst = *(const float4*)src;
    *(float4*)(dst + 4) = *(const float4*)(src + 4);
}

__global__ void __launch_bounds__(256) adjconv_kernel(const float* __restrict__ adj) {
    long idx = (long)blockIdx.x * 256 + threadIdx.x;
    const long TOT = (long)BB * NPAT * (KPAD / 8);
    if (idx >= TOT) return;
    int kq = (int)(idx % (KPAD / 8));
    long row = idx / (KPAD / 8);
    int k0 = kq * 8;
    const float* src = adj + row * NPAT + k0;
    __nv_bfloat16 o[8];
#pragma unroll
    for (int j = 0; j < 8; j++) {
        float v = (k0 + j < NPAT) ? src[j] : 0.f;
        o[j] = __float2bfloat16(v);
    }
    *(uint4*)&g_adjb[row * KPAD + k0] = *(uint4*)o;
}

__global__ void __launch_bounds__(128) gemmA_kernel(const float* __restrict__ w3) {
    __shared__ float sP[32][65];
    __shared__ float sW[64][128];
    int b = blockIdx.y;
    int n0 = blockIdx.x * 32;
    int tid = threadIdx.x;
    for (int l = 0; l < 64; l++) {
        int idx = tid + l * 128;
        sW[idx >> 7][idx & 127] = w3[idx];
    }
    for (int l = 0; l < 16; l++) {
        int idx = tid + l * 128;
        int n = idx >> 6, k = idx & 63;
        float v = 0.f;
        if (n0 + n < NPAT) v = g_patch[((long)b * NPAT + n0 + n) * PPF + k];
        sP[n][k] = v;
    }
    __syncthreads();
    int g = tid;
    float acc[32];
#pragma unroll
    for (int n = 0; n < 32; n++) acc[n] = 0.f;
    for (int k = 0; k < 64; k++) {
        float wv = sW[k][g];
#pragma unroll
        for (int n = 0; n < 32; n++) acc[n] += sP[n][k] * wv;
    }
    __nv_bfloat16* dst = g_supT + ((long)b * GHD + g) * KPAD + n0;
#pragma unroll
    for (int n = 0; n < 32; n++)
        dst[n] = (n0 + n < NPAT) ? __float2bfloat16(acc[n]) : __float2bfloat16(0.f);
}

__global__ void __launch_bounds__(128) gemmB_kernel(const float* __restrict__ w4) {
    __shared__ float sG[32][129];
    __shared__ float sW[64][64];
    int b = blockIdx.y;
    int n0 = blockIdx.x * 32;
    int tid = threadIdx.x;
    int p = tid & 63, half = tid >> 6;
    float acc[16];
#pragma unroll
    for (int i = 0; i < 16; i++) acc[i] = 0.f;
    for (int kc = 0; kc < 2; kc++) {
        __syncthreads();
        for (int l = 0; l < 32; l++) {
            int idx = tid + l * 128;
            int kk = idx >> 6, pp = idx & 63;
            sW[kk][pp] = w4[(kc * 64 + kk) * 64 + pp];
        }
        for (int l = 0; l < 16; l++) {
            int idx = tid + l * 128;
            int n = idx >> 6, kk = idx & 63;
            float v = 0.f;
            if (n0 + n < NPAT) v = g_g[((long)b * NPAT + n0 + n) * GHD + kc * 64 + kk];
            sG[n][kk] = v;
        }
        __syncthreads();
        for (int kk = 0; kk < 64; kk++) {
            float wv = sW[kk][p];
#pragma unroll
            for (int i = 0; i < 16; i++) acc[i] += sG[half * 16 + i][kk] * wv;
        }
    }
    __nv_bfloat16* dst = g_gsupT + ((long)b * PPF + p) * KPAD + n0 + half * 16;
#pragma unroll
    for (int i = 0; i < 16; i++)
        dst[i] = (n0 + half * 16 + i < NPAT) ? __float2bfloat16(acc[i]) : __float2bfloat16(0.f);
}

// ---------------- big HMMA GEMM, cp.async 5-stage, BM=64, 2 CTAs/SM ----------
// 8 warps as (2M x 2N x 2K); warp tile 32 x (NN/2) x 16.
// k-group 1 dumps accumulators to smem; k-group 0 reduces + epilogue.
#define LDT 40
#define STAGES 5

template<int NN>
__global__ void __launch_bounds__(256) mma_gemm_kernel(
        const __nv_bfloat16* __restrict__ A,
        const __nv_bfloat16* __restrict__ B,
        float* __restrict__ C,
        const float* __restrict__ bias, int relu) {
    constexpr int WNw = NN / 2;          // warp N tile: 64 or 32
    constexpr int NA = WNw / 8;          // 8 or 4
    constexpr int ASTG = 64 * LDT;
    constexpr int BSTG = NN * LDT;
    constexpr int NBU = NN * 4 / 256;    // B 16B units per thread (2 or 1)
    constexpr int RSTR = WNw + 1;        // reduction row stride (odd)
    extern __shared__ __nv_bfloat16 gsm[];
    __nv_bfloat16* A_s = gsm;
    __nv_bfloat16* B_s = gsm + STAGES * ASTG;

    int tid = threadIdx.x;
    int lane = tid & 31;
    int wid = tid >> 5;
    int mi = wid & 1, ni = (wid >> 1) & 1, kg = wid >> 2;
    int wm = mi * 32;
    int wn = ni * WNw;
    int bz = blockIdx.z;
    int m0 = blockIdx.x * 64;

    const __nv_bfloat16* Ab = A + (long)bz * NPAT * KPAD;
    const __nv_bfloat16* Bb = B + (long)bz * NN * KPAD;
    float* Cb = C + (long)bz * NPAT * NN;

    float acc[2][NA][4];
#pragma unroll
    for (int i = 0; i < 2; i++)
#pragma unroll
        for (int j = 0; j < NA; j++)
#pragma unroll
            for (int q = 0; q < 4; q++) acc[i][j][q] = 0.f;

    // loaders: 16B units. A: 256 units -> 1/thread; B: NN*4 units -> NBU/thread
    int a_row = tid >> 2, a_part = tid & 3;
    int gm = m0 + a_row;
    uint32_t a_bytes = (gm < NPAT) ? 16u : 0u;
    int gmc = gm < NPAT ? gm : NPAT - 1;
    const __nv_bfloat16* a_src = Ab + (long)gmc * KPAD + a_part * 8;
    uint32_t a_dst = smem_to_u32(&A_s[a_row * LDT + a_part * 8]);
    uint32_t b_dst[NBU];
    const __nv_bfloat16* b_src[NBU];
#pragma unroll
    for (int l = 0; l < NBU; l++) {
        int u = tid + l * 256;
        int row = u >> 2, part = u & 3;
        b_src[l] = Bb + (long)row * KPAD + part * 8;
        b_dst[l] = smem_to_u32(&B_s[row * LDT + part * 8]);
    }

    auto issue = [&](int c) {
        int s = c % STAGES;
        long kb = (long)c * 32;
        cp_async16(a_dst + s * (ASTG * 2), a_src + kb, a_bytes);
#pragma unroll
        for (int l = 0; l < NBU; l++)
            cp_async16(b_dst[l] + s * (BSTG * 2), b_src[l] + kb, 16u);
        CP_COMMIT();
    };

#pragma unroll
    for (int s = 0; s < STAGES - 1; s++) issue(s);

    uint32_t a_base0 = smem_to_u32(A_s);
    uint32_t b_base0 = smem_to_u32(B_s);
    uint32_t kks = (uint32_t)(kg * 32);   // byte offset of this warp's K half

    for (int c = 0; c < NCHUNK; c++) {
        CP_WAIT(STAGES - 2);
        __syncthreads();
        int s = c % STAGES;
        uint32_t a_base = a_base0 + s * (ASTG * 2);
        uint32_t b_base = b_base0 + s * (BSTG * 2);
        uint32_t af[2][4];
#pragma unroll
        for (int am = 0; am < 2; am++) {
            uint32_t addr = a_base +
                (uint32_t)((wm + am * 16 + (lane & 15)) * (LDT * 2)) +
                kks + (uint32_t)((lane >> 4) * 16);
            ldmatrix_x4(af[am], addr);
        }
        uint32_t bf[NA][2];
#pragma unroll
        for (int an = 0; an < NA; an++) {
            uint32_t addr = b_base +
                (uint32_t)((wn + an * 8 + (lane & 7)) * (LDT * 2)) +
                kks + (uint32_t)(((lane >> 3) & 1) * 16);
            ldmatrix_x2(bf[an], addr);
        }
#pragma unroll
        for (int am = 0; am < 2; am++)
#pragma unroll
            for (int an = 0; an < NA; an++)
                mma16816_bf16(acc[am][an], af[am], bf[an]);
        if (c + STAGES - 1 < NCHUNK) issue(c + STAGES - 1);
        else CP_COMMIT();
    }

    // ---- cross-k reduction via smem (reuse pipeline smem) ----
    CP_WAIT(0);
    __syncthreads();
    int r0 = lane >> 2, c0 = (lane & 3) * 2;
    float* red = (float*)gsm;
    int region = (mi * 2 + ni) * (32 * RSTR);
    if (kg == 1) {
#pragma unroll
        for (int am = 0; am < 2; am++)
#pragma unroll
            for (int an = 0; an < NA; an++)
#pragma unroll
                for (int q = 0; q < 4; q++) {
                    int row = am * 16 + r0 + ((q >> 1) << 3);
                    int col = an * 8 + c0 + (q & 1);
                    red[region + row * RSTR + col] = acc[am][an][q];
                }
    }
    __syncthreads();
    if (kg == 0) {
#pragma unroll
        for (int am = 0; am < 2; am++)
#pragma unroll
            for (int an = 0; an < NA; an++)
#pragma unroll
                for (int q = 0; q < 4; q++) {
                    int row = am * 16 + r0 + ((q >> 1) << 3);
                    int col = an * 8 + c0 + (q & 1);
                    acc[am][an][q] += red[region + row * RSTR + col];
                }
        // ---- epilogue (4 warps cover full 64 x NN tile) ----
#pragma unroll
        for (int am = 0; am < 2; am++) {
#pragma unroll
            for (int an = 0; an < NA; an++) {
                int gn = wn + an * 8 + c0;
                float b0 = bias[gn], b1 = bias[gn + 1];
                int gr0 = m0 + wm + am * 16 + r0;
                float v0 = acc[am][an][0] + b0;
                float v1 = acc[am][an][1] + b1;
                float v2 = acc[am][an][2] + b0;
                float v3 = acc[am][an][3] + b1;
                if (relu) {
                    v0 = fmaxf(v0, 0.f); v1 = fmaxf(v1, 0.f);
                    v2 = fmaxf(v2, 0.f); v3 = fmaxf(v3, 0.f);
                }
                if (gr0 < NPAT) {
                    Cb[(long)gr0 * NN + gn] = v0;
                    Cb[(long)gr0 * NN + gn + 1] = v1;
                }
                if (gr0 + 8 < NPAT) {
                    Cb[(long)(gr0 + 8) * NN + gn] = v2;
                    Cb[(long)(gr0 + 8) * NN + gn + 1] = v3;
                }
            }
        }
    }
}

// ---------------- final: tmp1 + tmp2 + patch2img(g2)/mask, relu --------------
__global__ void final_kernel(const float* __restrict__ in,
                             const float* __restrict__ proj,
                             const float* __restrict__ lam,
                             float* __restrict__ out) {
    int idx = blockIdx.x * 256 + threadIdx.x;
    if (idx >= BB * IMGD * IMGD) return;
    int x = idx & 255, y = (idx >> 8) & 255, b = idx >> 16;
    float lv = lam[0];
    float iv = in[idx], pv = proj[idx];
    float t1 = iv + lv * (pv - iv);
    float t2 = g_tmp2[idx];
    int tyv = y - 7;
    int py_lo = tyv > 0 ? (tyv + 3) >> 2 : 0;
    int py_hi = min(62, y >> 2);
    int txv = x - 7;
    int px_lo = txv > 0 ? (txv + 3) >> 2 : 0;
    int px_hi = min(62, x >> 2);
    float s = 0.f;
    int cnt = (py_hi - py_lo + 1) * (px_hi - px_lo + 1);
    for (int py = py_lo; py <= py_hi; py++) {
        int i = y - 4 * py;
        for (int px = px_lo; px <= px_hi; px++) {
            int j = x - 4 * px;
            s += g_g2[((long)b * NPAT + (py * PH + px)) * PPF + i * 8 + j];
        }
    }
    float v = t1 + t2 + s / (float)cnt;
    out[idx] = fmaxf(v, 0.f);
}

// ---------------- launch ----------------
extern "C" void kernel_launch(void* const* d_in, const int* in_sizes, int n_in,
                              void* d_out, int out_size) {
    const float* input = (const float*)d_in[0];
    const float* proj  = (const float*)d_in[1];
    const float* adj   = (const float*)d_in[2];
    const float* lam   = (const float*)d_in[3];
    const float* w1 = (const float*)d_in[4];
    const float* b1 = (const float*)d_in[5];
    const float* w2 = (const float*)d_in[6];
    const float* b2 = (const float*)d_in[7];
    const float* w3 = (const float*)d_in[8];
    const float* b3 = (const float*)d_in[9];
    const float* gw3 = (const float*)d_in[10];
    const float* gb3 = (const float*)d_in[11];
    const float* gw4 = (const float*)d_in[12];
    const float* gb4 = (const float*)d_in[13];
    float* out = (float*)d_out;

    __nv_bfloat16 *p_adjb, *p_supT, *p_gsupT;
    float *p_g, *p_g2;
    cudaGetSymbolAddress((void**)&p_adjb, g_adjb);
    cudaGetSymbolAddress((void**)&p_supT, g_supT);
    cudaGetSymbolAddress((void**)&p_gsupT, g_gsupT);
    cudaGetSymbolAddress((void**)&p_g, g_g);
    cudaGetSymbolAddress((void**)&p_g2, g_g2);

    const int C2_SMEM = (C2_XH + 2 * C2_WH) * 2;
    cudaFuncSetAttribute((const void*)conv2mma_kernel,
                         cudaFuncAttributeMaxDynamicSharedMemorySize, C2_SMEM);
    const int G1_SMEM = STAGES * (64 * LDT + 128 * LDT) * 2;  // 76800
    const int G2_SMEM = STAGES * (64 * LDT + 64 * LDT) * 2;   // 51200
    cudaFuncSetAttribute((const void*)mma_gemm_kernel<128>,
                         cudaFuncAttributeMaxDynamicSharedMemorySize, G1_SMEM);
    cudaFuncSetAttribute((const void*)mma_gemm_kernel<64>,
                         cudaFuncAttributeMaxDynamicSharedMemorySize, G2_SMEM);

    {
        long TOT = (long)BB * NPAT * (KPAD / 8);
        adjconv_kernel<<<(int)((TOT + 255) / 256), 256>>>(adj);
    }
    patch_kernel<<<(BB * NPAT * 8 + 255) / 256, 256>>>(input);
    gemmA_kernel<<<dim3(KPAD / 32, BB), 128>>>(gw3);
    mma_gemm_kernel<128><<<dim3(63, 1, BB), 256, G1_SMEM>>>(p_adjb, p_supT, p_g, gb3, 1);

    wt_kernel<<<144, 256>>>(w2);
    conv1_kernel<<<dim3(16, 16, BB), 256>>>(input, w1, b1);
    conv2mma_kernel<<<dim3(8, 32, BB), 256, C2_SMEM>>>(b2);
    conv3_kernel<<<dim3(4, 16, BB), 256>>>(w3, b3);

    gemmB_kernel<<<dim3(KPAD / 32, BB), 128>>>(gw4);
    mma_gemm_kernel<64><<<dim3(63, 1, BB), 256, G2_SMEM>>>(p_adjb, p_gsupT, p_g2, gb4, 0);

    final_kernel<<<(BB * IMGD * IMGD + 255) / 256, 256>>>(input, proj, lam, out);
}